// round 5
// baseline (speedup 1.0000x reference)
#include <cuda_runtime.h>
#include <cuda_bf16.h>
#include <math.h>
#include <stdint.h>

// Problem constants
#define NTOK 2048          // B*T
#define SEQ  1024
#define DMODEL 768
#define NHEAD 12
#define HDIM 64
#define NLAYER 8
#define VOCAB 50257
#define VPAD  50304        // 393*128

// per-layer transposed-weight plane offsets (elements)
#define OFF_ATTN  0
#define SZ_ATTN   (3 * DMODEL * DMODEL)            // 2304*768
#define OFF_PROJ  (NLAYER * SZ_ATTN)
#define SZ_PROJ   (DMODEL * DMODEL)
#define OFF_FC    (OFF_PROJ + NLAYER * SZ_PROJ)
#define SZ_FC     (4 * DMODEL * DMODEL)
#define OFF_PROJ2 (OFF_FC + NLAYER * SZ_FC)
#define SZ_PROJ2  (4 * DMODEL * DMODEL)
#define WT_TOTAL  (OFF_PROJ2 + NLAYER * SZ_PROJ2)  // 56.6M elems

// ---------------- scratch (device globals; no allocation allowed) ------------
__device__ float g_x[NTOK * DMODEL];
__device__ float g_rowloss[NTOK];
__device__ __nv_bfloat16 g_hH [NTOK * DMODEL];
__device__ __nv_bfloat16 g_hL [NTOK * DMODEL];
__device__ __nv_bfloat16 g_qkvH[NTOK * 3 * DMODEL];
__device__ __nv_bfloat16 g_qkvL[NTOK * 3 * DMODEL];
__device__ __nv_bfloat16 g_yH [NTOK * DMODEL];
__device__ __nv_bfloat16 g_yL [NTOK * DMODEL];
__device__ __nv_bfloat16 g_mH [NTOK * 4 * DMODEL];
__device__ __nv_bfloat16 g_mL [NTOK * 4 * DMODEL];
__device__ __nv_bfloat16 g_wTh[WT_TOTAL];
__device__ __nv_bfloat16 g_wTl[WT_TOTAL];
__device__ __nv_bfloat16 g_wteH[(size_t)VPAD * DMODEL];
__device__ __nv_bfloat16 g_wteL[(size_t)VPAD * DMODEL];

// ---------------- helpers -----------------------------------------------------
__device__ __forceinline__ uint32_t smem_u32(const void* p) {
    uint32_t a;
    asm("{ .reg .u64 t; cvta.to.shared.u64 t, %1; cvt.u32.u64 %0, t; }" : "=r"(a) : "l"(p));
    return a;
}

#define CP_ASYNC16(s, g) \
    asm volatile("cp.async.cg.shared.global [%0], [%1], 16;" :: "r"(s), "l"(g) : "memory")
#define CP_COMMIT() asm volatile("cp.async.commit_group;" ::: "memory")

__device__ __forceinline__ void ldsm4(uint32_t r[4], uint32_t addr) {
    asm volatile("ldmatrix.sync.aligned.m8n8.x4.shared.b16 {%0,%1,%2,%3}, [%4];"
        : "=r"(r[0]), "=r"(r[1]), "=r"(r[2]), "=r"(r[3]) : "r"(addr));
}
__device__ __forceinline__ void ldsm4t(uint32_t r[4], uint32_t addr) {
    asm volatile("ldmatrix.sync.aligned.m8n8.x4.trans.shared.b16 {%0,%1,%2,%3}, [%4];"
        : "=r"(r[0]), "=r"(r[1]), "=r"(r[2]), "=r"(r[3]) : "r"(addr));
}
__device__ __forceinline__ void mma_bf16(float c[4], const uint32_t a[4],
                                         uint32_t b0, uint32_t b1) {
    asm volatile("mma.sync.aligned.m16n8k16.row.col.f32.bf16.bf16.f32 "
        "{%0,%1,%2,%3}, {%4,%5,%6,%7}, {%8,%9}, {%0,%1,%2,%3};"
        : "+f"(c[0]), "+f"(c[1]), "+f"(c[2]), "+f"(c[3])
        : "r"(a[0]), "r"(a[1]), "r"(a[2]), "r"(a[3]), "r"(b0), "r"(b1));
}

__device__ __forceinline__ float gelu_f(float x) {
    const float c = 0.7978845608028654f;
    float x3 = x * x * x;
    return 0.5f * x * (1.0f + tanhf(c * (x + 0.044715f * x3)));
}

__device__ __forceinline__ void split_pack(float a, float b, uint32_t& hp, uint32_t& lp) {
    __nv_bfloat16 ha = __float2bfloat16(a), hb = __float2bfloat16(b);
    __nv_bfloat16 la = __float2bfloat16(a - __bfloat162float(ha));
    __nv_bfloat16 lb = __float2bfloat16(b - __bfloat162float(hb));
    hp = ((uint32_t)__bfloat16_as_ushort(hb) << 16) | __bfloat16_as_ushort(ha);
    lp = ((uint32_t)__bfloat16_as_ushort(lb) << 16) | __bfloat16_as_ushort(la);
}

// ---------------- HMMA bf16x3 GEMM --------------------------------------------
// C[M,N] = A[M,K]*B^T (B [N,K] hi/lo). CTA tile 128x128, KC=32, padded 80B rows.
// EPI: 0 plain, 1 +bias, 2 gelu(+bias), 3 residual (f32). OBF: bf16 hi/lo out.
#define KC 32
#define ROWB 80                    // padded row stride: (5r+g)%8 covers all granules
#define PLANE_B (128 * ROWB)       // 10240
#define STAGE_B (4 * PLANE_B)      // 40960
#define GSMEM_NEED (2 * STAGE_B + 128)

template <int EPI, bool NPRED, bool OBF>
__global__ void __launch_bounds__(256, 2)
gemm_tc(const __nv_bfloat16* __restrict__ Ah, const __nv_bfloat16* __restrict__ Al,
        const __nv_bfloat16* __restrict__ Bh, const __nv_bfloat16* __restrict__ Bl,
        const float* __restrict__ bias, float* __restrict__ C,
        __nv_bfloat16* __restrict__ CH, __nv_bfloat16* __restrict__ CL,
        int N, int K) {
    extern __shared__ char dsm[];
    uint32_t sb = (smem_u32(dsm) + 127) & ~127u;

    const int tid = threadIdx.x;
    const int wid = tid >> 5, lid = tid & 31;
    const long bm = (long)blockIdx.x * 128;
    const long bn = (long)blockIdx.y * 128;
    const int wm = (wid >> 2) * 64;
    const int wn = (wid & 3) * 32;
    const int lrow = lid & 15, lg = lid >> 4;

    const int nch = K / KC;

    auto load_stage = [&](int c, int st) {
        uint32_t stb = sb + st * STAGE_B;
        int kc0 = c * KC;
        #pragma unroll
        for (int i = 0; i < 2; i++) {
            int u = tid + 256 * i;            // 0..511
            int row = u >> 2, g = u & 3;
            uint32_t so = stb + row * ROWB + g * 16;
            long ka = (bm + row) * (long)K + kc0 + g * 8;
            long kb = (bn + row) * (long)K + kc0 + g * 8;
            CP_ASYNC16(so,               Ah + ka);
            CP_ASYNC16(so + PLANE_B,     Al + ka);
            CP_ASYNC16(so + 2 * PLANE_B, Bh + kb);
            CP_ASYNC16(so + 3 * PLANE_B, Bl + kb);
        }
        CP_COMMIT();
    };

    float creg[4][4][4];
    #pragma unroll
    for (int a = 0; a < 4; a++)
        #pragma unroll
        for (int b = 0; b < 4; b++)
            #pragma unroll
            for (int k = 0; k < 4; k++) creg[a][b][k] = 0.f;

    load_stage(0, 0);
    load_stage(1, 1);

    for (int c = 0; c < nch; c++) {
        if (c + 1 < nch) { asm volatile("cp.async.wait_group 1;" ::: "memory"); }
        else             { asm volatile("cp.async.wait_group 0;" ::: "memory"); }
        __syncthreads();

        uint32_t stb = sb + (c & 1) * STAGE_B;
        #pragma unroll
        for (int ks = 0; ks < 2; ks++) {
            int g = 2 * ks + lg;              // 0..3
            uint32_t aH[4][4], aL[4][4], bH[2][4], bL[2][4];
            #pragma unroll
            for (int mi = 0; mi < 4; mi++) {
                int row = wm + mi * 16 + lrow;
                uint32_t off = row * ROWB + g * 16;
                ldsm4(aH[mi], stb + off);
                ldsm4(aL[mi], stb + PLANE_B + off);
            }
            #pragma unroll
            for (int ng = 0; ng < 2; ng++) {
                int row = wn + ng * 16 + lrow;
                uint32_t off = row * ROWB + g * 16;
                ldsm4(bH[ng], stb + 2 * PLANE_B + off);
                ldsm4(bL[ng], stb + 3 * PLANE_B + off);
            }
            // pass 1: hi*hi  (16 independent MMAs)
            #pragma unroll
            for (int mi = 0; mi < 4; mi++)
                #pragma unroll
                for (int ni = 0; ni < 4; ni++) {
                    int ng = ni >> 1, h = ni & 1;
                    mma_bf16(creg[mi][ni], aH[mi], bH[ng][h], bH[ng][h + 2]);
                }
            // pass 2: hi*lo
            #pragma unroll
            for (int mi = 0; mi < 4; mi++)
                #pragma unroll
                for (int ni = 0; ni < 4; ni++) {
                    int ng = ni >> 1, h = ni & 1;
                    mma_bf16(creg[mi][ni], aH[mi], bL[ng][h], bL[ng][h + 2]);
                }
            // pass 3: lo*hi
            #pragma unroll
            for (int mi = 0; mi < 4; mi++)
                #pragma unroll
                for (int ni = 0; ni < 4; ni++) {
                    int ng = ni >> 1, h = ni & 1;
                    mma_bf16(creg[mi][ni], aL[mi], bH[ng][h], bH[ng][h + 2]);
                }
        }
        __syncthreads();
        if (c + 2 < nch) load_stage(c + 2, c & 1);
    }

    // ---- epilogue ----
    int gid = lid >> 2, tin = lid & 3;
    #pragma unroll
    for (int mi = 0; mi < 4; mi++) {
        long row0 = bm + wm + mi * 16 + gid;
        long row1 = row0 + 8;
        #pragma unroll
        for (int ni = 0; ni < 4; ni++) {
            long col = bn + wn + ni * 8 + tin * 2;
            float b0 = 0.f, b1 = 0.f;
            if (EPI >= 1) { b0 = bias[col]; b1 = bias[col + 1]; }
            float v0 = creg[mi][ni][0] + b0;
            float v1 = creg[mi][ni][1] + b1;
            float v2 = creg[mi][ni][2] + b0;
            float v3 = creg[mi][ni][3] + b1;
            if (EPI == 2) { v0 = gelu_f(v0); v1 = gelu_f(v1); v2 = gelu_f(v2); v3 = gelu_f(v3); }
            if (OBF) {
                uint32_t hp, lp;
                size_t o0 = (size_t)row0 * N + col;
                size_t o1 = (size_t)row1 * N + col;
                split_pack(v0, v1, hp, lp);
                *(uint32_t*)&CH[o0] = hp; *(uint32_t*)&CL[o0] = lp;
                split_pack(v2, v3, hp, lp);
                *(uint32_t*)&CH[o1] = hp; *(uint32_t*)&CL[o1] = lp;
            } else if (NPRED) {
                if (col < N)     { C[row0 * N + col]     = v0; C[row1 * N + col]     = v2; }
                if (col + 1 < N) { C[row0 * N + col + 1] = v1; C[row1 * N + col + 1] = v3; }
            } else {
                size_t o0 = (size_t)row0 * N + col;
                size_t o1 = (size_t)row1 * N + col;
                if (EPI == 3) {
                    float2 c0 = *(float2*)&C[o0];
                    float2 c1 = *(float2*)&C[o1];
                    v0 += c0.x; v1 += c0.y; v2 += c1.x; v3 += c1.y;
                }
                *(float2*)&C[o0] = make_float2(v0, v1);
                *(float2*)&C[o1] = make_float2(v2, v3);
            }
        }
    }
}

// ---------------- HMMA flash attention ----------------------------------------
// grid (SEQ/64, NHEAD, B), 128 threads. Warp w owns q rows [w*16, w*16+16).
#define ATT_SMEM (16384 + 2 * 32768 + 128)

__global__ void __launch_bounds__(128, 1)
attn_tc(const __nv_bfloat16* __restrict__ QKVh, const __nv_bfloat16* __restrict__ QKVl,
        __nv_bfloat16* __restrict__ Yh, __nv_bfloat16* __restrict__ Yl) {
    extern __shared__ char dsm[];
    uint32_t sb = (smem_u32(dsm) + 127) & ~127u;

    const int tid = threadIdx.x;
    const int wid = tid >> 5, lid = tid & 31;
    const int q0 = blockIdx.x * 64, h = blockIdx.y, b = blockIdx.z;
    const int wq = wid * 16;
    const int ntile = blockIdx.x + 1;
    const size_t rstride = 3 * DMODEL;

    auto ldplane = [&](uint32_t dst, const __nv_bfloat16* src) {
        #pragma unroll
        for (int i = 0; i < 4; i++) {
            int u = tid + 128 * i;
            int row = u >> 3, ch = u & 7;
            CP_ASYNC16(dst + row * 128 + ((ch ^ (row & 7)) << 4),
                       src + (size_t)row * rstride + ch * 8);
        }
    };
    auto ldstage = [&](int t) {
        uint32_t s = sb + 16384 + (t & 1) * 32768;
        size_t off = (size_t)(b * SEQ + t * 64) * rstride + h * HDIM;
        ldplane(s,         QKVh + off + DMODEL);
        ldplane(s + 8192,  QKVl + off + DMODEL);
        ldplane(s + 16384, QKVh + off + 2 * DMODEL);
        ldplane(s + 24576, QKVl + off + 2 * DMODEL);
        CP_COMMIT();
    };

    {
        size_t qoff = (size_t)(b * SEQ + q0) * rstride + h * HDIM;
        ldplane(sb,        QKVh + qoff);
        ldplane(sb + 8192, QKVl + qoff);
    }
    ldstage(0);

    float o[8][4];
    #pragma unroll
    for (int nb = 0; nb < 8; nb++)
        #pragma unroll
        for (int j = 0; j < 4; j++) o[nb][j] = 0.f;
    float mrun[2] = {-1e30f, -1e30f}, lrun[2] = {0.f, 0.f};

    for (int t = 0; t < ntile; t++) {
        asm volatile("cp.async.wait_group 0;" ::: "memory");
        __syncthreads();
        if (t + 1 < ntile) ldstage(t + 1);
        uint32_t kb = sb + 16384 + (t & 1) * 32768;

        float s[8][4];
        #pragma unroll
        for (int nb = 0; nb < 8; nb++)
            #pragma unroll
            for (int j = 0; j < 4; j++) s[nb][j] = 0.f;

        #pragma unroll
        for (int ks = 0; ks < 4; ks++) {
            uint32_t qh[4], ql[4];
            {
                int r = wq + (lid & 15);
                uint32_t off = r * 128 + (((2 * ks + (lid >> 4)) ^ (r & 7)) << 4);
                ldsm4(qh, sb + off);
                ldsm4(ql, sb + 8192 + off);
            }
            #pragma unroll
            for (int ng = 0; ng < 4; ng++) {
                int r = ng * 16 + (lid & 15);
                uint32_t off = r * 128 + (((2 * ks + (lid >> 4)) ^ (r & 7)) << 4);
                uint32_t kh[4], kl[4];
                ldsm4(kh, kb + off);
                ldsm4(kl, kb + 8192 + off);
                mma_bf16(s[2 * ng],     qh, kh[0], kh[2]);
                mma_bf16(s[2 * ng],     qh, kl[0], kl[2]);
                mma_bf16(s[2 * ng],     ql, kh[0], kh[2]);
                mma_bf16(s[2 * ng + 1], qh, kh[1], kh[3]);
                mma_bf16(s[2 * ng + 1], qh, kl[1], kl[3]);
                mma_bf16(s[2 * ng + 1], ql, kh[1], kh[3]);
            }
        }

        #pragma unroll
        for (int nb = 0; nb < 8; nb++)
            #pragma unroll
            for (int j = 0; j < 4; j++) s[nb][j] *= 0.125f;

        if (t == blockIdx.x) {
            int r0g = q0 + wq + (lid >> 2);
            #pragma unroll
            for (int nb = 0; nb < 8; nb++) {
                int colg = t * 64 + nb * 8 + (lid & 3) * 2;
                if (colg     > r0g)     s[nb][0] = -1e30f;
                if (colg + 1 > r0g)     s[nb][1] = -1e30f;
                if (colg     > r0g + 8) s[nb][2] = -1e30f;
                if (colg + 1 > r0g + 8) s[nb][3] = -1e30f;
            }
        }

        #pragma unroll
        for (int half = 0; half < 2; half++) {
            float mx = -1e30f;
            #pragma unroll
            for (int nb = 0; nb < 8; nb++)
                mx = fmaxf(mx, fmaxf(s[nb][2 * half], s[nb][2 * half + 1]));
            mx = fmaxf(mx, __shfl_xor_sync(~0u, mx, 1));
            mx = fmaxf(mx, __shfl_xor_sync(~0u, mx, 2));
            float mn = fmaxf(mrun[half], mx);
            float al = __expf(mrun[half] - mn);
            mrun[half] = mn;
            float sum = 0.f;
            #pragma unroll
            for (int nb = 0; nb < 8; nb++) {
                float p0 = __expf(s[nb][2 * half]     - mn);
                float p1 = __expf(s[nb][2 * half + 1] - mn);
                s[nb][2 * half] = p0; s[nb][2 * half + 1] = p1;
                sum += p0 + p1;
            }
            lrun[half] = lrun[half] * al + sum;
            #pragma unroll
            for (int nb = 0; nb < 8; nb++) {
                o[nb][2 * half] *= al; o[nb][2 * half + 1] *= al;
            }
        }

        #pragma unroll
        for (int kk = 0; kk < 4; kk++) {
            uint32_t ph[4], pl[4];
            split_pack(s[2 * kk][0],     s[2 * kk][1],     ph[0], pl[0]);
            split_pack(s[2 * kk][2],     s[2 * kk][3],     ph[1], pl[1]);
            split_pack(s[2 * kk + 1][0], s[2 * kk + 1][1], ph[2], pl[2]);
            split_pack(s[2 * kk + 1][2], s[2 * kk + 1][3], ph[3], pl[3]);
            #pragma unroll
            for (int cc = 0; cc < 4; cc++) {
                int r = kk * 16 + (lid & 15);
                uint32_t off = r * 128 + (((2 * cc + (lid >> 4)) ^ (r & 7)) << 4);
                uint32_t vh[4], vl[4];
                ldsm4t(vh, kb + 16384 + off);
                ldsm4t(vl, kb + 24576 + off);
                mma_bf16(o[2 * cc],     ph, vh[0], vh[1]);
                mma_bf16(o[2 * cc],     pl, vh[0], vh[1]);
                mma_bf16(o[2 * cc],     ph, vl[0], vl[1]);
                mma_bf16(o[2 * cc + 1], ph, vh[2], vh[3]);
                mma_bf16(o[2 * cc + 1], pl, vh[2], vh[3]);
                mma_bf16(o[2 * cc + 1], ph, vl[2], vl[3]);
            }
        }
    }

    float inv[2];
    #pragma unroll
    for (int half = 0; half < 2; half++) {
        float l = lrun[half];
        l += __shfl_xor_sync(~0u, l, 1);
        l += __shfl_xor_sync(~0u, l, 2);
        inv[half] = 1.0f / l;
    }
    int r0 = q0 + wq + (lid >> 2);
    #pragma unroll
    for (int nb = 0; nb < 8; nb++) {
        int col = h * HDIM + nb * 8 + (lid & 3) * 2;
        size_t o0 = (size_t)(b * SEQ + r0) * DMODEL + col;
        size_t o1 = (size_t)(b * SEQ + r0 + 8) * DMODEL + col;
        uint32_t hp, lp;
        split_pack(o[nb][0] * inv[0], o[nb][1] * inv[0], hp, lp);
        *(uint32_t*)&Yh[o0] = hp; *(uint32_t*)&Yl[o0] = lp;
        split_pack(o[nb][2] * inv[1], o[nb][3] * inv[1], hp, lp);
        *(uint32_t*)&Yh[o1] = hp; *(uint32_t*)&Yl[o1] = lp;
    }
}

// ---------------- weight conversion (batched over layers via grid.z) ----------
__global__ void cvt_wte_k(const float* __restrict__ wte) {
    size_t i = (size_t)blockIdx.x * 256 + threadIdx.x;
    if (i >= (size_t)VPAD * DMODEL) return;
    float v = (i < (size_t)VOCAB * DMODEL) ? wte[i] : 0.0f;
    __nv_bfloat16 hb = __float2bfloat16(v);
    g_wteH[i] = hb;
    g_wteL[i] = __float2bfloat16(v - __bfloat162float(hb));
}

// w [L,K,N] f32 -> out [L,N,K] bf16 hi/lo. grid (N/32, K/32, L), block (32,8)
__global__ void cvt_wT(const float* __restrict__ w, __nv_bfloat16* __restrict__ th,
                       __nv_bfloat16* __restrict__ tl, int K, int N) {
    __shared__ float t[32][33];
    const float* wsrc = w + (size_t)blockIdx.z * K * N;
    __nv_bfloat16* thd = th + (size_t)blockIdx.z * N * K;
    __nv_bfloat16* tld = tl + (size_t)blockIdx.z * N * K;
    int n0 = blockIdx.x * 32, k0 = blockIdx.y * 32;
    int tx = threadIdx.x, ty = threadIdx.y;
    #pragma unroll
    for (int i = 0; i < 4; i++)
        t[ty + 8 * i][tx] = wsrc[(size_t)(k0 + ty + 8 * i) * N + n0 + tx];
    __syncthreads();
    #pragma unroll
    for (int i = 0; i < 4; i++) {
        float v = t[tx][ty + 8 * i];
        __nv_bfloat16 hb = __float2bfloat16(v);
        size_t o = (size_t)(n0 + ty + 8 * i) * K + k0 + tx;
        thd[o] = hb;
        tld[o] = __float2bfloat16(v - __bfloat162float(hb));
    }
}

// ---------------- embedding --------------------------------------------------
__global__ void embed_kernel(const int* __restrict__ idx,
                             const float* __restrict__ wte,
                             const float* __restrict__ wpe) {
    int row = blockIdx.x;
    int t = row & (SEQ - 1);
    int tok = idx[row];
    const float* we = wte + (size_t)tok * DMODEL;
    const float* wp = wpe + (size_t)t * DMODEL;
    float* xr = g_x + (size_t)row * DMODEL;
    for (int d = threadIdx.x; d < DMODEL; d += blockDim.x)
        xr[d] = we[d] + wp[d];
}

// ---------------- layernorm (writes bf16 hi/lo planes) -----------------------
__global__ void __launch_bounds__(256) ln_kernel(const float* __restrict__ x,
                                                 const float* __restrict__ sc,
                                                 const float* __restrict__ bi,
                                                 __nv_bfloat16* __restrict__ outH,
                                                 __nv_bfloat16* __restrict__ outL) {
    __shared__ float red[8];
    int row = blockIdx.x, tid = threadIdx.x;
    const float* xr = x + (size_t)row * DMODEL;
    float v0 = xr[tid], v1 = xr[tid + 256], v2 = xr[tid + 512];

    float s = v0 + v1 + v2;
    #pragma unroll
    for (int o = 16; o > 0; o >>= 1) s += __shfl_xor_sync(~0u, s, o);
    if ((tid & 31) == 0) red[tid >> 5] = s;
    __syncthreads();
    if (tid < 32) {
        float t = (tid < 8) ? red[tid] : 0.f;
        #pragma unroll
        for (int o = 4; o > 0; o >>= 1) t += __shfl_xor_sync(~0u, t, o);
        if (tid == 0) red[0] = t;
    }
    __syncthreads();
    float mu = red[0] * (1.0f / DMODEL);
    __syncthreads();

    float d0 = v0 - mu, d1 = v1 - mu, d2 = v2 - mu;
    float s2 = d0 * d0 + d1 * d1 + d2 * d2;
    #pragma unroll
    for (int o = 16; o > 0; o >>= 1) s2 += __shfl_xor_sync(~0u, s2, o);
    if ((tid & 31) == 0) red[tid >> 5] = s2;
    __syncthreads();
    if (tid < 32) {
        float t = (tid < 8) ? red[tid] : 0.f;
        #pragma unroll
        for (int o = 4; o > 0; o >>= 1) t += __shfl_xor_sync(~0u, t, o);
        if (tid == 0) red[0] = t;
    }
    __syncthreads();
    float var = red[0] * (1.0f / DMODEL);
    float rs = rsqrtf(var + 1e-5f);

    size_t base = (size_t)row * DMODEL;
    #pragma unroll
    for (int e = 0; e < 3; e++) {
        float d = (e == 0) ? d0 : (e == 1) ? d1 : d2;
        int c = tid + 256 * e;
        float v = d * rs * sc[c] + bi[c];
        __nv_bfloat16 hb = __float2bfloat16(v);
        outH[base + c] = hb;
        outL[base + c] = __float2bfloat16(v - __bfloat162float(hb));
    }
}

// ---------------- loss --------------------------------------------------------
__global__ void __launch_bounds__(256) lossrow_kernel(const float* __restrict__ logits,
                                                      const int* __restrict__ targets) {
    int row = blockIdx.x;
    const float* lr_ = logits + (size_t)row * VOCAB;
    float m = -1e30f, s = 0.f;
    for (int jv = threadIdx.x; jv < VOCAB; jv += 256) {
        float v = lr_[jv];
        if (v <= m) {
            s += __expf(v - m);
        } else {
            s = s * __expf(m - v) + 1.0f;
            m = v;
        }
    }
    __shared__ float sm[256], ss[256];
    sm[threadIdx.x] = m; ss[threadIdx.x] = s;
    __syncthreads();
    for (int st = 128; st > 0; st >>= 1) {
        if (threadIdx.x < st) {
            float ma = sm[threadIdx.x], sa = ss[threadIdx.x];
            float mb = sm[threadIdx.x + st], sb = ss[threadIdx.x + st];
            float M = fmaxf(ma, mb);
            ss[threadIdx.x] = sa * __expf(ma - M) + sb * __expf(mb - M);
            sm[threadIdx.x] = M;
        }
        __syncthreads();
    }
    if (threadIdx.x == 0) {
        float lse = sm[0] + logf(ss[0]);
        g_rowloss[row] = lse - lr_[targets[row]];
    }
}

__global__ void __launch_bounds__(256) lossreduce_kernel(float* __restrict__ out_loss) {
    __shared__ float red[8];
    float s = 0.f;
    for (int i = threadIdx.x; i < NTOK; i += 256) s += g_rowloss[i];
    #pragma unroll
    for (int o = 16; o > 0; o >>= 1) s += __shfl_xor_sync(~0u, s, o);
    if ((threadIdx.x & 31) == 0) red[threadIdx.x >> 5] = s;
    __syncthreads();
    if (threadIdx.x == 0) {
        float t = 0.f;
        for (int w = 0; w < 8; w++) t += red[w];
        out_loss[0] = t * (1.0f / NTOK);
    }
}

// ---------------- host orchestration -----------------------------------------
extern "C" void kernel_launch(void* const* d_in, const int* in_sizes, int n_in,
                              void* d_out, int out_size) {
    const int*   idx     = (const int*)  d_in[0];
    const int*   targets = (const int*)  d_in[1];
    const float* wte     = (const float*)d_in[2];
    const float* wpe     = (const float*)d_in[3];
    const float* ln1_s   = (const float*)d_in[4];
    const float* ln1_b   = (const float*)d_in[5];
    const float* attn_w  = (const float*)d_in[6];
    const float* attn_b  = (const float*)d_in[7];
    const float* proj_w  = (const float*)d_in[8];
    const float* proj_b  = (const float*)d_in[9];
    const float* ln2_s   = (const float*)d_in[10];
    const float* ln2_b   = (const float*)d_in[11];
    const float* fc_w    = (const float*)d_in[12];
    const float* fc_b    = (const float*)d_in[13];
    const float* proj2_w = (const float*)d_in[14];
    const float* proj2_b = (const float*)d_in[15];
    const float* lnf_s   = (const float*)d_in[16];
    const float* lnf_b   = (const float*)d_in[17];
    float* out = (float*)d_out;

    float* px;
    __nv_bfloat16 *phH, *phL, *pqH, *pqL, *pyH, *pyL, *pmH, *pmL;
    __nv_bfloat16 *pwTh, *pwTl, *pwteH, *pwteL;
    cudaGetSymbolAddress((void**)&px, g_x);
    cudaGetSymbolAddress((void**)&phH, g_hH);
    cudaGetSymbolAddress((void**)&phL, g_hL);
    cudaGetSymbolAddress((void**)&pqH, g_qkvH);
    cudaGetSymbolAddress((void**)&pqL, g_qkvL);
    cudaGetSymbolAddress((void**)&pyH, g_yH);
    cudaGetSymbolAddress((void**)&pyL, g_yL);
    cudaGetSymbolAddress((void**)&pmH, g_mH);
    cudaGetSymbolAddress((void**)&pmL, g_mL);
    cudaGetSymbolAddress((void**)&pwTh, g_wTh);
    cudaGetSymbolAddress((void**)&pwTl, g_wTl);
    cudaGetSymbolAddress((void**)&pwteH, g_wteH);
    cudaGetSymbolAddress((void**)&pwteL, g_wteL);

    cudaFuncSetAttribute(gemm_tc<1, false, true>,  cudaFuncAttributeMaxDynamicSharedMemorySize, GSMEM_NEED);
    cudaFuncSetAttribute(gemm_tc<2, false, true>,  cudaFuncAttributeMaxDynamicSharedMemorySize, GSMEM_NEED);
    cudaFuncSetAttribute(gemm_tc<3, false, false>, cudaFuncAttributeMaxDynamicSharedMemorySize, GSMEM_NEED);
    cudaFuncSetAttribute(gemm_tc<0, true, false>,  cudaFuncAttributeMaxDynamicSharedMemorySize, GSMEM_NEED);
    cudaFuncSetAttribute(attn_tc, cudaFuncAttributeMaxDynamicSharedMemorySize, ATT_SMEM);

    embed_kernel<<<NTOK, 256>>>(idx, wte, wpe);

    // --- all weight conversions up-front (batched over layers) ---
    cvt_wT<<<dim3(3 * DMODEL / 32, DMODEL / 32, NLAYER), dim3(32, 8)>>>(
        attn_w, pwTh + OFF_ATTN, pwTl + OFF_ATTN, DMODEL, 3 * DMODEL);
    cvt_wT<<<dim3(DMODEL / 32, DMODEL / 32, NLAYER), dim3(32, 8)>>>(
        proj_w, pwTh + OFF_PROJ, pwTl + OFF_PROJ, DMODEL, DMODEL);
    cvt_wT<<<dim3(4 * DMODEL / 32, DMODEL / 32, NLAYER), dim3(32, 8)>>>(
        fc_w, pwTh + OFF_FC, pwTl + OFF_FC, DMODEL, 4 * DMODEL);
    cvt_wT<<<dim3(DMODEL / 32, 4 * DMODEL / 32, NLAYER), dim3(32, 8)>>>(
        proj2_w, pwTh + OFF_PROJ2, pwTl + OFF_PROJ2, 4 * DMODEL, DMODEL);
    {
        size_t nw = (size_t)VPAD * DMODEL;
        cvt_wte_k<<<(unsigned)((nw + 255) / 256), 256>>>(wte);
    }

    for (int l = 0; l < NLAYER; l++) {
        const float* ab  = attn_b  + (size_t)l * 3 * DMODEL;
        const float* pb  = proj_b  + (size_t)l * DMODEL;
        const float* fb  = fc_b    + (size_t)l * 4 * DMODEL;
        const float* p2b = proj2_b + (size_t)l * DMODEL;
        size_t oAttn  = OFF_ATTN  + (size_t)l * SZ_ATTN;
        size_t oProj  = OFF_PROJ  + (size_t)l * SZ_PROJ;
        size_t oFc    = OFF_FC    + (size_t)l * SZ_FC;
        size_t oProj2 = OFF_PROJ2 + (size_t)l * SZ_PROJ2;

        // --- attention block ---
        ln_kernel<<<NTOK, 256>>>(px, ln1_s + l * DMODEL, ln1_b + l * DMODEL, phH, phL);
        gemm_tc<1, false, true><<<dim3(NTOK / 128, 3 * DMODEL / 128), 256, GSMEM_NEED>>>(
            phH, phL, pwTh + oAttn, pwTl + oAttn, ab, nullptr, pqH, pqL, 3 * DMODEL, DMODEL);
        attn_tc<<<dim3(SEQ / 64, NHEAD, 2), 128, ATT_SMEM>>>(pqH, pqL, pyH, pyL);
        gemm_tc<3, false, false><<<dim3(NTOK / 128, DMODEL / 128), 256, GSMEM_NEED>>>(
            pyH, pyL, pwTh + oProj, pwTl + oProj, pb, px, nullptr, nullptr, DMODEL, DMODEL);

        // --- MLP block ---
        ln_kernel<<<NTOK, 256>>>(px, ln2_s + l * DMODEL, ln2_b + l * DMODEL, phH, phL);
        gemm_tc<2, false, true><<<dim3(NTOK / 128, 4 * DMODEL / 128), 256, GSMEM_NEED>>>(
            phH, phL, pwTh + oFc, pwTl + oFc, fb, nullptr, pmH, pmL, 4 * DMODEL, DMODEL);
        gemm_tc<3, false, false><<<dim3(NTOK / 128, DMODEL / 128), 256, GSMEM_NEED>>>(
            pmH, pmL, pwTh + oProj2, pwTl + oProj2, p2b, px, nullptr, nullptr, DMODEL, 4 * DMODEL);
    }

    // --- final LN + tied lm_head + loss ---
    ln_kernel<<<NTOK, 256>>>(px, lnf_s, lnf_b, phH, phL);
    gemm_tc<0, true, false><<<dim3(NTOK / 128, VPAD / 128), 256, GSMEM_NEED>>>(
        phH, phL, pwteH, pwteL, nullptr, out, nullptr, nullptr, VOCAB, DMODEL);

    lossrow_kernel<<<NTOK, 256>>>(out, targets);
    lossreduce_kernel<<<1, 256>>>(out + (size_t)NTOK * VOCAB);
}

// round 6
// speedup vs baseline: 1.1547x; 1.1547x over previous
#include <cuda_runtime.h>
#include <cuda_bf16.h>
#include <math.h>
#include <stdint.h>

// Problem constants
#define NTOK 2048          // B*T
#define SEQ  1024
#define DMODEL 768
#define NHEAD 12
#define HDIM 64
#define NLAYER 8
#define VOCAB 50257
#define VPAD  50304        // 393*128

// per-layer transposed-weight plane offsets (elements)
#define OFF_ATTN  0
#define SZ_ATTN   (3 * DMODEL * DMODEL)
#define OFF_PROJ  (NLAYER * SZ_ATTN)
#define SZ_PROJ   (DMODEL * DMODEL)
#define OFF_FC    (OFF_PROJ + NLAYER * SZ_PROJ)
#define SZ_FC     (4 * DMODEL * DMODEL)
#define OFF_PROJ2 (OFF_FC + NLAYER * SZ_FC)
#define SZ_PROJ2  (4 * DMODEL * DMODEL)
#define WT_TOTAL  (OFF_PROJ2 + NLAYER * SZ_PROJ2)

// ---------------- scratch (device globals; no allocation allowed) ------------
__device__ float g_x[NTOK * DMODEL];
__device__ float g_rowloss[NTOK];
__device__ __nv_bfloat16 g_hH [NTOK * DMODEL];
__device__ __nv_bfloat16 g_hL [NTOK * DMODEL];
__device__ __nv_bfloat16 g_qkvH[NTOK * 3 * DMODEL];
__device__ __nv_bfloat16 g_qkvL[NTOK * 3 * DMODEL];
__device__ __nv_bfloat16 g_yH [NTOK * DMODEL];
__device__ __nv_bfloat16 g_yL [NTOK * DMODEL];
__device__ __nv_bfloat16 g_mH [NTOK * 4 * DMODEL];
__device__ __nv_bfloat16 g_mL [NTOK * 4 * DMODEL];
__device__ __nv_bfloat16 g_wTh[WT_TOTAL];
__device__ __nv_bfloat16 g_wTl[WT_TOTAL];
__device__ __nv_bfloat16 g_wteH[(size_t)VPAD * DMODEL];
__device__ __nv_bfloat16 g_wteL[(size_t)VPAD * DMODEL];

// ---------------- helpers -----------------------------------------------------
__device__ __forceinline__ uint32_t smem_u32(const void* p) {
    uint32_t a;
    asm("{ .reg .u64 t; cvta.to.shared.u64 t, %1; cvt.u32.u64 %0, t; }" : "=r"(a) : "l"(p));
    return a;
}

#define CP_ASYNC16(s, g) \
    asm volatile("cp.async.cg.shared.global [%0], [%1], 16;" :: "r"(s), "l"(g) : "memory")
#define CP_COMMIT() asm volatile("cp.async.commit_group;" ::: "memory")

__device__ __forceinline__ void ldsm4(uint32_t r[4], uint32_t addr) {
    asm volatile("ldmatrix.sync.aligned.m8n8.x4.shared.b16 {%0,%1,%2,%3}, [%4];"
        : "=r"(r[0]), "=r"(r[1]), "=r"(r[2]), "=r"(r[3]) : "r"(addr));
}
__device__ __forceinline__ void ldsm4t(uint32_t r[4], uint32_t addr) {
    asm volatile("ldmatrix.sync.aligned.m8n8.x4.trans.shared.b16 {%0,%1,%2,%3}, [%4];"
        : "=r"(r[0]), "=r"(r[1]), "=r"(r[2]), "=r"(r[3]) : "r"(addr));
}
__device__ __forceinline__ void mma_bf16(float c[4], const uint32_t a[4],
                                         uint32_t b0, uint32_t b1) {
    asm volatile("mma.sync.aligned.m16n8k16.row.col.f32.bf16.bf16.f32 "
        "{%0,%1,%2,%3}, {%4,%5,%6,%7}, {%8,%9}, {%0,%1,%2,%3};"
        : "+f"(c[0]), "+f"(c[1]), "+f"(c[2]), "+f"(c[3])
        : "r"(a[0]), "r"(a[1]), "r"(a[2]), "r"(a[3]), "r"(b0), "r"(b1));
}

__device__ __forceinline__ float gelu_f(float x) {
    const float c = 0.7978845608028654f;
    float x3 = x * x * x;
    return 0.5f * x * (1.0f + tanhf(c * (x + 0.044715f * x3)));
}

__device__ __forceinline__ void split_pack(float a, float b, uint32_t& hp, uint32_t& lp) {
    __nv_bfloat16 ha = __float2bfloat16(a), hb = __float2bfloat16(b);
    __nv_bfloat16 la = __float2bfloat16(a - __bfloat162float(ha));
    __nv_bfloat16 lb = __float2bfloat16(b - __bfloat162float(hb));
    hp = ((uint32_t)__bfloat16_as_ushort(hb) << 16) | __bfloat16_as_ushort(ha);
    lp = ((uint32_t)__bfloat16_as_ushort(lb) << 16) | __bfloat16_as_ushort(la);
}

// ---------------- HMMA bf16x3 GEMM --------------------------------------------
// C[M,N] = A[M,K]*B^T (B [N,K] hi/lo). CTA tile 128x128, 512 threads (16 warps,
// warp tile 32x32), KC=64, 2-stage cp.async pipeline, 128B swizzled rows.
// EPI: 0 plain, 1 +bias, 2 gelu(+bias), 3 residual (f32). OBF: bf16 hi/lo out.
#define KC 64
#define PLANE_B 16384              // 128 rows * 128 bytes
#define STAGE_B (4 * PLANE_B)
#define GSMEM_NEED (2 * STAGE_B + 128)

template <int EPI, bool NPRED, bool OBF>
__global__ void __launch_bounds__(512, 1)
gemm_tc(const __nv_bfloat16* __restrict__ Ah, const __nv_bfloat16* __restrict__ Al,
        const __nv_bfloat16* __restrict__ Bh, const __nv_bfloat16* __restrict__ Bl,
        const float* __restrict__ bias, float* __restrict__ C,
        __nv_bfloat16* __restrict__ CH, __nv_bfloat16* __restrict__ CL,
        int N, int K) {
    extern __shared__ char dsm[];
    uint32_t sb = (smem_u32(dsm) + 127) & ~127u;

    const int tid = threadIdx.x;
    const int wid = tid >> 5, lid = tid & 31;
    const long bm = (long)blockIdx.x * 128;
    const long bn = (long)blockIdx.y * 128;
    const int wm = (wid >> 2) * 32;           // 4x4 warp grid, warp tile 32x32
    const int wn = (wid & 3) * 32;
    const int lrow = lid & 15, lg = lid >> 4;

    const int nch = K / KC;

    auto load_stage = [&](int c, int st) {
        uint32_t stb = sb + st * STAGE_B;
        int kc0 = c * KC;
        #pragma unroll
        for (int i = 0; i < 2; i++) {
            int u = tid + 512 * i;            // 0..1023
            int row = u >> 3, g = u & 7;
            uint32_t so = stb + row * 128 + ((g ^ (row & 7)) << 4);
            long ka = (bm + row) * (long)K + kc0 + g * 8;
            long kb = (bn + row) * (long)K + kc0 + g * 8;
            CP_ASYNC16(so,               Ah + ka);
            CP_ASYNC16(so + PLANE_B,     Al + ka);
            CP_ASYNC16(so + 2 * PLANE_B, Bh + kb);
            CP_ASYNC16(so + 3 * PLANE_B, Bl + kb);
        }
        CP_COMMIT();
    };

    float creg[2][4][4];
    #pragma unroll
    for (int a = 0; a < 2; a++)
        #pragma unroll
        for (int b = 0; b < 4; b++)
            #pragma unroll
            for (int k = 0; k < 4; k++) creg[a][b][k] = 0.f;

    load_stage(0, 0);
    load_stage(1, 1);

    for (int c = 0; c < nch; c++) {
        if (c + 1 < nch) { asm volatile("cp.async.wait_group 1;" ::: "memory"); }
        else             { asm volatile("cp.async.wait_group 0;" ::: "memory"); }
        __syncthreads();

        uint32_t stb = sb + (c & 1) * STAGE_B;
        #pragma unroll
        for (int ks = 0; ks < 4; ks++) {
            int g = 2 * ks + lg;
            uint32_t aH[2][4], aL[2][4], bH[2][4], bL[2][4];
            #pragma unroll
            for (int mi = 0; mi < 2; mi++) {
                int row = wm + mi * 16 + lrow;
                uint32_t off = row * 128 + ((g ^ (row & 7)) << 4);
                ldsm4(aH[mi], stb + off);
                ldsm4(aL[mi], stb + PLANE_B + off);
            }
            #pragma unroll
            for (int ng = 0; ng < 2; ng++) {
                int row = wn + ng * 16 + lrow;
                uint32_t off = row * 128 + ((g ^ (row & 7)) << 4);
                ldsm4(bH[ng], stb + 2 * PLANE_B + off);
                ldsm4(bL[ng], stb + 3 * PLANE_B + off);
            }
            // pass 1: hi*hi (8 independent MMAs)
            #pragma unroll
            for (int mi = 0; mi < 2; mi++)
                #pragma unroll
                for (int ni = 0; ni < 4; ni++) {
                    int ng = ni >> 1, h = ni & 1;
                    mma_bf16(creg[mi][ni], aH[mi], bH[ng][h], bH[ng][h + 2]);
                }
            // pass 2: hi*lo
            #pragma unroll
            for (int mi = 0; mi < 2; mi++)
                #pragma unroll
                for (int ni = 0; ni < 4; ni++) {
                    int ng = ni >> 1, h = ni & 1;
                    mma_bf16(creg[mi][ni], aH[mi], bL[ng][h], bL[ng][h + 2]);
                }
            // pass 3: lo*hi
            #pragma unroll
            for (int mi = 0; mi < 2; mi++)
                #pragma unroll
                for (int ni = 0; ni < 4; ni++) {
                    int ng = ni >> 1, h = ni & 1;
                    mma_bf16(creg[mi][ni], aL[mi], bH[ng][h], bH[ng][h + 2]);
                }
        }
        __syncthreads();
        if (c + 2 < nch) load_stage(c + 2, c & 1);
    }

    // ---- epilogue ----
    int gid = lid >> 2, tin = lid & 3;
    #pragma unroll
    for (int mi = 0; mi < 2; mi++) {
        long row0 = bm + wm + mi * 16 + gid;
        long row1 = row0 + 8;
        #pragma unroll
        for (int ni = 0; ni < 4; ni++) {
            long col = bn + wn + ni * 8 + tin * 2;
            float b0 = 0.f, b1 = 0.f;
            if (EPI >= 1) { b0 = bias[col]; b1 = bias[col + 1]; }
            float v0 = creg[mi][ni][0] + b0;
            float v1 = creg[mi][ni][1] + b1;
            float v2 = creg[mi][ni][2] + b0;
            float v3 = creg[mi][ni][3] + b1;
            if (EPI == 2) { v0 = gelu_f(v0); v1 = gelu_f(v1); v2 = gelu_f(v2); v3 = gelu_f(v3); }
            if (OBF) {
                uint32_t hp, lp;
                size_t o0 = (size_t)row0 * N + col;
                size_t o1 = (size_t)row1 * N + col;
                split_pack(v0, v1, hp, lp);
                *(uint32_t*)&CH[o0] = hp; *(uint32_t*)&CL[o0] = lp;
                split_pack(v2, v3, hp, lp);
                *(uint32_t*)&CH[o1] = hp; *(uint32_t*)&CL[o1] = lp;
            } else if (NPRED) {
                if (col < N)     { C[row0 * N + col]     = v0; C[row1 * N + col]     = v2; }
                if (col + 1 < N) { C[row0 * N + col + 1] = v1; C[row1 * N + col + 1] = v3; }
            } else {
                size_t o0 = (size_t)row0 * N + col;
                size_t o1 = (size_t)row1 * N + col;
                if (EPI == 3) {
                    float2 c0 = *(float2*)&C[o0];
                    float2 c1 = *(float2*)&C[o1];
                    v0 += c0.x; v1 += c0.y; v2 += c1.x; v3 += c1.y;
                }
                *(float2*)&C[o0] = make_float2(v0, v1);
                *(float2*)&C[o1] = make_float2(v2, v3);
            }
        }
    }
}

// ---------------- HMMA flash attention ----------------------------------------
// grid (SEQ/64, NHEAD, B), 128 threads. Warp w owns q rows [w*16, w*16+16).
#define ATT_SMEM (16384 + 2 * 32768 + 128)

__global__ void __launch_bounds__(128, 2)
attn_tc(const __nv_bfloat16* __restrict__ QKVh, const __nv_bfloat16* __restrict__ QKVl,
        __nv_bfloat16* __restrict__ Yh, __nv_bfloat16* __restrict__ Yl) {
    extern __shared__ char dsm[];
    uint32_t sb = (smem_u32(dsm) + 127) & ~127u;

    const int tid = threadIdx.x;
    const int wid = tid >> 5, lid = tid & 31;
    const int q0 = blockIdx.x * 64, h = blockIdx.y, b = blockIdx.z;
    const int wq = wid * 16;
    const int ntile = blockIdx.x + 1;
    const size_t rstride = 3 * DMODEL;

    auto ldplane = [&](uint32_t dst, const __nv_bfloat16* src) {
        #pragma unroll
        for (int i = 0; i < 4; i++) {
            int u = tid + 128 * i;
            int row = u >> 3, ch = u & 7;
            CP_ASYNC16(dst + row * 128 + ((ch ^ (row & 7)) << 4),
                       src + (size_t)row * rstride + ch * 8);
        }
    };
    auto ldstage = [&](int t) {
        uint32_t s = sb + 16384 + (t & 1) * 32768;
        size_t off = (size_t)(b * SEQ + t * 64) * rstride + h * HDIM;
        ldplane(s,         QKVh + off + DMODEL);
        ldplane(s + 8192,  QKVl + off + DMODEL);
        ldplane(s + 16384, QKVh + off + 2 * DMODEL);
        ldplane(s + 24576, QKVl + off + 2 * DMODEL);
        CP_COMMIT();
    };

    {
        size_t qoff = (size_t)(b * SEQ + q0) * rstride + h * HDIM;
        ldplane(sb,        QKVh + qoff);
        ldplane(sb + 8192, QKVl + qoff);
    }
    ldstage(0);

    float o[8][4];
    #pragma unroll
    for (int nb = 0; nb < 8; nb++)
        #pragma unroll
        for (int j = 0; j < 4; j++) o[nb][j] = 0.f;
    float mrun[2] = {-1e30f, -1e30f}, lrun[2] = {0.f, 0.f};

    for (int t = 0; t < ntile; t++) {
        asm volatile("cp.async.wait_group 0;" ::: "memory");
        __syncthreads();
        if (t + 1 < ntile) ldstage(t + 1);
        uint32_t kb = sb + 16384 + (t & 1) * 32768;

        float s[8][4];
        #pragma unroll
        for (int nb = 0; nb < 8; nb++)
            #pragma unroll
            for (int j = 0; j < 4; j++) s[nb][j] = 0.f;

        #pragma unroll
        for (int ks = 0; ks < 4; ks++) {
            uint32_t qh[4], ql[4];
            {
                int r = wq + (lid & 15);
                uint32_t off = r * 128 + (((2 * ks + (lid >> 4)) ^ (r & 7)) << 4);
                ldsm4(qh, sb + off);
                ldsm4(ql, sb + 8192 + off);
            }
            #pragma unroll
            for (int ng = 0; ng < 4; ng++) {
                int r = ng * 16 + (lid & 15);
                uint32_t off = r * 128 + (((2 * ks + (lid >> 4)) ^ (r & 7)) << 4);
                uint32_t kh[4], kl[4];
                ldsm4(kh, kb + off);
                ldsm4(kl, kb + 8192 + off);
                mma_bf16(s[2 * ng],     qh, kh[0], kh[2]);
                mma_bf16(s[2 * ng],     qh, kl[0], kl[2]);
                mma_bf16(s[2 * ng],     ql, kh[0], kh[2]);
                mma_bf16(s[2 * ng + 1], qh, kh[1], kh[3]);
                mma_bf16(s[2 * ng + 1], qh, kl[1], kl[3]);
                mma_bf16(s[2 * ng + 1], ql, kh[1], kh[3]);
            }
        }

        #pragma unroll
        for (int nb = 0; nb < 8; nb++)
            #pragma unroll
            for (int j = 0; j < 4; j++) s[nb][j] *= 0.125f;

        if (t == blockIdx.x) {
            int r0g = q0 + wq + (lid >> 2);
            #pragma unroll
            for (int nb = 0; nb < 8; nb++) {
                int colg = t * 64 + nb * 8 + (lid & 3) * 2;
                if (colg     > r0g)     s[nb][0] = -1e30f;
                if (colg + 1 > r0g)     s[nb][1] = -1e30f;
                if (colg     > r0g + 8) s[nb][2] = -1e30f;
                if (colg + 1 > r0g + 8) s[nb][3] = -1e30f;
            }
        }

        #pragma unroll
        for (int half = 0; half < 2; half++) {
            float mx = -1e30f;
            #pragma unroll
            for (int nb = 0; nb < 8; nb++)
                mx = fmaxf(mx, fmaxf(s[nb][2 * half], s[nb][2 * half + 1]));
            mx = fmaxf(mx, __shfl_xor_sync(~0u, mx, 1));
            mx = fmaxf(mx, __shfl_xor_sync(~0u, mx, 2));
            float mn = fmaxf(mrun[half], mx);
            float al = __expf(mrun[half] - mn);
            mrun[half] = mn;
            float sum = 0.f;
            #pragma unroll
            for (int nb = 0; nb < 8; nb++) {
                float p0 = __expf(s[nb][2 * half]     - mn);
                float p1 = __expf(s[nb][2 * half + 1] - mn);
                s[nb][2 * half] = p0; s[nb][2 * half + 1] = p1;
                sum += p0 + p1;
            }
            lrun[half] = lrun[half] * al + sum;
            #pragma unroll
            for (int nb = 0; nb < 8; nb++) {
                o[nb][2 * half] *= al; o[nb][2 * half + 1] *= al;
            }
        }

        #pragma unroll
        for (int kk = 0; kk < 4; kk++) {
            uint32_t ph[4], pl[4];
            split_pack(s[2 * kk][0],     s[2 * kk][1],     ph[0], pl[0]);
            split_pack(s[2 * kk][2],     s[2 * kk][3],     ph[1], pl[1]);
            split_pack(s[2 * kk + 1][0], s[2 * kk + 1][1], ph[2], pl[2]);
            split_pack(s[2 * kk + 1][2], s[2 * kk + 1][3], ph[3], pl[3]);
            #pragma unroll
            for (int cc = 0; cc < 4; cc++) {
                int r = kk * 16 + (lid & 15);
                uint32_t off = r * 128 + (((2 * cc + (lid >> 4)) ^ (r & 7)) << 4);
                uint32_t vh[4], vl[4];
                ldsm4t(vh, kb + 16384 + off);
                ldsm4t(vl, kb + 24576 + off);
                mma_bf16(o[2 * cc],     ph, vh[0], vh[1]);
                mma_bf16(o[2 * cc],     pl, vh[0], vh[1]);
                mma_bf16(o[2 * cc],     ph, vl[0], vl[1]);
                mma_bf16(o[2 * cc + 1], ph, vh[2], vh[3]);
                mma_bf16(o[2 * cc + 1], pl, vh[2], vh[3]);
                mma_bf16(o[2 * cc + 1], ph, vl[2], vl[3]);
            }
        }
    }

    float inv[2];
    #pragma unroll
    for (int half = 0; half < 2; half++) {
        float l = lrun[half];
        l += __shfl_xor_sync(~0u, l, 1);
        l += __shfl_xor_sync(~0u, l, 2);
        inv[half] = 1.0f / l;
    }
    int r0 = q0 + wq + (lid >> 2);
    #pragma unroll
    for (int nb = 0; nb < 8; nb++) {
        int col = h * HDIM + nb * 8 + (lid & 3) * 2;
        size_t o0 = (size_t)(b * SEQ + r0) * DMODEL + col;
        size_t o1 = (size_t)(b * SEQ + r0 + 8) * DMODEL + col;
        uint32_t hp, lp;
        split_pack(o[nb][0] * inv[0], o[nb][1] * inv[0], hp, lp);
        *(uint32_t*)&Yh[o0] = hp; *(uint32_t*)&Yl[o0] = lp;
        split_pack(o[nb][2] * inv[1], o[nb][3] * inv[1], hp, lp);
        *(uint32_t*)&Yh[o1] = hp; *(uint32_t*)&Yl[o1] = lp;
    }
}

// ---------------- weight conversion (batched over layers via grid.z) ----------
__global__ void cvt_wte_k(const float* __restrict__ wte) {
    size_t i = (size_t)blockIdx.x * 256 + threadIdx.x;
    if (i >= (size_t)VPAD * DMODEL) return;
    float v = (i < (size_t)VOCAB * DMODEL) ? wte[i] : 0.0f;
    __nv_bfloat16 hb = __float2bfloat16(v);
    g_wteH[i] = hb;
    g_wteL[i] = __float2bfloat16(v - __bfloat162float(hb));
}

// w [L,K,N] f32 -> out [L,N,K] bf16 hi/lo. grid (N/32, K/32, L), block (32,8)
__global__ void cvt_wT(const float* __restrict__ w, __nv_bfloat16* __restrict__ th,
                       __nv_bfloat16* __restrict__ tl, int K, int N) {
    __shared__ float t[32][33];
    const float* wsrc = w + (size_t)blockIdx.z * K * N;
    __nv_bfloat16* thd = th + (size_t)blockIdx.z * N * K;
    __nv_bfloat16* tld = tl + (size_t)blockIdx.z * N * K;
    int n0 = blockIdx.x * 32, k0 = blockIdx.y * 32;
    int tx = threadIdx.x, ty = threadIdx.y;
    #pragma unroll
    for (int i = 0; i < 4; i++)
        t[ty + 8 * i][tx] = wsrc[(size_t)(k0 + ty + 8 * i) * N + n0 + tx];
    __syncthreads();
    #pragma unroll
    for (int i = 0; i < 4; i++) {
        float v = t[tx][ty + 8 * i];
        __nv_bfloat16 hb = __float2bfloat16(v);
        size_t o = (size_t)(n0 + ty + 8 * i) * K + k0 + tx;
        thd[o] = hb;
        tld[o] = __float2bfloat16(v - __bfloat162float(hb));
    }
}

// ---------------- embedding --------------------------------------------------
__global__ void embed_kernel(const int* __restrict__ idx,
                             const float* __restrict__ wte,
                             const float* __restrict__ wpe) {
    int row = blockIdx.x;
    int t = row & (SEQ - 1);
    int tok = idx[row];
    const float* we = wte + (size_t)tok * DMODEL;
    const float* wp = wpe + (size_t)t * DMODEL;
    float* xr = g_x + (size_t)row * DMODEL;
    for (int d = threadIdx.x; d < DMODEL; d += blockDim.x)
        xr[d] = we[d] + wp[d];
}

// ---------------- layernorm (writes bf16 hi/lo planes) -----------------------
__global__ void __launch_bounds__(256) ln_kernel(const float* __restrict__ x,
                                                 const float* __restrict__ sc,
                                                 const float* __restrict__ bi,
                                                 __nv_bfloat16* __restrict__ outH,
                                                 __nv_bfloat16* __restrict__ outL) {
    __shared__ float red[8];
    int row = blockIdx.x, tid = threadIdx.x;
    const float* xr = x + (size_t)row * DMODEL;
    float v0 = xr[tid], v1 = xr[tid + 256], v2 = xr[tid + 512];

    float s = v0 + v1 + v2;
    #pragma unroll
    for (int o = 16; o > 0; o >>= 1) s += __shfl_xor_sync(~0u, s, o);
    if ((tid & 31) == 0) red[tid >> 5] = s;
    __syncthreads();
    if (tid < 32) {
        float t = (tid < 8) ? red[tid] : 0.f;
        #pragma unroll
        for (int o = 4; o > 0; o >>= 1) t += __shfl_xor_sync(~0u, t, o);
        if (tid == 0) red[0] = t;
    }
    __syncthreads();
    float mu = red[0] * (1.0f / DMODEL);
    __syncthreads();

    float d0 = v0 - mu, d1 = v1 - mu, d2 = v2 - mu;
    float s2 = d0 * d0 + d1 * d1 + d2 * d2;
    #pragma unroll
    for (int o = 16; o > 0; o >>= 1) s2 += __shfl_xor_sync(~0u, s2, o);
    if ((tid & 31) == 0) red[tid >> 5] = s2;
    __syncthreads();
    if (tid < 32) {
        float t = (tid < 8) ? red[tid] : 0.f;
        #pragma unroll
        for (int o = 4; o > 0; o >>= 1) t += __shfl_xor_sync(~0u, t, o);
        if (tid == 0) red[0] = t;
    }
    __syncthreads();
    float var = red[0] * (1.0f / DMODEL);
    float rs = rsqrtf(var + 1e-5f);

    size_t base = (size_t)row * DMODEL;
    #pragma unroll
    for (int e = 0; e < 3; e++) {
        float d = (e == 0) ? d0 : (e == 1) ? d1 : d2;
        int c = tid + 256 * e;
        float v = d * rs * sc[c] + bi[c];
        __nv_bfloat16 hb = __float2bfloat16(v);
        outH[base + c] = hb;
        outL[base + c] = __float2bfloat16(v - __bfloat162float(hb));
    }
}

// ---------------- loss --------------------------------------------------------
__global__ void __launch_bounds__(256) lossrow_kernel(const float* __restrict__ logits,
                                                      const int* __restrict__ targets) {
    int row = blockIdx.x;
    const float* lr_ = logits + (size_t)row * VOCAB;
    float m = -1e30f, s = 0.f;
    for (int jv = threadIdx.x; jv < VOCAB; jv += 256) {
        float v = lr_[jv];
        if (v <= m) {
            s += __expf(v - m);
        } else {
            s = s * __expf(m - v) + 1.0f;
            m = v;
        }
    }
    __shared__ float sm[256], ss[256];
    sm[threadIdx.x] = m; ss[threadIdx.x] = s;
    __syncthreads();
    for (int st = 128; st > 0; st >>= 1) {
        if (threadIdx.x < st) {
            float ma = sm[threadIdx.x], sa = ss[threadIdx.x];
            float mb = sm[threadIdx.x + st], sb = ss[threadIdx.x + st];
            float M = fmaxf(ma, mb);
            ss[threadIdx.x] = sa * __expf(ma - M) + sb * __expf(mb - M);
            sm[threadIdx.x] = M;
        }
        __syncthreads();
    }
    if (threadIdx.x == 0) {
        float lse = sm[0] + logf(ss[0]);
        g_rowloss[row] = lse - lr_[targets[row]];
    }
}

__global__ void __launch_bounds__(256) lossreduce_kernel(float* __restrict__ out_loss) {
    __shared__ float red[8];
    float s = 0.f;
    for (int i = threadIdx.x; i < NTOK; i += 256) s += g_rowloss[i];
    #pragma unroll
    for (int o = 16; o > 0; o >>= 1) s += __shfl_xor_sync(~0u, s, o);
    if ((threadIdx.x & 31) == 0) red[threadIdx.x >> 5] = s;
    __syncthreads();
    if (threadIdx.x == 0) {
        float t = 0.f;
        for (int w = 0; w < 8; w++) t += red[w];
        out_loss[0] = t * (1.0f / NTOK);
    }
}

// ---------------- host orchestration -----------------------------------------
extern "C" void kernel_launch(void* const* d_in, const int* in_sizes, int n_in,
                              void* d_out, int out_size) {
    const int*   idx     = (const int*)  d_in[0];
    const int*   targets = (const int*)  d_in[1];
    const float* wte     = (const float*)d_in[2];
    const float* wpe     = (const float*)d_in[3];
    const float* ln1_s   = (const float*)d_in[4];
    const float* ln1_b   = (const float*)d_in[5];
    const float* attn_w  = (const float*)d_in[6];
    const float* attn_b  = (const float*)d_in[7];
    const float* proj_w  = (const float*)d_in[8];
    const float* proj_b  = (const float*)d_in[9];
    const float* ln2_s   = (const float*)d_in[10];
    const float* ln2_b   = (const float*)d_in[11];
    const float* fc_w    = (const float*)d_in[12];
    const float* fc_b    = (const float*)d_in[13];
    const float* proj2_w = (const float*)d_in[14];
    const float* proj2_b = (const float*)d_in[15];
    const float* lnf_s   = (const float*)d_in[16];
    const float* lnf_b   = (const float*)d_in[17];
    float* out = (float*)d_out;

    float* px;
    __nv_bfloat16 *phH, *phL, *pqH, *pqL, *pyH, *pyL, *pmH, *pmL;
    __nv_bfloat16 *pwTh, *pwTl, *pwteH, *pwteL;
    cudaGetSymbolAddress((void**)&px, g_x);
    cudaGetSymbolAddress((void**)&phH, g_hH);
    cudaGetSymbolAddress((void**)&phL, g_hL);
    cudaGetSymbolAddress((void**)&pqH, g_qkvH);
    cudaGetSymbolAddress((void**)&pqL, g_qkvL);
    cudaGetSymbolAddress((void**)&pyH, g_yH);
    cudaGetSymbolAddress((void**)&pyL, g_yL);
    cudaGetSymbolAddress((void**)&pmH, g_mH);
    cudaGetSymbolAddress((void**)&pmL, g_mL);
    cudaGetSymbolAddress((void**)&pwTh, g_wTh);
    cudaGetSymbolAddress((void**)&pwTl, g_wTl);
    cudaGetSymbolAddress((void**)&pwteH, g_wteH);
    cudaGetSymbolAddress((void**)&pwteL, g_wteL);

    cudaFuncSetAttribute(gemm_tc<1, false, true>,  cudaFuncAttributeMaxDynamicSharedMemorySize, GSMEM_NEED);
    cudaFuncSetAttribute(gemm_tc<2, false, true>,  cudaFuncAttributeMaxDynamicSharedMemorySize, GSMEM_NEED);
    cudaFuncSetAttribute(gemm_tc<3, false, false>, cudaFuncAttributeMaxDynamicSharedMemorySize, GSMEM_NEED);
    cudaFuncSetAttribute(gemm_tc<0, true, false>,  cudaFuncAttributeMaxDynamicSharedMemorySize, GSMEM_NEED);
    cudaFuncSetAttribute(attn_tc, cudaFuncAttributeMaxDynamicSharedMemorySize, ATT_SMEM);

    embed_kernel<<<NTOK, 256>>>(idx, wte, wpe);

    // --- all weight conversions up-front (batched over layers) ---
    cvt_wT<<<dim3(3 * DMODEL / 32, DMODEL / 32, NLAYER), dim3(32, 8)>>>(
        attn_w, pwTh + OFF_ATTN, pwTl + OFF_ATTN, DMODEL, 3 * DMODEL);
    cvt_wT<<<dim3(DMODEL / 32, DMODEL / 32, NLAYER), dim3(32, 8)>>>(
        proj_w, pwTh + OFF_PROJ, pwTl + OFF_PROJ, DMODEL, DMODEL);
    cvt_wT<<<dim3(4 * DMODEL / 32, DMODEL / 32, NLAYER), dim3(32, 8)>>>(
        fc_w, pwTh + OFF_FC, pwTl + OFF_FC, DMODEL, 4 * DMODEL);
    cvt_wT<<<dim3(DMODEL / 32, 4 * DMODEL / 32, NLAYER), dim3(32, 8)>>>(
        proj2_w, pwTh + OFF_PROJ2, pwTl + OFF_PROJ2, 4 * DMODEL, DMODEL);
    {
        size_t nw = (size_t)VPAD * DMODEL;
        cvt_wte_k<<<(unsigned)((nw + 255) / 256), 256>>>(wte);
    }

    for (int l = 0; l < NLAYER; l++) {
        const float* ab  = attn_b  + (size_t)l * 3 * DMODEL;
        const float* pb  = proj_b  + (size_t)l * DMODEL;
        const float* fb  = fc_b    + (size_t)l * 4 * DMODEL;
        const float* p2b = proj2_b + (size_t)l * DMODEL;
        size_t oAttn  = OFF_ATTN  + (size_t)l * SZ_ATTN;
        size_t oProj  = OFF_PROJ  + (size_t)l * SZ_PROJ;
        size_t oFc    = OFF_FC    + (size_t)l * SZ_FC;
        size_t oProj2 = OFF_PROJ2 + (size_t)l * SZ_PROJ2;

        // --- attention block ---
        ln_kernel<<<NTOK, 256>>>(px, ln1_s + l * DMODEL, ln1_b + l * DMODEL, phH, phL);
        gemm_tc<1, false, true><<<dim3(NTOK / 128, 3 * DMODEL / 128), 512, GSMEM_NEED>>>(
            phH, phL, pwTh + oAttn, pwTl + oAttn, ab, nullptr, pqH, pqL, 3 * DMODEL, DMODEL);
        attn_tc<<<dim3(SEQ / 64, NHEAD, 2), 128, ATT_SMEM>>>(pqH, pqL, pyH, pyL);
        gemm_tc<3, false, false><<<dim3(NTOK / 128, DMODEL / 128), 512, GSMEM_NEED>>>(
            pyH, pyL, pwTh + oProj, pwTl + oProj, pb, px, nullptr, nullptr, DMODEL, DMODEL);

        // --- MLP block ---
        ln_kernel<<<NTOK, 256>>>(px, ln2_s + l * DMODEL, ln2_b + l * DMODEL, phH, phL);
        gemm_tc<2, false, true><<<dim3(NTOK / 128, 4 * DMODEL / 128), 512, GSMEM_NEED>>>(
            phH, phL, pwTh + oFc, pwTl + oFc, fb, nullptr, pmH, pmL, 4 * DMODEL, DMODEL);
        gemm_tc<3, false, false><<<dim3(NTOK / 128, DMODEL / 128), 512, GSMEM_NEED>>>(
            pmH, pmL, pwTh + oProj2, pwTl + oProj2, p2b, px, nullptr, nullptr, DMODEL, 4 * DMODEL);
    }

    // --- final LN + tied lm_head + loss ---
    ln_kernel<<<NTOK, 256>>>(px, lnf_s, lnf_b, phH, phL);
    gemm_tc<0, true, false><<<dim3(NTOK / 128, VPAD / 128), 512, GSMEM_NEED>>>(
        phH, phL, pwteH, pwteL, nullptr, out, nullptr, nullptr, VOCAB, DMODEL);

    lossrow_kernel<<<NTOK, 256>>>(out, targets);
    lossreduce_kernel<<<1, 256>>>(out + (size_t)NTOK * VOCAB);
}

// round 7
// speedup vs baseline: 1.3835x; 1.1981x over previous
#include <cuda_runtime.h>
#include <cuda_bf16.h>
#include <math.h>
#include <stdint.h>

// Problem constants
#define NTOK 2048          // B*T
#define SEQ  1024
#define DMODEL 768
#define NHEAD 12
#define HDIM 64
#define NLAYER 8
#define VOCAB 50257
#define VPAD  50304        // 393*128

// per-layer transposed-weight plane offsets (elements)
#define OFF_ATTN  0
#define SZ_ATTN   (3 * DMODEL * DMODEL)
#define OFF_PROJ  (NLAYER * SZ_ATTN)
#define SZ_PROJ   (DMODEL * DMODEL)
#define OFF_FC    (OFF_PROJ + NLAYER * SZ_PROJ)
#define SZ_FC     (4 * DMODEL * DMODEL)
#define OFF_PROJ2 (OFF_FC + NLAYER * SZ_FC)
#define SZ_PROJ2  (4 * DMODEL * DMODEL)
#define WT_TOTAL  (OFF_PROJ2 + NLAYER * SZ_PROJ2)

// ---------------- scratch (device globals; no allocation allowed) ------------
__device__ float g_x[NTOK * DMODEL];
__device__ float g_rowloss[NTOK];
__device__ float g_hf[NTOK * DMODEL];        // LN out, tf32-rounded
__device__ float g_yf[NTOK * DMODEL];        // attn out, tf32-rounded
__device__ float g_mf[NTOK * 4 * DMODEL];    // mlp hidden, tf32-rounded
__device__ float g_wTf[WT_TOTAL];            // transposed weights, tf32-rounded
__device__ __nv_bfloat16 g_hH [NTOK * DMODEL];       // final LN hi/lo (lm_head)
__device__ __nv_bfloat16 g_hL [NTOK * DMODEL];
__device__ __nv_bfloat16 g_qkvH[NTOK * 3 * DMODEL];  // qkv hi/lo (attention)
__device__ __nv_bfloat16 g_qkvL[NTOK * 3 * DMODEL];
__device__ __nv_bfloat16 g_wteH[(size_t)VPAD * DMODEL];
__device__ __nv_bfloat16 g_wteL[(size_t)VPAD * DMODEL];

// ---------------- helpers -----------------------------------------------------
__device__ __forceinline__ uint32_t smem_u32(const void* p) {
    uint32_t a;
    asm("{ .reg .u64 t; cvta.to.shared.u64 t, %1; cvt.u32.u64 %0, t; }" : "=r"(a) : "l"(p));
    return a;
}

#define CP_ASYNC16(s, g) \
    asm volatile("cp.async.cg.shared.global [%0], [%1], 16;" :: "r"(s), "l"(g) : "memory")
#define CP_COMMIT() asm volatile("cp.async.commit_group;" ::: "memory")

__device__ __forceinline__ void ldsm4(uint32_t r[4], uint32_t addr) {
    asm volatile("ldmatrix.sync.aligned.m8n8.x4.shared.b16 {%0,%1,%2,%3}, [%4];"
        : "=r"(r[0]), "=r"(r[1]), "=r"(r[2]), "=r"(r[3]) : "r"(addr));
}
__device__ __forceinline__ void ldsm4t(uint32_t r[4], uint32_t addr) {
    asm volatile("ldmatrix.sync.aligned.m8n8.x4.trans.shared.b16 {%0,%1,%2,%3}, [%4];"
        : "=r"(r[0]), "=r"(r[1]), "=r"(r[2]), "=r"(r[3]) : "r"(addr));
}
__device__ __forceinline__ void mma_bf16(float c[4], const uint32_t a[4],
                                         uint32_t b0, uint32_t b1) {
    asm volatile("mma.sync.aligned.m16n8k16.row.col.f32.bf16.bf16.f32 "
        "{%0,%1,%2,%3}, {%4,%5,%6,%7}, {%8,%9}, {%0,%1,%2,%3};"
        : "+f"(c[0]), "+f"(c[1]), "+f"(c[2]), "+f"(c[3])
        : "r"(a[0]), "r"(a[1]), "r"(a[2]), "r"(a[3]), "r"(b0), "r"(b1));
}
__device__ __forceinline__ void mma_tf32(float c[4], const uint32_t a[4],
                                         uint32_t b0, uint32_t b1) {
    asm volatile("mma.sync.aligned.m16n8k8.row.col.f32.tf32.tf32.f32 "
        "{%0,%1,%2,%3}, {%4,%5,%6,%7}, {%8,%9}, {%0,%1,%2,%3};"
        : "+f"(c[0]), "+f"(c[1]), "+f"(c[2]), "+f"(c[3])
        : "r"(a[0]), "r"(a[1]), "r"(a[2]), "r"(a[3]), "r"(b0), "r"(b1));
}
__device__ __forceinline__ uint32_t lds_b32(uint32_t addr) {
    uint32_t v;
    asm volatile("ld.shared.b32 %0, [%1];" : "=r"(v) : "r"(addr));
    return v;
}

__device__ __forceinline__ float tf32r(float x) {
    uint32_t r;
    asm("cvt.rna.tf32.f32 %0, %1;" : "=r"(r) : "f"(x));
    return __uint_as_float(r);
}

__device__ __forceinline__ float gelu_f(float x) {
    const float c = 0.7978845608028654f;
    float x3 = x * x * x;
    return 0.5f * x * (1.0f + tanhf(c * (x + 0.044715f * x3)));
}

__device__ __forceinline__ void split_pack(float a, float b, uint32_t& hp, uint32_t& lp) {
    __nv_bfloat16 ha = __float2bfloat16(a), hb = __float2bfloat16(b);
    __nv_bfloat16 la = __float2bfloat16(a - __bfloat162float(ha));
    __nv_bfloat16 lb = __float2bfloat16(b - __bfloat162float(hb));
    hp = ((uint32_t)__bfloat16_as_ushort(hb) << 16) | __bfloat16_as_ushort(ha);
    lp = ((uint32_t)__bfloat16_as_ushort(lb) << 16) | __bfloat16_as_ushort(la);
}

// ---------------- TF32 GEMM (layer GEMMs) -------------------------------------
// C[M,N] = A[M,K]*B^T, A fp32(tf32-rounded) [M,K], B fp32(tf32-rounded) [N,K].
// CTA tile 128x128, 512 threads (16 warps, warp tile 32x32), KC=64, 2-stage.
// EPI: 1 = +bias -> bf16 hi/lo planes (qkv); 2 = gelu(+bias) -> tf32 f32 (fc);
//      3 = +bias, residual C += (proj/proj2).
#define TKC 64
#define TROWB 256                   // 64 fp32 per row
#define TPLANE (128 * TROWB)        // 32KB
#define TSTAGE (2 * TPLANE)         // 64KB (A + B)
#define TSMEM_NEED (2 * TSTAGE + 128)

template <int EPI>
__global__ void __launch_bounds__(512, 1)
gemm_tf32(const float* __restrict__ A, const float* __restrict__ B,
          const float* __restrict__ bias, float* __restrict__ C,
          __nv_bfloat16* __restrict__ CH, __nv_bfloat16* __restrict__ CL,
          int N, int K) {
    extern __shared__ char dsm[];
    uint32_t sb = (smem_u32(dsm) + 127) & ~127u;

    const int tid = threadIdx.x;
    const int wid = tid >> 5, lid = tid & 31;
    const long bm = (long)blockIdx.x * 128;
    const long bn = (long)blockIdx.y * 128;
    const int wm = (wid >> 2) * 32;
    const int wn = (wid & 3) * 32;

    const int nch = K / TKC;

    auto load_stage = [&](int c, int st) {
        uint32_t stb = sb + st * TSTAGE;
        int kc0 = c * TKC;
        #pragma unroll
        for (int i = 0; i < 4; i++) {
            int u = tid + 512 * i;            // 0..2047
            int row = u >> 4, g = u & 15;
            uint32_t so = stb + row * TROWB + ((g ^ (row & 7)) << 4);
            long ka = (bm + row) * (long)K + kc0 + g * 4;
            long kb = (bn + row) * (long)K + kc0 + g * 4;
            CP_ASYNC16(so,          A + ka);
            CP_ASYNC16(so + TPLANE, B + kb);
        }
        CP_COMMIT();
    };

    float creg[2][4][4];
    #pragma unroll
    for (int a = 0; a < 2; a++)
        #pragma unroll
        for (int b = 0; b < 4; b++)
            #pragma unroll
            for (int k = 0; k < 4; k++) creg[a][b][k] = 0.f;

    load_stage(0, 0);
    load_stage(1, 1);

    // A-ldsm lane mapping: lanes 0-7->tile0(rows0-7,kw0-3) 8-15->tile1(rows8-15)
    // 16-23->tile2(rows0-7,kw4-7) 24-31->tile3(rows8-15,kw4-7)
    const int arowoff = ((lid >> 3) & 1) * 8 + (lid & 7);
    const int ags = lid >> 4;                 // +0 or +1 granule
    const int bn_lane = lid >> 2, bk4 = (lid & 3) * 4;

    for (int c = 0; c < nch; c++) {
        if (c + 1 < nch) { asm volatile("cp.async.wait_group 1;" ::: "memory"); }
        else             { asm volatile("cp.async.wait_group 0;" ::: "memory"); }
        __syncthreads();

        uint32_t stb = sb + (c & 1) * TSTAGE;
        #pragma unroll
        for (int s = 0; s < 8; s++) {         // 8 k8-steps per chunk
            uint32_t af[2][4];
            #pragma unroll
            for (int mi = 0; mi < 2; mi++) {
                int r = wm + mi * 16 + arowoff;
                uint32_t addr = stb + r * TROWB + (((2 * s + ags) ^ (r & 7)) << 4);
                ldsm4(af[mi], addr);
            }
            uint32_t bf0[4], bf1[4];
            #pragma unroll
            for (int nt = 0; nt < 4; nt++) {
                int n = wn + nt * 8 + bn_lane;
                uint32_t nb = stb + TPLANE + n * TROWB + bk4;
                bf0[nt] = lds_b32(nb + (((2 * s)     ^ (n & 7)) << 4));
                bf1[nt] = lds_b32(nb + (((2 * s + 1) ^ (n & 7)) << 4));
            }
            #pragma unroll
            for (int mi = 0; mi < 2; mi++)
                #pragma unroll
                for (int nt = 0; nt < 4; nt++)
                    mma_tf32(creg[mi][nt], af[mi], bf0[nt], bf1[nt]);
        }
        __syncthreads();
        if (c + 2 < nch) load_stage(c + 2, c & 1);
    }

    // ---- epilogue ----
    int gid = lid >> 2, tin = lid & 3;
    #pragma unroll
    for (int mi = 0; mi < 2; mi++) {
        long row0 = bm + wm + mi * 16 + gid;
        long row1 = row0 + 8;
        #pragma unroll
        for (int ni = 0; ni < 4; ni++) {
            long col = bn + wn + ni * 8 + tin * 2;
            float b0 = bias[col], b1 = bias[col + 1];
            float v0 = creg[mi][ni][0] + b0;
            float v1 = creg[mi][ni][1] + b1;
            float v2 = creg[mi][ni][2] + b0;
            float v3 = creg[mi][ni][3] + b1;
            size_t o0 = (size_t)row0 * N + col;
            size_t o1 = (size_t)row1 * N + col;
            if (EPI == 1) {
                uint32_t hp, lp;
                split_pack(v0, v1, hp, lp);
                *(uint32_t*)&CH[o0] = hp; *(uint32_t*)&CL[o0] = lp;
                split_pack(v2, v3, hp, lp);
                *(uint32_t*)&CH[o1] = hp; *(uint32_t*)&CL[o1] = lp;
            } else if (EPI == 2) {
                *(float2*)&C[o0] = make_float2(tf32r(gelu_f(v0)), tf32r(gelu_f(v1)));
                *(float2*)&C[o1] = make_float2(tf32r(gelu_f(v2)), tf32r(gelu_f(v3)));
            } else {
                float2 c0 = *(float2*)&C[o0];
                float2 c1 = *(float2*)&C[o1];
                *(float2*)&C[o0] = make_float2(v0 + c0.x, v1 + c0.y);
                *(float2*)&C[o1] = make_float2(v2 + c1.x, v3 + c1.y);
            }
        }
    }
}

// ---------------- HMMA bf16x3 GEMM (lm_head only) ------------------------------
#define KC 64
#define PLANE_B 16384
#define STAGE_B (4 * PLANE_B)
#define GSMEM_NEED (2 * STAGE_B + 128)

__global__ void __launch_bounds__(512, 1)
gemm_lmhead(const __nv_bfloat16* __restrict__ Ah, const __nv_bfloat16* __restrict__ Al,
            const __nv_bfloat16* __restrict__ Bh, const __nv_bfloat16* __restrict__ Bl,
            float* __restrict__ C, int N, int K) {
    extern __shared__ char dsm[];
    uint32_t sb = (smem_u32(dsm) + 127) & ~127u;

    const int tid = threadIdx.x;
    const int wid = tid >> 5, lid = tid & 31;
    const long bm = (long)blockIdx.x * 128;
    const long bn = (long)blockIdx.y * 128;
    const int wm = (wid >> 2) * 32;
    const int wn = (wid & 3) * 32;
    const int lrow = lid & 15, lg = lid >> 4;

    const int nch = K / KC;

    auto load_stage = [&](int c, int st) {
        uint32_t stb = sb + st * STAGE_B;
        int kc0 = c * KC;
        #pragma unroll
        for (int i = 0; i < 2; i++) {
            int u = tid + 512 * i;
            int row = u >> 3, g = u & 7;
            uint32_t so = stb + row * 128 + ((g ^ (row & 7)) << 4);
            long ka = (bm + row) * (long)K + kc0 + g * 8;
            long kb = (bn + row) * (long)K + kc0 + g * 8;
            CP_ASYNC16(so,               Ah + ka);
            CP_ASYNC16(so + PLANE_B,     Al + ka);
            CP_ASYNC16(so + 2 * PLANE_B, Bh + kb);
            CP_ASYNC16(so + 3 * PLANE_B, Bl + kb);
        }
        CP_COMMIT();
    };

    float creg[2][4][4];
    #pragma unroll
    for (int a = 0; a < 2; a++)
        #pragma unroll
        for (int b = 0; b < 4; b++)
            #pragma unroll
            for (int k = 0; k < 4; k++) creg[a][b][k] = 0.f;

    load_stage(0, 0);
    load_stage(1, 1);

    for (int c = 0; c < nch; c++) {
        if (c + 1 < nch) { asm volatile("cp.async.wait_group 1;" ::: "memory"); }
        else             { asm volatile("cp.async.wait_group 0;" ::: "memory"); }
        __syncthreads();

        uint32_t stb = sb + (c & 1) * STAGE_B;
        #pragma unroll
        for (int ks = 0; ks < 4; ks++) {
            int g = 2 * ks + lg;
            uint32_t aH[2][4], aL[2][4], bH[2][4], bL[2][4];
            #pragma unroll
            for (int mi = 0; mi < 2; mi++) {
                int row = wm + mi * 16 + lrow;
                uint32_t off = row * 128 + ((g ^ (row & 7)) << 4);
                ldsm4(aH[mi], stb + off);
                ldsm4(aL[mi], stb + PLANE_B + off);
            }
            #pragma unroll
            for (int ng = 0; ng < 2; ng++) {
                int row = wn + ng * 16 + lrow;
                uint32_t off = row * 128 + ((g ^ (row & 7)) << 4);
                ldsm4(bH[ng], stb + 2 * PLANE_B + off);
                ldsm4(bL[ng], stb + 3 * PLANE_B + off);
            }
            #pragma unroll
            for (int mi = 0; mi < 2; mi++)
                #pragma unroll
                for (int ni = 0; ni < 4; ni++) {
                    int ng = ni >> 1, h = ni & 1;
                    mma_bf16(creg[mi][ni], aH[mi], bH[ng][h], bH[ng][h + 2]);
                }
            #pragma unroll
            for (int mi = 0; mi < 2; mi++)
                #pragma unroll
                for (int ni = 0; ni < 4; ni++) {
                    int ng = ni >> 1, h = ni & 1;
                    mma_bf16(creg[mi][ni], aH[mi], bL[ng][h], bL[ng][h + 2]);
                }
            #pragma unroll
            for (int mi = 0; mi < 2; mi++)
                #pragma unroll
                for (int ni = 0; ni < 4; ni++) {
                    int ng = ni >> 1, h = ni & 1;
                    mma_bf16(creg[mi][ni], aL[mi], bH[ng][h], bH[ng][h + 2]);
                }
        }
        __syncthreads();
        if (c + 2 < nch) load_stage(c + 2, c & 1);
    }

    int gid = lid >> 2, tin = lid & 3;
    #pragma unroll
    for (int mi = 0; mi < 2; mi++) {
        long row0 = bm + wm + mi * 16 + gid;
        long row1 = row0 + 8;
        #pragma unroll
        for (int ni = 0; ni < 4; ni++) {
            long col = bn + wn + ni * 8 + tin * 2;
            if (col < N)     { C[row0 * N + col]     = creg[mi][ni][0]; C[row1 * N + col]     = creg[mi][ni][2]; }
            if (col + 1 < N) { C[row0 * N + col + 1] = creg[mi][ni][1]; C[row1 * N + col + 1] = creg[mi][ni][3]; }
        }
    }
}

// ---------------- HMMA flash attention ----------------------------------------
// grid (SEQ/64, NHEAD, B), 128 threads. Reversed x order: longest KV first.
#define ATT_SMEM (16384 + 2 * 32768 + 128)

__global__ void __launch_bounds__(128, 2)
attn_tc(const __nv_bfloat16* __restrict__ QKVh, const __nv_bfloat16* __restrict__ QKVl,
        float* __restrict__ Y) {
    extern __shared__ char dsm[];
    uint32_t sb = (smem_u32(dsm) + 127) & ~127u;

    const int tid = threadIdx.x;
    const int wid = tid >> 5, lid = tid & 31;
    const int qtile = gridDim.x - 1 - blockIdx.x;   // heavy blocks first
    const int q0 = qtile * 64, h = blockIdx.y, b = blockIdx.z;
    const int wq = wid * 16;
    const int ntile = qtile + 1;
    const size_t rstride = 3 * DMODEL;

    auto ldplane = [&](uint32_t dst, const __nv_bfloat16* src) {
        #pragma unroll
        for (int i = 0; i < 4; i++) {
            int u = tid + 128 * i;
            int row = u >> 3, ch = u & 7;
            CP_ASYNC16(dst + row * 128 + ((ch ^ (row & 7)) << 4),
                       src + (size_t)row * rstride + ch * 8);
        }
    };
    auto ldstage = [&](int t) {
        uint32_t s = sb + 16384 + (t & 1) * 32768;
        size_t off = (size_t)(b * SEQ + t * 64) * rstride + h * HDIM;
        ldplane(s,         QKVh + off + DMODEL);
        ldplane(s + 8192,  QKVl + off + DMODEL);
        ldplane(s + 16384, QKVh + off + 2 * DMODEL);
        ldplane(s + 24576, QKVl + off + 2 * DMODEL);
        CP_COMMIT();
    };

    {
        size_t qoff = (size_t)(b * SEQ + q0) * rstride + h * HDIM;
        ldplane(sb,        QKVh + qoff);
        ldplane(sb + 8192, QKVl + qoff);
    }
    ldstage(0);

    float o[8][4];
    #pragma unroll
    for (int nb = 0; nb < 8; nb++)
        #pragma unroll
        for (int j = 0; j < 4; j++) o[nb][j] = 0.f;
    float mrun[2] = {-1e30f, -1e30f}, lrun[2] = {0.f, 0.f};

    for (int t = 0; t < ntile; t++) {
        asm volatile("cp.async.wait_group 0;" ::: "memory");
        __syncthreads();
        if (t + 1 < ntile) ldstage(t + 1);
        uint32_t kb = sb + 16384 + (t & 1) * 32768;

        float s[8][4];
        #pragma unroll
        for (int nb = 0; nb < 8; nb++)
            #pragma unroll
            for (int j = 0; j < 4; j++) s[nb][j] = 0.f;

        #pragma unroll
        for (int ks = 0; ks < 4; ks++) {
            uint32_t qh[4], ql[4];
            {
                int r = wq + (lid & 15);
                uint32_t off = r * 128 + (((2 * ks + (lid >> 4)) ^ (r & 7)) << 4);
                ldsm4(qh, sb + off);
                ldsm4(ql, sb + 8192 + off);
            }
            #pragma unroll
            for (int ng = 0; ng < 4; ng++) {
                int r = ng * 16 + (lid & 15);
                uint32_t off = r * 128 + (((2 * ks + (lid >> 4)) ^ (r & 7)) << 4);
                uint32_t kh[4], kl[4];
                ldsm4(kh, kb + off);
                ldsm4(kl, kb + 8192 + off);
                mma_bf16(s[2 * ng],     qh, kh[0], kh[2]);
                mma_bf16(s[2 * ng],     qh, kl[0], kl[2]);
                mma_bf16(s[2 * ng],     ql, kh[0], kh[2]);
                mma_bf16(s[2 * ng + 1], qh, kh[1], kh[3]);
                mma_bf16(s[2 * ng + 1], qh, kl[1], kl[3]);
                mma_bf16(s[2 * ng + 1], ql, kh[1], kh[3]);
            }
        }

        #pragma unroll
        for (int nb = 0; nb < 8; nb++)
            #pragma unroll
            for (int j = 0; j < 4; j++) s[nb][j] *= 0.125f;

        if (t == ntile - 1) {
            int r0g = q0 + wq + (lid >> 2);
            #pragma unroll
            for (int nb = 0; nb < 8; nb++) {
                int colg = t * 64 + nb * 8 + (lid & 3) * 2;
                if (colg     > r0g)     s[nb][0] = -1e30f;
                if (colg + 1 > r0g)     s[nb][1] = -1e30f;
                if (colg     > r0g + 8) s[nb][2] = -1e30f;
                if (colg + 1 > r0g + 8) s[nb][3] = -1e30f;
            }
        }

        #pragma unroll
        for (int half = 0; half < 2; half++) {
            float mx = -1e30f;
            #pragma unroll
            for (int nb = 0; nb < 8; nb++)
                mx = fmaxf(mx, fmaxf(s[nb][2 * half], s[nb][2 * half + 1]));
            mx = fmaxf(mx, __shfl_xor_sync(~0u, mx, 1));
            mx = fmaxf(mx, __shfl_xor_sync(~0u, mx, 2));
            float mn = fmaxf(mrun[half], mx);
            float al = __expf(mrun[half] - mn);
            mrun[half] = mn;
            float sum = 0.f;
            #pragma unroll
            for (int nb = 0; nb < 8; nb++) {
                float p0 = __expf(s[nb][2 * half]     - mn);
                float p1 = __expf(s[nb][2 * half + 1] - mn);
                s[nb][2 * half] = p0; s[nb][2 * half + 1] = p1;
                sum += p0 + p1;
            }
            lrun[half] = lrun[half] * al + sum;
            #pragma unroll
            for (int nb = 0; nb < 8; nb++) {
                o[nb][2 * half] *= al; o[nb][2 * half + 1] *= al;
            }
        }

        #pragma unroll
        for (int kk = 0; kk < 4; kk++) {
            uint32_t ph[4], pl[4];
            split_pack(s[2 * kk][0],     s[2 * kk][1],     ph[0], pl[0]);
            split_pack(s[2 * kk][2],     s[2 * kk][3],     ph[1], pl[1]);
            split_pack(s[2 * kk + 1][0], s[2 * kk + 1][1], ph[2], pl[2]);
            split_pack(s[2 * kk + 1][2], s[2 * kk + 1][3], ph[3], pl[3]);
            #pragma unroll
            for (int cc = 0; cc < 4; cc++) {
                int r = kk * 16 + (lid & 15);
                uint32_t off = r * 128 + (((2 * cc + (lid >> 4)) ^ (r & 7)) << 4);
                uint32_t vh[4], vl[4];
                ldsm4t(vh, kb + 16384 + off);
                ldsm4t(vl, kb + 24576 + off);
                mma_bf16(o[2 * cc],     ph, vh[0], vh[1]);
                mma_bf16(o[2 * cc],     pl, vh[0], vh[1]);
                mma_bf16(o[2 * cc],     ph, vl[0], vl[1]);
                mma_bf16(o[2 * cc + 1], ph, vh[2], vh[3]);
                mma_bf16(o[2 * cc + 1], pl, vh[2], vh[3]);
                mma_bf16(o[2 * cc + 1], ph, vl[2], vl[3]);
            }
        }
    }

    float inv[2];
    #pragma unroll
    for (int half = 0; half < 2; half++) {
        float l = lrun[half];
        l += __shfl_xor_sync(~0u, l, 1);
        l += __shfl_xor_sync(~0u, l, 2);
        inv[half] = 1.0f / l;
    }
    int r0 = q0 + wq + (lid >> 2);
    #pragma unroll
    for (int nb = 0; nb < 8; nb++) {
        int col = h * HDIM + nb * 8 + (lid & 3) * 2;
        size_t o0 = (size_t)(b * SEQ + r0) * DMODEL + col;
        size_t o1 = (size_t)(b * SEQ + r0 + 8) * DMODEL + col;
        *(float2*)&Y[o0] = make_float2(tf32r(o[nb][0] * inv[0]), tf32r(o[nb][1] * inv[0]));
        *(float2*)&Y[o1] = make_float2(tf32r(o[nb][2] * inv[1]), tf32r(o[nb][3] * inv[1]));
    }
}

// ---------------- weight conversions ------------------------------------------
__global__ void cvt_wte_k(const float* __restrict__ wte) {
    size_t i = (size_t)blockIdx.x * 256 + threadIdx.x;
    if (i >= (size_t)VPAD * DMODEL) return;
    float v = (i < (size_t)VOCAB * DMODEL) ? wte[i] : 0.0f;
    __nv_bfloat16 hb = __float2bfloat16(v);
    g_wteH[i] = hb;
    g_wteL[i] = __float2bfloat16(v - __bfloat162float(hb));
}

// w [L,K,N] f32 -> out [L,N,K] tf32-rounded f32. grid (N/32, K/32, L), block (32,8)
__global__ void cvt_wTf(const float* __restrict__ w, float* __restrict__ tf,
                        int K, int N) {
    __shared__ float t[32][33];
    const float* wsrc = w + (size_t)blockIdx.z * K * N;
    float* tfd = tf + (size_t)blockIdx.z * N * K;
    int n0 = blockIdx.x * 32, k0 = blockIdx.y * 32;
    int tx = threadIdx.x, ty = threadIdx.y;
    #pragma unroll
    for (int i = 0; i < 4; i++)
        t[ty + 8 * i][tx] = wsrc[(size_t)(k0 + ty + 8 * i) * N + n0 + tx];
    __syncthreads();
    #pragma unroll
    for (int i = 0; i < 4; i++) {
        size_t o = (size_t)(n0 + ty + 8 * i) * K + k0 + tx;
        tfd[o] = tf32r(t[tx][ty + 8 * i]);
    }
}

// ---------------- embedding --------------------------------------------------
__global__ void embed_kernel(const int* __restrict__ idx,
                             const float* __restrict__ wte,
                             const float* __restrict__ wpe) {
    int row = blockIdx.x;
    int t = row & (SEQ - 1);
    int tok = idx[row];
    const float* we = wte + (size_t)tok * DMODEL;
    const float* wp = wpe + (size_t)t * DMODEL;
    float* xr = g_x + (size_t)row * DMODEL;
    for (int d = threadIdx.x; d < DMODEL; d += blockDim.x)
        xr[d] = we[d] + wp[d];
}

// ---------------- layernorm: MODE 0 -> tf32 f32 plane, MODE 1 -> bf16 hi/lo ---
template <int MODE>
__global__ void __launch_bounds__(256) ln_kernel(const float* __restrict__ x,
                                                 const float* __restrict__ sc,
                                                 const float* __restrict__ bi,
                                                 float* __restrict__ outF,
                                                 __nv_bfloat16* __restrict__ outH,
                                                 __nv_bfloat16* __restrict__ outL) {
    __shared__ float red[8];
    int row = blockIdx.x, tid = threadIdx.x;
    const float* xr = x + (size_t)row * DMODEL;
    float v0 = xr[tid], v1 = xr[tid + 256], v2 = xr[tid + 512];

    float s = v0 + v1 + v2;
    #pragma unroll
    for (int o = 16; o > 0; o >>= 1) s += __shfl_xor_sync(~0u, s, o);
    if ((tid & 31) == 0) red[tid >> 5] = s;
    __syncthreads();
    if (tid < 32) {
        float t = (tid < 8) ? red[tid] : 0.f;
        #pragma unroll
        for (int o = 4; o > 0; o >>= 1) t += __shfl_xor_sync(~0u, t, o);
        if (tid == 0) red[0] = t;
    }
    __syncthreads();
    float mu = red[0] * (1.0f / DMODEL);
    __syncthreads();

    float d0 = v0 - mu, d1 = v1 - mu, d2 = v2 - mu;
    float s2 = d0 * d0 + d1 * d1 + d2 * d2;
    #pragma unroll
    for (int o = 16; o > 0; o >>= 1) s2 += __shfl_xor_sync(~0u, s2, o);
    if ((tid & 31) == 0) red[tid >> 5] = s2;
    __syncthreads();
    if (tid < 32) {
        float t = (tid < 8) ? red[tid] : 0.f;
        #pragma unroll
        for (int o = 4; o > 0; o >>= 1) t += __shfl_xor_sync(~0u, t, o);
        if (tid == 0) red[0] = t;
    }
    __syncthreads();
    float var = red[0] * (1.0f / DMODEL);
    float rs = rsqrtf(var + 1e-5f);

    size_t base = (size_t)row * DMODEL;
    #pragma unroll
    for (int e = 0; e < 3; e++) {
        float d = (e == 0) ? d0 : (e == 1) ? d1 : d2;
        int c = tid + 256 * e;
        float v = d * rs * sc[c] + bi[c];
        if (MODE == 0) {
            outF[base + c] = tf32r(v);
        } else {
            __nv_bfloat16 hb = __float2bfloat16(v);
            outH[base + c] = hb;
            outL[base + c] = __float2bfloat16(v - __bfloat162float(hb));
        }
    }
}

// ---------------- loss --------------------------------------------------------
__global__ void __launch_bounds__(256) lossrow_kernel(const float* __restrict__ logits,
                                                      const int* __restrict__ targets) {
    int row = blockIdx.x;
    const float* lr_ = logits + (size_t)row * VOCAB;
    float m = -1e30f, s = 0.f;
    for (int jv = threadIdx.x; jv < VOCAB; jv += 256) {
        float v = lr_[jv];
        if (v <= m) {
            s += __expf(v - m);
        } else {
            s = s * __expf(m - v) + 1.0f;
            m = v;
        }
    }
    __shared__ float sm[256], ss[256];
    sm[threadIdx.x] = m; ss[threadIdx.x] = s;
    __syncthreads();
    for (int st = 128; st > 0; st >>= 1) {
        if (threadIdx.x < st) {
            float ma = sm[threadIdx.x], sa = ss[threadIdx.x];
            float mb = sm[threadIdx.x + st], sb = ss[threadIdx.x + st];
            float M = fmaxf(ma, mb);
            ss[threadIdx.x] = sa * __expf(ma - M) + sb * __expf(mb - M);
            sm[threadIdx.x] = M;
        }
        __syncthreads();
    }
    if (threadIdx.x == 0) {
        float lse = sm[0] + logf(ss[0]);
        g_rowloss[row] = lse - lr_[targets[row]];
    }
}

__global__ void __launch_bounds__(256) lossreduce_kernel(float* __restrict__ out_loss) {
    __shared__ float red[8];
    float s = 0.f;
    for (int i = threadIdx.x; i < NTOK; i += 256) s += g_rowloss[i];
    #pragma unroll
    for (int o = 16; o > 0; o >>= 1) s += __shfl_xor_sync(~0u, s, o);
    if ((threadIdx.x & 31) == 0) red[threadIdx.x >> 5] = s;
    __syncthreads();
    if (threadIdx.x == 0) {
        float t = 0.f;
        for (int w = 0; w < 8; w++) t += red[w];
        out_loss[0] = t * (1.0f / NTOK);
    }
}

// ---------------- host orchestration -----------------------------------------
extern "C" void kernel_launch(void* const* d_in, const int* in_sizes, int n_in,
                              void* d_out, int out_size) {
    const int*   idx     = (const int*)  d_in[0];
    const int*   targets = (const int*)  d_in[1];
    const float* wte     = (const float*)d_in[2];
    const float* wpe     = (const float*)d_in[3];
    const float* ln1_s   = (const float*)d_in[4];
    const float* ln1_b   = (const float*)d_in[5];
    const float* attn_w  = (const float*)d_in[6];
    const float* attn_b  = (const float*)d_in[7];
    const float* proj_w  = (const float*)d_in[8];
    const float* proj_b  = (const float*)d_in[9];
    const float* ln2_s   = (const float*)d_in[10];
    const float* ln2_b   = (const float*)d_in[11];
    const float* fc_w    = (const float*)d_in[12];
    const float* fc_b    = (const float*)d_in[13];
    const float* proj2_w = (const float*)d_in[14];
    const float* proj2_b = (const float*)d_in[15];
    const float* lnf_s   = (const float*)d_in[16];
    const float* lnf_b   = (const float*)d_in[17];
    float* out = (float*)d_out;

    float *px, *phf, *pyf, *pmf, *pwTf;
    __nv_bfloat16 *phH, *phL, *pqH, *pqL, *pwteH, *pwteL;
    cudaGetSymbolAddress((void**)&px, g_x);
    cudaGetSymbolAddress((void**)&phf, g_hf);
    cudaGetSymbolAddress((void**)&pyf, g_yf);
    cudaGetSymbolAddress((void**)&pmf, g_mf);
    cudaGetSymbolAddress((void**)&pwTf, g_wTf);
    cudaGetSymbolAddress((void**)&phH, g_hH);
    cudaGetSymbolAddress((void**)&phL, g_hL);
    cudaGetSymbolAddress((void**)&pqH, g_qkvH);
    cudaGetSymbolAddress((void**)&pqL, g_qkvL);
    cudaGetSymbolAddress((void**)&pwteH, g_wteH);
    cudaGetSymbolAddress((void**)&pwteL, g_wteL);

    cudaFuncSetAttribute(gemm_tf32<1>, cudaFuncAttributeMaxDynamicSharedMemorySize, TSMEM_NEED);
    cudaFuncSetAttribute(gemm_tf32<2>, cudaFuncAttributeMaxDynamicSharedMemorySize, TSMEM_NEED);
    cudaFuncSetAttribute(gemm_tf32<3>, cudaFuncAttributeMaxDynamicSharedMemorySize, TSMEM_NEED);
    cudaFuncSetAttribute(gemm_lmhead,  cudaFuncAttributeMaxDynamicSharedMemorySize, GSMEM_NEED);
    cudaFuncSetAttribute(attn_tc, cudaFuncAttributeMaxDynamicSharedMemorySize, ATT_SMEM);

    embed_kernel<<<NTOK, 256>>>(idx, wte, wpe);

    // --- all weight conversions up-front (batched over layers) ---
    cvt_wTf<<<dim3(3 * DMODEL / 32, DMODEL / 32, NLAYER), dim3(32, 8)>>>(
        attn_w, pwTf + OFF_ATTN, DMODEL, 3 * DMODEL);
    cvt_wTf<<<dim3(DMODEL / 32, DMODEL / 32, NLAYER), dim3(32, 8)>>>(
        proj_w, pwTf + OFF_PROJ, DMODEL, DMODEL);
    cvt_wTf<<<dim3(4 * DMODEL / 32, DMODEL / 32, NLAYER), dim3(32, 8)>>>(
        fc_w, pwTf + OFF_FC, DMODEL, 4 * DMODEL);
    cvt_wTf<<<dim3(DMODEL / 32, 4 * DMODEL / 32, NLAYER), dim3(32, 8)>>>(
        proj2_w, pwTf + OFF_PROJ2, 4 * DMODEL, DMODEL);
    {
        size_t nw = (size_t)VPAD * DMODEL;
        cvt_wte_k<<<(unsigned)((nw + 255) / 256), 256>>>(wte);
    }

    for (int l = 0; l < NLAYER; l++) {
        const float* ab  = attn_b  + (size_t)l * 3 * DMODEL;
        const float* pb  = proj_b  + (size_t)l * DMODEL;
        const float* fb  = fc_b    + (size_t)l * 4 * DMODEL;
        const float* p2b = proj2_b + (size_t)l * DMODEL;
        size_t oAttn  = OFF_ATTN  + (size_t)l * SZ_ATTN;
        size_t oProj  = OFF_PROJ  + (size_t)l * SZ_PROJ;
        size_t oFc    = OFF_FC    + (size_t)l * SZ_FC;
        size_t oProj2 = OFF_PROJ2 + (size_t)l * SZ_PROJ2;

        // --- attention block ---
        ln_kernel<0><<<NTOK, 256>>>(px, ln1_s + l * DMODEL, ln1_b + l * DMODEL,
                                    phf, nullptr, nullptr);
        gemm_tf32<1><<<dim3(NTOK / 128, 3 * DMODEL / 128), 512, TSMEM_NEED>>>(
            phf, pwTf + oAttn, ab, nullptr, pqH, pqL, 3 * DMODEL, DMODEL);
        attn_tc<<<dim3(SEQ / 64, NHEAD, 2), 128, ATT_SMEM>>>(pqH, pqL, pyf);
        gemm_tf32<3><<<dim3(NTOK / 128, DMODEL / 128), 512, TSMEM_NEED>>>(
            pyf, pwTf + oProj, pb, px, nullptr, nullptr, DMODEL, DMODEL);

        // --- MLP block ---
        ln_kernel<0><<<NTOK, 256>>>(px, ln2_s + l * DMODEL, ln2_b + l * DMODEL,
                                    phf, nullptr, nullptr);
        gemm_tf32<2><<<dim3(NTOK / 128, 4 * DMODEL / 128), 512, TSMEM_NEED>>>(
            phf, pwTf + oFc, fb, pmf, nullptr, nullptr, 4 * DMODEL, DMODEL);
        gemm_tf32<3><<<dim3(NTOK / 128, DMODEL / 128), 512, TSMEM_NEED>>>(
            pmf, pwTf + oProj2, p2b, px, nullptr, nullptr, DMODEL, 4 * DMODEL);
    }

    // --- final LN + tied lm_head (bf16x3) + loss ---
    ln_kernel<1><<<NTOK, 256>>>(px, lnf_s, lnf_b, nullptr, phH, phL);
    gemm_lmhead<<<dim3(NTOK / 128, VPAD / 128), 512, GSMEM_NEED>>>(
        phH, phL, pwteH, pwteL, out, VOCAB, DMODEL);

    lossrow_kernel<<<NTOK, 256>>>(out, targets);
    lossreduce_kernel<<<1, 256>>>(out + (size_t)NTOK * VOCAB);
}

// round 9
// speedup vs baseline: 2.1487x; 1.5531x over previous
#include <cuda_runtime.h>
#include <cuda_bf16.h>
#include <cuda_fp16.h>
#include <math.h>
#include <stdint.h>

// Problem constants
#define NTOK 2048          // B*T
#define SEQ  1024
#define DMODEL 768
#define NHEAD 12
#define HDIM 64
#define NLAYER 8
#define VOCAB 50257
#define VPAD  50304        // 393*128

// per-layer transposed-weight plane offsets (elements)
#define OFF_ATTN  0
#define SZ_ATTN   (3 * DMODEL * DMODEL)
#define OFF_PROJ  (NLAYER * SZ_ATTN)
#define SZ_PROJ   (DMODEL * DMODEL)
#define OFF_FC    (OFF_PROJ + NLAYER * SZ_PROJ)
#define SZ_FC     (4 * DMODEL * DMODEL)
#define OFF_PROJ2 (OFF_FC + NLAYER * SZ_FC)
#define SZ_PROJ2  (4 * DMODEL * DMODEL)
#define WT_TOTAL  (OFF_PROJ2 + NLAYER * SZ_PROJ2)

// ---------------- scratch (device globals; no allocation allowed) ------------
__device__ float g_x[NTOK * DMODEL];
__device__ float g_rowloss[NTOK];
__device__ __half g_h16[NTOK * DMODEL];        // LN out (fp16)
__device__ __half g_y16[NTOK * DMODEL];        // attn out (fp16)
__device__ __half g_m16[NTOK * 4 * DMODEL];    // mlp hidden (fp16)
__device__ __half g_wT16[WT_TOTAL];            // transposed weights (fp16)
__device__ __half g_wte16[(size_t)VPAD * DMODEL];
__device__ __nv_bfloat16 g_qkvH[NTOK * 3 * DMODEL];  // qkv hi/lo (attention, bf16x3)
__device__ __nv_bfloat16 g_qkvL[NTOK * 3 * DMODEL];

// ---------------- helpers -----------------------------------------------------
__device__ __forceinline__ uint32_t smem_u32(const void* p) {
    uint32_t a;
    asm("{ .reg .u64 t; cvta.to.shared.u64 t, %1; cvt.u32.u64 %0, t; }" : "=r"(a) : "l"(p));
    return a;
}

#define CP_ASYNC16(s, g) \
    asm volatile("cp.async.cg.shared.global [%0], [%1], 16;" :: "r"(s), "l"(g) : "memory")
#define CP_COMMIT() asm volatile("cp.async.commit_group;" ::: "memory")

__device__ __forceinline__ void ldsm4(uint32_t r[4], uint32_t addr) {
    asm volatile("ldmatrix.sync.aligned.m8n8.x4.shared.b16 {%0,%1,%2,%3}, [%4];"
        : "=r"(r[0]), "=r"(r[1]), "=r"(r[2]), "=r"(r[3]) : "r"(addr));
}
__device__ __forceinline__ void ldsm4t(uint32_t r[4], uint32_t addr) {
    asm volatile("ldmatrix.sync.aligned.m8n8.x4.trans.shared.b16 {%0,%1,%2,%3}, [%4];"
        : "=r"(r[0]), "=r"(r[1]), "=r"(r[2]), "=r"(r[3]) : "r"(addr));
}
__device__ __forceinline__ void mma_bf16(float c[4], const uint32_t a[4],
                                         uint32_t b0, uint32_t b1) {
    asm volatile("mma.sync.aligned.m16n8k16.row.col.f32.bf16.bf16.f32 "
        "{%0,%1,%2,%3}, {%4,%5,%6,%7}, {%8,%9}, {%0,%1,%2,%3};"
        : "+f"(c[0]), "+f"(c[1]), "+f"(c[2]), "+f"(c[3])
        : "r"(a[0]), "r"(a[1]), "r"(a[2]), "r"(a[3]), "r"(b0), "r"(b1));
}
__device__ __forceinline__ void mma_f16(float c[4], const uint32_t a[4],
                                        uint32_t b0, uint32_t b1) {
    asm volatile("mma.sync.aligned.m16n8k16.row.col.f32.f16.f16.f32 "
        "{%0,%1,%2,%3}, {%4,%5,%6,%7}, {%8,%9}, {%0,%1,%2,%3};"
        : "+f"(c[0]), "+f"(c[1]), "+f"(c[2]), "+f"(c[3])
        : "r"(a[0]), "r"(a[1]), "r"(a[2]), "r"(a[3]), "r"(b0), "r"(b1));
}

__device__ __forceinline__ float gelu_f(float x) {
    const float c = 0.7978845608028654f;
    float x3 = x * x * x;
    return 0.5f * x * (1.0f + tanhf(c * (x + 0.044715f * x3)));
}

__device__ __forceinline__ void split_pack(float a, float b, uint32_t& hp, uint32_t& lp) {
    __nv_bfloat16 ha = __float2bfloat16(a), hb = __float2bfloat16(b);
    __nv_bfloat16 la = __float2bfloat16(a - __bfloat162float(ha));
    __nv_bfloat16 lb = __float2bfloat16(b - __bfloat162float(hb));
    hp = ((uint32_t)__bfloat16_as_ushort(hb) << 16) | __bfloat16_as_ushort(ha);
    lp = ((uint32_t)__bfloat16_as_ushort(lb) << 16) | __bfloat16_as_ushort(la);
}

// ---------------- fp16 single-plane GEMM --------------------------------------
// C[M,N] = A[M,K]*B^T, A fp16 [M,K], B fp16 [N,K]. CTA tile 128x128, 512 threads
// (16 warps, warp tile 32x32), KC=64, 3-stage cp.async pipeline, 128B swizzled.
// EPI: 0 = plain f32 out, N-predicated (lm_head)
//      1 = +bias -> bf16 hi/lo planes (qkv)
//      2 = gelu(+bias) -> fp16 plane (fc)
//      3 = +bias, residual C += (proj / proj2)
#define KC 64
#define FPLANE 16384                // 128 rows * 128 bytes
#define FSTAGE (2 * FPLANE)         // A + B = 32KB
#define NSTG 3
#define FSMEM_NEED (NSTG * FSTAGE + 128)

template <int EPI>
__global__ void __launch_bounds__(512, 1)
gemm_f16(const __half* __restrict__ A, const __half* __restrict__ B,
         const float* __restrict__ bias, float* __restrict__ C,
         __half* __restrict__ CF,
         __nv_bfloat16* __restrict__ CH, __nv_bfloat16* __restrict__ CL,
         int N, int K) {
    extern __shared__ char dsm[];
    uint32_t sb = (smem_u32(dsm) + 127) & ~127u;

    const int tid = threadIdx.x;
    const int wid = tid >> 5, lid = tid & 31;
    const long bm = (long)blockIdx.x * 128;
    const long bn = (long)blockIdx.y * 128;
    const int wm = (wid >> 2) * 32;
    const int wn = (wid & 3) * 32;
    const int lrow = lid & 15, lg = lid >> 4;

    const int nch = K / KC;

    auto load_stage = [&](int c) {
        uint32_t stb = sb + (c % NSTG) * FSTAGE;
        int kc0 = c * KC;
        #pragma unroll
        for (int i = 0; i < 2; i++) {
            int u = tid + 512 * i;            // 0..1023
            int row = u >> 3, g = u & 7;
            uint32_t so = stb + row * 128 + ((g ^ (row & 7)) << 4);
            long ka = (bm + row) * (long)K + kc0 + g * 8;
            long kb = (bn + row) * (long)K + kc0 + g * 8;
            CP_ASYNC16(so,          A + ka);
            CP_ASYNC16(so + FPLANE, B + kb);
        }
        CP_COMMIT();
    };

    float creg[2][4][4];
    #pragma unroll
    for (int a = 0; a < 2; a++)
        #pragma unroll
        for (int b = 0; b < 4; b++)
            #pragma unroll
            for (int k = 0; k < 4; k++) creg[a][b][k] = 0.f;

    load_stage(0);
    load_stage(1);
    load_stage(2);

    for (int c = 0; c < nch; c++) {
        if (c + 3 <= nch)      { asm volatile("cp.async.wait_group 2;" ::: "memory"); }
        else if (c + 2 <= nch) { asm volatile("cp.async.wait_group 1;" ::: "memory"); }
        else                   { asm volatile("cp.async.wait_group 0;" ::: "memory"); }
        __syncthreads();

        uint32_t stb = sb + (c % NSTG) * FSTAGE;
        #pragma unroll
        for (int ks = 0; ks < 4; ks++) {
            int g = 2 * ks + lg;
            uint32_t aF[2][4], bF[2][4];
            #pragma unroll
            for (int mi = 0; mi < 2; mi++) {
                int row = wm + mi * 16 + lrow;
                uint32_t off = row * 128 + ((g ^ (row & 7)) << 4);
                ldsm4(aF[mi], stb + off);
            }
            #pragma unroll
            for (int ng = 0; ng < 2; ng++) {
                int row = wn + ng * 16 + lrow;
                uint32_t off = row * 128 + ((g ^ (row & 7)) << 4);
                ldsm4(bF[ng], stb + FPLANE + off);
            }
            #pragma unroll
            for (int mi = 0; mi < 2; mi++)
                #pragma unroll
                for (int ni = 0; ni < 4; ni++) {
                    int ng = ni >> 1, h = ni & 1;
                    mma_f16(creg[mi][ni], aF[mi], bF[ng][h], bF[ng][h + 2]);
                }
        }
        __syncthreads();
        if (c + 3 < nch) load_stage(c + 3);
    }

    // ---- epilogue ----
    int gid = lid >> 2, tin = lid & 3;
    #pragma unroll
    for (int mi = 0; mi < 2; mi++) {
        long row0 = bm + wm + mi * 16 + gid;
        long row1 = row0 + 8;
        #pragma unroll
        for (int ni = 0; ni < 4; ni++) {
            long col = bn + wn + ni * 8 + tin * 2;
            float b0 = 0.f, b1 = 0.f;
            if (EPI >= 1) { b0 = bias[col]; b1 = bias[col + 1]; }
            float v0 = creg[mi][ni][0] + b0;
            float v1 = creg[mi][ni][1] + b1;
            float v2 = creg[mi][ni][2] + b0;
            float v3 = creg[mi][ni][3] + b1;
            size_t o0 = (size_t)row0 * N + col;
            size_t o1 = (size_t)row1 * N + col;
            if (EPI == 0) {
                if (col < N)     { C[row0 * N + col]     = v0; C[row1 * N + col]     = v2; }
                if (col + 1 < N) { C[row0 * N + col + 1] = v1; C[row1 * N + col + 1] = v3; }
            } else if (EPI == 1) {
                uint32_t hp, lp;
                split_pack(v0, v1, hp, lp);
                *(uint32_t*)&CH[o0] = hp; *(uint32_t*)&CL[o0] = lp;
                split_pack(v2, v3, hp, lp);
                *(uint32_t*)&CH[o1] = hp; *(uint32_t*)&CL[o1] = lp;
            } else if (EPI == 2) {
                *(__half2*)&CF[o0] = __floats2half2_rn(gelu_f(v0), gelu_f(v1));
                *(__half2*)&CF[o1] = __floats2half2_rn(gelu_f(v2), gelu_f(v3));
            } else {
                float2 c0 = *(float2*)&C[o0];
                float2 c1 = *(float2*)&C[o1];
                *(float2*)&C[o0] = make_float2(v0 + c0.x, v1 + c0.y);
                *(float2*)&C[o1] = make_float2(v2 + c1.x, v3 + c1.y);
            }
        }
    }
}

// ---------------- HMMA bf16x3 flash attention ----------------------------------
// grid (SEQ/64, NHEAD, B), 128 threads. Reversed x order: longest KV first.
#define ATT_SMEM (16384 + 2 * 32768 + 128)

__global__ void __launch_bounds__(128, 2)
attn_tc(const __nv_bfloat16* __restrict__ QKVh, const __nv_bfloat16* __restrict__ QKVl,
        __half* __restrict__ Y) {
    extern __shared__ char dsm[];
    uint32_t sb = (smem_u32(dsm) + 127) & ~127u;

    const int tid = threadIdx.x;
    const int wid = tid >> 5, lid = tid & 31;
    const int qtile = gridDim.x - 1 - blockIdx.x;   // heavy blocks first
    const int q0 = qtile * 64, h = blockIdx.y, b = blockIdx.z;
    const int wq = wid * 16;
    const int ntile = qtile + 1;
    const size_t rstride = 3 * DMODEL;

    auto ldplane = [&](uint32_t dst, const __nv_bfloat16* src) {
        #pragma unroll
        for (int i = 0; i < 4; i++) {
            int u = tid + 128 * i;
            int row = u >> 3, ch = u & 7;
            CP_ASYNC16(dst + row * 128 + ((ch ^ (row & 7)) << 4),
                       src + (size_t)row * rstride + ch * 8);
        }
    };
    auto ldstage = [&](int t) {
        uint32_t s = sb + 16384 + (t & 1) * 32768;
        size_t off = (size_t)(b * SEQ + t * 64) * rstride + h * HDIM;
        ldplane(s,         QKVh + off + DMODEL);
        ldplane(s + 8192,  QKVl + off + DMODEL);
        ldplane(s + 16384, QKVh + off + 2 * DMODEL);
        ldplane(s + 24576, QKVl + off + 2 * DMODEL);
        CP_COMMIT();
    };

    {
        size_t qoff = (size_t)(b * SEQ + q0) * rstride + h * HDIM;
        ldplane(sb,        QKVh + qoff);
        ldplane(sb + 8192, QKVl + qoff);
    }
    ldstage(0);

    float o[8][4];
    #pragma unroll
    for (int nb = 0; nb < 8; nb++)
        #pragma unroll
        for (int j = 0; j < 4; j++) o[nb][j] = 0.f;
    float mrun[2] = {-1e30f, -1e30f}, lrun[2] = {0.f, 0.f};

    for (int t = 0; t < ntile; t++) {
        asm volatile("cp.async.wait_group 0;" ::: "memory");
        __syncthreads();
        if (t + 1 < ntile) ldstage(t + 1);
        uint32_t kb = sb + 16384 + (t & 1) * 32768;

        float s[8][4];
        #pragma unroll
        for (int nb = 0; nb < 8; nb++)
            #pragma unroll
            for (int j = 0; j < 4; j++) s[nb][j] = 0.f;

        #pragma unroll
        for (int ks = 0; ks < 4; ks++) {
            uint32_t qh[4], ql[4];
            {
                int r = wq + (lid & 15);
                uint32_t off = r * 128 + (((2 * ks + (lid >> 4)) ^ (r & 7)) << 4);
                ldsm4(qh, sb + off);
                ldsm4(ql, sb + 8192 + off);
            }
            #pragma unroll
            for (int ng = 0; ng < 4; ng++) {
                int r = ng * 16 + (lid & 15);
                uint32_t off = r * 128 + (((2 * ks + (lid >> 4)) ^ (r & 7)) << 4);
                uint32_t kh[4], kl[4];
                ldsm4(kh, kb + off);
                ldsm4(kl, kb + 8192 + off);
                mma_bf16(s[2 * ng],     qh, kh[0], kh[2]);
                mma_bf16(s[2 * ng],     qh, kl[0], kl[2]);
                mma_bf16(s[2 * ng],     ql, kh[0], kh[2]);
                mma_bf16(s[2 * ng + 1], qh, kh[1], kh[3]);
                mma_bf16(s[2 * ng + 1], qh, kl[1], kl[3]);
                mma_bf16(s[2 * ng + 1], ql, kh[1], kh[3]);
            }
        }

        #pragma unroll
        for (int nb = 0; nb < 8; nb++)
            #pragma unroll
            for (int j = 0; j < 4; j++) s[nb][j] *= 0.125f;

        if (t == ntile - 1) {
            int r0g = q0 + wq + (lid >> 2);
            #pragma unroll
            for (int nb = 0; nb < 8; nb++) {
                int colg = t * 64 + nb * 8 + (lid & 3) * 2;
                if (colg     > r0g)     s[nb][0] = -1e30f;
                if (colg + 1 > r0g)     s[nb][1] = -1e30f;
                if (colg     > r0g + 8) s[nb][2] = -1e30f;
                if (colg + 1 > r0g + 8) s[nb][3] = -1e30f;
            }
        }

        #pragma unroll
        for (int half = 0; half < 2; half++) {
            float mx = -1e30f;
            #pragma unroll
            for (int nb = 0; nb < 8; nb++)
                mx = fmaxf(mx, fmaxf(s[nb][2 * half], s[nb][2 * half + 1]));
            mx = fmaxf(mx, __shfl_xor_sync(~0u, mx, 1));
            mx = fmaxf(mx, __shfl_xor_sync(~0u, mx, 2));
            float mn = fmaxf(mrun[half], mx);
            float al = __expf(mrun[half] - mn);
            mrun[half] = mn;
            float sum = 0.f;
            #pragma unroll
            for (int nb = 0; nb < 8; nb++) {
                float p0 = __expf(s[nb][2 * half]     - mn);
                float p1 = __expf(s[nb][2 * half + 1] - mn);
                s[nb][2 * half] = p0; s[nb][2 * half + 1] = p1;
                sum += p0 + p1;
            }
            lrun[half] = lrun[half] * al + sum;
            #pragma unroll
            for (int nb = 0; nb < 8; nb++) {
                o[nb][2 * half] *= al; o[nb][2 * half + 1] *= al;
            }
        }

        #pragma unroll
        for (int kk = 0; kk < 4; kk++) {
            uint32_t ph[4], pl[4];
            split_pack(s[2 * kk][0],     s[2 * kk][1],     ph[0], pl[0]);
            split_pack(s[2 * kk][2],     s[2 * kk][3],     ph[1], pl[1]);
            split_pack(s[2 * kk + 1][0], s[2 * kk + 1][1], ph[2], pl[2]);
            split_pack(s[2 * kk + 1][2], s[2 * kk + 1][3], ph[3], pl[3]);
            #pragma unroll
            for (int cc = 0; cc < 4; cc++) {
                int r = kk * 16 + (lid & 15);
                uint32_t off = r * 128 + (((2 * cc + (lid >> 4)) ^ (r & 7)) << 4);
                uint32_t vh[4], vl[4];
                ldsm4t(vh, kb + 16384 + off);
                ldsm4t(vl, kb + 24576 + off);
                mma_bf16(o[2 * cc],     ph, vh[0], vh[1]);
                mma_bf16(o[2 * cc],     pl, vh[0], vh[1]);
                mma_bf16(o[2 * cc],     ph, vl[0], vl[1]);
                mma_bf16(o[2 * cc + 1], ph, vh[2], vh[3]);
                mma_bf16(o[2 * cc + 1], pl, vh[2], vh[3]);
                mma_bf16(o[2 * cc + 1], ph, vl[2], vl[3]);
            }
        }
    }

    float inv[2];
    #pragma unroll
    for (int half = 0; half < 2; half++) {
        float l = lrun[half];
        l += __shfl_xor_sync(~0u, l, 1);
        l += __shfl_xor_sync(~0u, l, 2);
        inv[half] = 1.0f / l;
    }
    int r0 = q0 + wq + (lid >> 2);
    #pragma unroll
    for (int nb = 0; nb < 8; nb++) {
        int col = h * HDIM + nb * 8 + (lid & 3) * 2;
        size_t o0 = (size_t)(b * SEQ + r0) * DMODEL + col;
        size_t o1 = (size_t)(b * SEQ + r0 + 8) * DMODEL + col;
        *(__half2*)&Y[o0] = __floats2half2_rn(o[nb][0] * inv[0], o[nb][1] * inv[0]);
        *(__half2*)&Y[o1] = __floats2half2_rn(o[nb][2] * inv[1], o[nb][3] * inv[1]);
    }
}

// ---------------- weight conversions ------------------------------------------
__global__ void cvt_wte16(const float* __restrict__ wte) {
    size_t i = (size_t)blockIdx.x * 256 + threadIdx.x;
    if (i >= (size_t)VPAD * DMODEL) return;
    float v = (i < (size_t)VOCAB * DMODEL) ? wte[i] : 0.0f;
    g_wte16[i] = __float2half_rn(v);
}

// w [L,K,N] f32 -> out [L,N,K] fp16. grid (N/32, K/32, L), block (32,8)
__global__ void cvt_wT16(const float* __restrict__ w, __half* __restrict__ tf,
                         int K, int N) {
    __shared__ float t[32][33];
    const float* wsrc = w + (size_t)blockIdx.z * K * N;
    __half* tfd = tf + (size_t)blockIdx.z * N * K;
    int n0 = blockIdx.x * 32, k0 = blockIdx.y * 32;
    int tx = threadIdx.x, ty = threadIdx.y;
    #pragma unroll
    for (int i = 0; i < 4; i++)
        t[ty + 8 * i][tx] = wsrc[(size_t)(k0 + ty + 8 * i) * N + n0 + tx];
    __syncthreads();
    #pragma unroll
    for (int i = 0; i < 4; i++) {
        size_t o = (size_t)(n0 + ty + 8 * i) * K + k0 + tx;
        tfd[o] = __float2half_rn(t[tx][ty + 8 * i]);
    }
}

// ---------------- embedding --------------------------------------------------
__global__ void embed_kernel(const int* __restrict__ idx,
                             const float* __restrict__ wte,
                             const float* __restrict__ wpe) {
    int row = blockIdx.x;
    int t = row & (SEQ - 1);
    int tok = idx[row];
    const float* we = wte + (size_t)tok * DMODEL;
    const float* wp = wpe + (size_t)t * DMODEL;
    float* xr = g_x + (size_t)row * DMODEL;
    for (int d = threadIdx.x; d < DMODEL; d += blockDim.x)
        xr[d] = we[d] + wp[d];
}

// ---------------- layernorm (writes fp16 plane) -------------------------------
__global__ void __launch_bounds__(256) ln_kernel(const float* __restrict__ x,
                                                 const float* __restrict__ sc,
                                                 const float* __restrict__ bi,
                                                 __half* __restrict__ outF) {
    __shared__ float red[8];
    int row = blockIdx.x, tid = threadIdx.x;
    const float* xr = x + (size_t)row * DMODEL;
    float v0 = xr[tid], v1 = xr[tid + 256], v2 = xr[tid + 512];

    float s = v0 + v1 + v2;
    #pragma unroll
    for (int o = 16; o > 0; o >>= 1) s += __shfl_xor_sync(~0u, s, o);
    if ((tid & 31) == 0) red[tid >> 5] = s;
    __syncthreads();
    if (tid < 32) {
        float t = (tid < 8) ? red[tid] : 0.f;
        #pragma unroll
        for (int o = 4; o > 0; o >>= 1) t += __shfl_xor_sync(~0u, t, o);
        if (tid == 0) red[0] = t;
    }
    __syncthreads();
    float mu = red[0] * (1.0f / DMODEL);
    __syncthreads();

    float d0 = v0 - mu, d1 = v1 - mu, d2 = v2 - mu;
    float s2 = d0 * d0 + d1 * d1 + d2 * d2;
    #pragma unroll
    for (int o = 16; o > 0; o >>= 1) s2 += __shfl_xor_sync(~0u, s2, o);
    if ((tid & 31) == 0) red[tid >> 5] = s2;
    __syncthreads();
    if (tid < 32) {
        float t = (tid < 8) ? red[tid] : 0.f;
        #pragma unroll
        for (int o = 4; o > 0; o >>= 1) t += __shfl_xor_sync(~0u, t, o);
        if (tid == 0) red[0] = t;
    }
    __syncthreads();
    float var = red[0] * (1.0f / DMODEL);
    float rs = rsqrtf(var + 1e-5f);

    size_t base = (size_t)row * DMODEL;
    #pragma unroll
    for (int e = 0; e < 3; e++) {
        float d = (e == 0) ? d0 : (e == 1) ? d1 : d2;
        int c = tid + 256 * e;
        outF[base + c] = __float2half_rn(d * rs * sc[c] + bi[c]);
    }
}

// ---------------- loss --------------------------------------------------------
__global__ void __launch_bounds__(256) lossrow_kernel(const float* __restrict__ logits,
                                                      const int* __restrict__ targets) {
    int row = blockIdx.x;
    const float* lr_ = logits + (size_t)row * VOCAB;
    float m = -1e30f, s = 0.f;
    for (int jv = threadIdx.x; jv < VOCAB; jv += 256) {
        float v = lr_[jv];
        if (v <= m) {
            s += __expf(v - m);
        } else {
            s = s * __expf(m - v) + 1.0f;
            m = v;
        }
    }
    __shared__ float sm[256], ss[256];
    sm[threadIdx.x] = m; ss[threadIdx.x] = s;
    __syncthreads();
    for (int st = 128; st > 0; st >>= 1) {
        if (threadIdx.x < st) {
            float ma = sm[threadIdx.x], sa = ss[threadIdx.x];
            float mb = sm[threadIdx.x + st], sb = ss[threadIdx.x + st];
            float M = fmaxf(ma, mb);
            ss[threadIdx.x] = sa * __expf(ma - M) + sb * __expf(mb - M);
            sm[threadIdx.x] = M;
        }
        __syncthreads();
    }
    if (threadIdx.x == 0) {
        float lse = sm[0] + logf(ss[0]);
        g_rowloss[row] = lse - lr_[targets[row]];
    }
}

__global__ void __launch_bounds__(256) lossreduce_kernel(float* __restrict__ out_loss) {
    __shared__ float red[8];
    float s = 0.f;
    for (int i = threadIdx.x; i < NTOK; i += 256) s += g_rowloss[i];
    #pragma unroll
    for (int o = 16; o > 0; o >>= 1) s += __shfl_xor_sync(~0u, s, o);
    if ((threadIdx.x & 31) == 0) red[threadIdx.x >> 5] = s;
    __syncthreads();
    if (threadIdx.x == 0) {
        float t = 0.f;
        for (int w = 0; w < 8; w++) t += red[w];
        out_loss[0] = t * (1.0f / NTOK);
    }
}

// ---------------- host orchestration -----------------------------------------
extern "C" void kernel_launch(void* const* d_in, const int* in_sizes, int n_in,
                              void* d_out, int out_size) {
    const int*   idx     = (const int*)  d_in[0];
    const int*   targets = (const int*)  d_in[1];
    const float* wte     = (const float*)d_in[2];
    const float* wpe     = (const float*)d_in[3];
    const float* ln1_s   = (const float*)d_in[4];
    const float* ln1_b   = (const float*)d_in[5];
    const float* attn_w  = (const float*)d_in[6];
    const float* attn_b  = (const float*)d_in[7];
    const float* proj_w  = (const float*)d_in[8];
    const float* proj_b  = (const float*)d_in[9];
    const float* ln2_s   = (const float*)d_in[10];
    const float* ln2_b   = (const float*)d_in[11];
    const float* fc_w    = (const float*)d_in[12];
    const float* fc_b    = (const float*)d_in[13];
    const float* proj2_w = (const float*)d_in[14];
    const float* proj2_b = (const float*)d_in[15];
    const float* lnf_s   = (const float*)d_in[16];
    const float* lnf_b   = (const float*)d_in[17];
    float* out = (float*)d_out;

    float* px;
    __half *ph16, *py16, *pm16, *pwT16, *pwte16;
    __nv_bfloat16 *pqH, *pqL;
    cudaGetSymbolAddress((void**)&px, g_x);
    cudaGetSymbolAddress((void**)&ph16, g_h16);
    cudaGetSymbolAddress((void**)&py16, g_y16);
    cudaGetSymbolAddress((void**)&pm16, g_m16);
    cudaGetSymbolAddress((void**)&pwT16, g_wT16);
    cudaGetSymbolAddress((void**)&pwte16, g_wte16);
    cudaGetSymbolAddress((void**)&pqH, g_qkvH);
    cudaGetSymbolAddress((void**)&pqL, g_qkvL);

    cudaFuncSetAttribute(gemm_f16<0>, cudaFuncAttributeMaxDynamicSharedMemorySize, FSMEM_NEED);
    cudaFuncSetAttribute(gemm_f16<1>, cudaFuncAttributeMaxDynamicSharedMemorySize, FSMEM_NEED);
    cudaFuncSetAttribute(gemm_f16<2>, cudaFuncAttributeMaxDynamicSharedMemorySize, FSMEM_NEED);
    cudaFuncSetAttribute(gemm_f16<3>, cudaFuncAttributeMaxDynamicSharedMemorySize, FSMEM_NEED);
    cudaFuncSetAttribute(attn_tc, cudaFuncAttributeMaxDynamicSharedMemorySize, ATT_SMEM);

    embed_kernel<<<NTOK, 256>>>(idx, wte, wpe);

    // --- all weight conversions up-front (batched over layers) ---
    cvt_wT16<<<dim3(3 * DMODEL / 32, DMODEL / 32, NLAYER), dim3(32, 8)>>>(
        attn_w, pwT16 + OFF_ATTN, DMODEL, 3 * DMODEL);
    cvt_wT16<<<dim3(DMODEL / 32, DMODEL / 32, NLAYER), dim3(32, 8)>>>(
        proj_w, pwT16 + OFF_PROJ, DMODEL, DMODEL);
    cvt_wT16<<<dim3(4 * DMODEL / 32, DMODEL / 32, NLAYER), dim3(32, 8)>>>(
        fc_w, pwT16 + OFF_FC, DMODEL, 4 * DMODEL);
    cvt_wT16<<<dim3(DMODEL / 32, 4 * DMODEL / 32, NLAYER), dim3(32, 8)>>>(
        proj2_w, pwT16 + OFF_PROJ2, 4 * DMODEL, DMODEL);
    {
        size_t nw = (size_t)VPAD * DMODEL;
        cvt_wte16<<<(unsigned)((nw + 255) / 256), 256>>>(wte);
    }

    for (int l = 0; l < NLAYER; l++) {
        const float* ab  = attn_b  + (size_t)l * 3 * DMODEL;
        const float* pb  = proj_b  + (size_t)l * DMODEL;
        const float* fb  = fc_b    + (size_t)l * 4 * DMODEL;
        const float* p2b = proj2_b + (size_t)l * DMODEL;
        size_t oAttn  = OFF_ATTN  + (size_t)l * SZ_ATTN;
        size_t oProj  = OFF_PROJ  + (size_t)l * SZ_PROJ;
        size_t oFc    = OFF_FC    + (size_t)l * SZ_FC;
        size_t oProj2 = OFF_PROJ2 + (size_t)l * SZ_PROJ2;

        // --- attention block ---
        ln_kernel<<<NTOK, 256>>>(px, ln1_s + l * DMODEL, ln1_b + l * DMODEL, ph16);
        gemm_f16<1><<<dim3(NTOK / 128, 3 * DMODEL / 128), 512, FSMEM_NEED>>>(
            ph16, pwT16 + oAttn, ab, nullptr, nullptr, pqH, pqL, 3 * DMODEL, DMODEL);
        attn_tc<<<dim3(SEQ / 64, NHEAD, 2), 128, ATT_SMEM>>>(pqH, pqL, py16);
        gemm_f16<3><<<dim3(NTOK / 128, DMODEL / 128), 512, FSMEM_NEED>>>(
            py16, pwT16 + oProj, pb, px, nullptr, nullptr, nullptr, DMODEL, DMODEL);

        // --- MLP block ---
        ln_kernel<<<NTOK, 256>>>(px, ln2_s + l * DMODEL, ln2_b + l * DMODEL, ph16);
        gemm_f16<2><<<dim3(NTOK / 128, 4 * DMODEL / 128), 512, FSMEM_NEED>>>(
            ph16, pwT16 + oFc, fb, nullptr, pm16, nullptr, nullptr, 4 * DMODEL, DMODEL);
        gemm_f16<3><<<dim3(NTOK / 128, DMODEL / 128), 512, FSMEM_NEED>>>(
            pm16, pwT16 + oProj2, p2b, px, nullptr, nullptr, nullptr, DMODEL, 4 * DMODEL);
    }

    // --- final LN + tied lm_head (fp16) + loss ---
    ln_kernel<<<NTOK, 256>>>(px, lnf_s, lnf_b, ph16);
    gemm_f16<0><<<dim3(NTOK / 128, VPAD / 128), 512, FSMEM_NEED>>>(
        ph16, pwte16, nullptr, out, nullptr, nullptr, nullptr, VOCAB, DMODEL);

    lossrow_kernel<<<NTOK, 256>>>(out, targets);
    lossreduce_kernel<<<1, 256>>>(out + (size_t)NTOK * VOCAB);
}

// round 11
// speedup vs baseline: 2.3866x; 1.1107x over previous
#include <cuda_runtime.h>
#include <cuda_bf16.h>
#include <cuda_fp16.h>
#include <math.h>
#include <stdint.h>

// Problem constants
#define NTOK 2048          // B*T
#define SEQ  1024
#define DMODEL 768
#define NHEAD 12
#define HDIM 64
#define NLAYER 8
#define VOCAB 50257
#define VPAD  50304        // 393*128
#define NBT   (VPAD / 128) // 393 lm_head column tiles

// per-layer transposed-weight plane offsets (elements)
#define OFF_ATTN  0
#define SZ_ATTN   (3 * DMODEL * DMODEL)
#define OFF_PROJ  (NLAYER * SZ_ATTN)
#define SZ_PROJ   (DMODEL * DMODEL)
#define OFF_FC    (OFF_PROJ + NLAYER * SZ_PROJ)
#define SZ_FC     (4 * DMODEL * DMODEL)
#define OFF_PROJ2 (OFF_FC + NLAYER * SZ_FC)
#define SZ_PROJ2  (4 * DMODEL * DMODEL)
#define WT_TOTAL  (OFF_PROJ2 + NLAYER * SZ_PROJ2)

// ---------------- scratch (device globals; no allocation allowed) ------------
__device__ float g_x[NTOK * DMODEL];
__device__ float g_rowloss[NTOK];
__device__ float2 g_lpart[NTOK * NBT];         // lm_head loss partials (max, sumexp)
__device__ __half g_h16[NTOK * DMODEL];        // LN out (fp16)
__device__ __half g_y16[NTOK * DMODEL];        // attn out (fp16)
__device__ __half g_m16[NTOK * 4 * DMODEL];    // mlp hidden (fp16)
__device__ __half g_qkv16[NTOK * 3 * DMODEL];  // qkv (fp16)
__device__ __half g_wT16[WT_TOTAL];            // transposed weights (fp16)
__device__ __half g_wte16[(size_t)VPAD * DMODEL];

// ---------------- helpers -----------------------------------------------------
__device__ __forceinline__ uint32_t smem_u32(const void* p) {
    uint32_t a;
    asm("{ .reg .u64 t; cvta.to.shared.u64 t, %1; cvt.u32.u64 %0, t; }" : "=r"(a) : "l"(p));
    return a;
}

#define CP_ASYNC16(s, g) \
    asm volatile("cp.async.cg.shared.global [%0], [%1], 16;" :: "r"(s), "l"(g) : "memory")
#define CP_COMMIT() asm volatile("cp.async.commit_group;" ::: "memory")

__device__ __forceinline__ void ldsm4(uint32_t r[4], uint32_t addr) {
    asm volatile("ldmatrix.sync.aligned.m8n8.x4.shared.b16 {%0,%1,%2,%3}, [%4];"
        : "=r"(r[0]), "=r"(r[1]), "=r"(r[2]), "=r"(r[3]) : "r"(addr));
}
__device__ __forceinline__ void ldsm4t(uint32_t r[4], uint32_t addr) {
    asm volatile("ldmatrix.sync.aligned.m8n8.x4.trans.shared.b16 {%0,%1,%2,%3}, [%4];"
        : "=r"(r[0]), "=r"(r[1]), "=r"(r[2]), "=r"(r[3]) : "r"(addr));
}
__device__ __forceinline__ void mma_f16(float c[4], const uint32_t a[4],
                                        uint32_t b0, uint32_t b1) {
    asm volatile("mma.sync.aligned.m16n8k16.row.col.f32.f16.f16.f32 "
        "{%0,%1,%2,%3}, {%4,%5,%6,%7}, {%8,%9}, {%0,%1,%2,%3};"
        : "+f"(c[0]), "+f"(c[1]), "+f"(c[2]), "+f"(c[3])
        : "r"(a[0]), "r"(a[1]), "r"(a[2]), "r"(a[3]), "r"(b0), "r"(b1));
}

// pack two fp32 into one u32 of fp16x2 (elem0 low)
__device__ __forceinline__ uint32_t pack_h2(float a, float b) {
    __half2 h = __floats2half2_rn(a, b);
    uint32_t u;
    memcpy(&u, &h, 4);
    return u;
}

__device__ __forceinline__ float gelu_f(float x) {
    const float c = 0.7978845608028654f;
    float x3 = x * x * x;
    return 0.5f * x * (1.0f + tanhf(c * (x + 0.044715f * x3)));
}

// online logsumexp merge of a value into (m, s)
__device__ __forceinline__ void lse_add(float& m, float& s, float v) {
    float nm = fmaxf(m, v);
    s = s * __expf(m - nm) + __expf(v - nm);
    m = nm;
}
__device__ __forceinline__ void lse_merge(float& m, float& s, float m2, float s2) {
    float nm = fmaxf(m, m2);
    s = s * __expf(m - nm) + s2 * __expf(m2 - nm);
    m = nm;
}

// ---------------- fp16 single-plane GEMM --------------------------------------
// C[M,N] = A[M,K]*B^T, fp16 operands, fp32 accum. CTA tile 128x128, 512 threads,
// KC=64, 3-stage cp.async pipeline, 128B swizzled rows.
// EPI: 1 = +bias -> fp16 plane (qkv); 2 = gelu(+bias) -> fp16 plane (fc);
//      3 = +bias, residual f32 C += (proj / proj2)
#define KC 64
#define FPLANE 16384                // 128 rows * 128 bytes
#define FSTAGE (2 * FPLANE)         // A + B = 32KB
#define NSTG 3
#define FSMEM_NEED (NSTG * FSTAGE + 128)

template <int EPI>
__global__ void __launch_bounds__(512, 1)
gemm_f16(const __half* __restrict__ A, const __half* __restrict__ B,
         const float* __restrict__ bias, float* __restrict__ C,
         __half* __restrict__ CF, int N, int K) {
    extern __shared__ char dsm[];
    uint32_t sb = (smem_u32(dsm) + 127) & ~127u;

    const int tid = threadIdx.x;
    const int wid = tid >> 5, lid = tid & 31;
    const long bm = (long)blockIdx.x * 128;
    const long bn = (long)blockIdx.y * 128;
    const int wm = (wid >> 2) * 32;
    const int wn = (wid & 3) * 32;
    const int lrow = lid & 15, lg = lid >> 4;

    const int nch = K / KC;

    auto load_stage = [&](int c) {
        uint32_t stb = sb + (c % NSTG) * FSTAGE;
        int kc0 = c * KC;
        #pragma unroll
        for (int i = 0; i < 2; i++) {
            int u = tid + 512 * i;
            int row = u >> 3, g = u & 7;
            uint32_t so = stb + row * 128 + ((g ^ (row & 7)) << 4);
            long ka = (bm + row) * (long)K + kc0 + g * 8;
            long kb = (bn + row) * (long)K + kc0 + g * 8;
            CP_ASYNC16(so,          A + ka);
            CP_ASYNC16(so + FPLANE, B + kb);
        }
        CP_COMMIT();
    };

    float creg[2][4][4];
    #pragma unroll
    for (int a = 0; a < 2; a++)
        #pragma unroll
        for (int b = 0; b < 4; b++)
            #pragma unroll
            for (int k = 0; k < 4; k++) creg[a][b][k] = 0.f;

    load_stage(0);
    load_stage(1);
    load_stage(2);

    for (int c = 0; c < nch; c++) {
        if (c + 3 <= nch)      { asm volatile("cp.async.wait_group 2;" ::: "memory"); }
        else if (c + 2 <= nch) { asm volatile("cp.async.wait_group 1;" ::: "memory"); }
        else                   { asm volatile("cp.async.wait_group 0;" ::: "memory"); }
        __syncthreads();

        uint32_t stb = sb + (c % NSTG) * FSTAGE;
        #pragma unroll
        for (int ks = 0; ks < 4; ks++) {
            int g = 2 * ks + lg;
            uint32_t aF[2][4], bF[2][4];
            #pragma unroll
            for (int mi = 0; mi < 2; mi++) {
                int row = wm + mi * 16 + lrow;
                uint32_t off = row * 128 + ((g ^ (row & 7)) << 4);
                ldsm4(aF[mi], stb + off);
            }
            #pragma unroll
            for (int ng = 0; ng < 2; ng++) {
                int row = wn + ng * 16 + lrow;
                uint32_t off = row * 128 + ((g ^ (row & 7)) << 4);
                ldsm4(bF[ng], stb + FPLANE + off);
            }
            #pragma unroll
            for (int mi = 0; mi < 2; mi++)
                #pragma unroll
                for (int ni = 0; ni < 4; ni++) {
                    int ng = ni >> 1, h = ni & 1;
                    mma_f16(creg[mi][ni], aF[mi], bF[ng][h], bF[ng][h + 2]);
                }
        }
        __syncthreads();
        if (c + 3 < nch) load_stage(c + 3);
    }

    // ---- epilogue ----
    int gid = lid >> 2, tin = lid & 3;
    #pragma unroll
    for (int mi = 0; mi < 2; mi++) {
        long row0 = bm + wm + mi * 16 + gid;
        long row1 = row0 + 8;
        #pragma unroll
        for (int ni = 0; ni < 4; ni++) {
            long col = bn + wn + ni * 8 + tin * 2;
            float b0 = bias[col], b1 = bias[col + 1];
            float v0 = creg[mi][ni][0] + b0;
            float v1 = creg[mi][ni][1] + b1;
            float v2 = creg[mi][ni][2] + b0;
            float v3 = creg[mi][ni][3] + b1;
            size_t o0 = (size_t)row0 * N + col;
            size_t o1 = (size_t)row1 * N + col;
            if (EPI == 1) {
                *(__half2*)&CF[o0] = __floats2half2_rn(v0, v1);
                *(__half2*)&CF[o1] = __floats2half2_rn(v2, v3);
            } else if (EPI == 2) {
                *(__half2*)&CF[o0] = __floats2half2_rn(gelu_f(v0), gelu_f(v1));
                *(__half2*)&CF[o1] = __floats2half2_rn(gelu_f(v2), gelu_f(v3));
            } else {
                float2 c0 = *(float2*)&C[o0];
                float2 c1 = *(float2*)&C[o1];
                *(float2*)&C[o0] = make_float2(v0 + c0.x, v1 + c0.y);
                *(float2*)&C[o1] = make_float2(v2 + c1.x, v3 + c1.y);
            }
        }
    }
}

// ---------------- lm_head GEMM with fused loss partials ------------------------
// C = A * wte^T (no bias), writes f32 logits (N-predicated) and per-(row, n-tile)
// online logsumexp partials to g_lpart.
__global__ void __launch_bounds__(512, 1)
gemm_lmh(const __half* __restrict__ A, const __half* __restrict__ B,
         float* __restrict__ C, int N, int K) {
    extern __shared__ char dsm[];
    uint32_t sb = (smem_u32(dsm) + 127) & ~127u;

    const int tid = threadIdx.x;
    const int wid = tid >> 5, lid = tid & 31;
    const long bm = (long)blockIdx.x * 128;
    const long bn = (long)blockIdx.y * 128;
    const int wm = (wid >> 2) * 32;
    const int wn = (wid & 3) * 32;
    const int lrow = lid & 15, lg = lid >> 4;

    const int nch = K / KC;

    auto load_stage = [&](int c) {
        uint32_t stb = sb + (c % NSTG) * FSTAGE;
        int kc0 = c * KC;
        #pragma unroll
        for (int i = 0; i < 2; i++) {
            int u = tid + 512 * i;
            int row = u >> 3, g = u & 7;
            uint32_t so = stb + row * 128 + ((g ^ (row & 7)) << 4);
            long ka = (bm + row) * (long)K + kc0 + g * 8;
            long kb = (bn + row) * (long)K + kc0 + g * 8;
            CP_ASYNC16(so,          A + ka);
            CP_ASYNC16(so + FPLANE, B + kb);
        }
        CP_COMMIT();
    };

    float creg[2][4][4];
    #pragma unroll
    for (int a = 0; a < 2; a++)
        #pragma unroll
        for (int b = 0; b < 4; b++)
            #pragma unroll
            for (int k = 0; k < 4; k++) creg[a][b][k] = 0.f;

    load_stage(0);
    load_stage(1);
    load_stage(2);

    for (int c = 0; c < nch; c++) {
        if (c + 3 <= nch)      { asm volatile("cp.async.wait_group 2;" ::: "memory"); }
        else if (c + 2 <= nch) { asm volatile("cp.async.wait_group 1;" ::: "memory"); }
        else                   { asm volatile("cp.async.wait_group 0;" ::: "memory"); }
        __syncthreads();

        uint32_t stb = sb + (c % NSTG) * FSTAGE;
        #pragma unroll
        for (int ks = 0; ks < 4; ks++) {
            int g = 2 * ks + lg;
            uint32_t aF[2][4], bF[2][4];
            #pragma unroll
            for (int mi = 0; mi < 2; mi++) {
                int row = wm + mi * 16 + lrow;
                uint32_t off = row * 128 + ((g ^ (row & 7)) << 4);
                ldsm4(aF[mi], stb + off);
            }
            #pragma unroll
            for (int ng = 0; ng < 2; ng++) {
                int row = wn + ng * 16 + lrow;
                uint32_t off = row * 128 + ((g ^ (row & 7)) << 4);
                ldsm4(bF[ng], stb + FPLANE + off);
            }
            #pragma unroll
            for (int mi = 0; mi < 2; mi++)
                #pragma unroll
                for (int ni = 0; ni < 4; ni++) {
                    int ng = ni >> 1, h = ni & 1;
                    mma_f16(creg[mi][ni], aF[mi], bF[ng][h], bF[ng][h + 2]);
                }
        }
        __syncthreads();
        if (c + 3 < nch) load_stage(c + 3);
    }

    // ---- epilogue: store logits + per-row loss partials ----
    int gid = lid >> 2, tin = lid & 3;
    float pm[2][2], ps[2][2];
    #pragma unroll
    for (int a = 0; a < 2; a++)
        #pragma unroll
        for (int b = 0; b < 2; b++) { pm[a][b] = -1e30f; ps[a][b] = 0.f; }

    #pragma unroll
    for (int mi = 0; mi < 2; mi++) {
        long row0 = bm + wm + mi * 16 + gid;
        long row1 = row0 + 8;
        #pragma unroll
        for (int ni = 0; ni < 4; ni++) {
            long col = bn + wn + ni * 8 + tin * 2;
            float v0 = creg[mi][ni][0];
            float v1 = creg[mi][ni][1];
            float v2 = creg[mi][ni][2];
            float v3 = creg[mi][ni][3];
            if (col < N) {
                C[row0 * N + col] = v0; C[row1 * N + col] = v2;
                lse_add(pm[mi][0], ps[mi][0], v0);
                lse_add(pm[mi][1], ps[mi][1], v2);
            }
            if (col + 1 < N) {
                C[row0 * N + col + 1] = v1; C[row1 * N + col + 1] = v3;
                lse_add(pm[mi][0], ps[mi][0], v1);
                lse_add(pm[mi][1], ps[mi][1], v3);
            }
        }
    }

    // smem reduce: buf[rowInTile][unit], unit = (wid&3)*4 + tin
    float2* buf = (float2*)dsm;
    int unit = (wid & 3) * 4 + tin;
    __syncthreads();
    #pragma unroll
    for (int mi = 0; mi < 2; mi++)
        #pragma unroll
        for (int rh = 0; rh < 2; rh++) {
            int rit = wm + mi * 16 + gid + rh * 8;
            buf[rit * 16 + unit] = make_float2(pm[mi][rh], ps[mi][rh]);
        }
    __syncthreads();
    if (tid < 128) {
        float m = -1e30f, s = 0.f;
        #pragma unroll
        for (int u = 0; u < 16; u++) {
            float2 p = buf[tid * 16 + u];
            lse_merge(m, s, p.x, p.y);
        }
        g_lpart[(bm + tid) * NBT + blockIdx.y] = make_float2(m, s);
    }
}

// ---------------- fp16 flash attention -----------------------------------------
// grid (SEQ/64, NHEAD, B), 128 threads. Reversed x order: longest KV first.
// smem: Q(8K) | stage{0,1}: K(8K) V(8K)
#define ATT_SMEM (8192 + 2 * 16384 + 128)

__global__ void __launch_bounds__(128, 4)
attn_tc(const __half* __restrict__ QKV, __half* __restrict__ Y) {
    extern __shared__ char dsm[];
    uint32_t sb = (smem_u32(dsm) + 127) & ~127u;

    const int tid = threadIdx.x;
    const int wid = tid >> 5, lid = tid & 31;
    const int qtile = gridDim.x - 1 - blockIdx.x;   // heavy blocks first
    const int q0 = qtile * 64, h = blockIdx.y, b = blockIdx.z;
    const int wq = wid * 16;
    const int ntile = qtile + 1;
    const size_t rstride = 3 * DMODEL;

    auto ldplane = [&](uint32_t dst, const __half* src) {
        #pragma unroll
        for (int i = 0; i < 4; i++) {
            int u = tid + 128 * i;
            int row = u >> 3, ch = u & 7;
            CP_ASYNC16(dst + row * 128 + ((ch ^ (row & 7)) << 4),
                       src + (size_t)row * rstride + ch * 8);
        }
    };
    auto ldstage = [&](int t) {
        uint32_t s = sb + 8192 + (t & 1) * 16384;
        size_t off = (size_t)(b * SEQ + t * 64) * rstride + h * HDIM;
        ldplane(s,        QKV + off + DMODEL);       // K
        ldplane(s + 8192, QKV + off + 2 * DMODEL);   // V
        CP_COMMIT();
    };

    {
        size_t qoff = (size_t)(b * SEQ + q0) * rstride + h * HDIM;
        ldplane(sb, QKV + qoff);
    }
    ldstage(0);

    float o[8][4];
    #pragma unroll
    for (int nb = 0; nb < 8; nb++)
        #pragma unroll
        for (int j = 0; j < 4; j++) o[nb][j] = 0.f;
    float mrun[2] = {-1e30f, -1e30f}, lrun[2] = {0.f, 0.f};

    for (int t = 0; t < ntile; t++) {
        asm volatile("cp.async.wait_group 0;" ::: "memory");
        __syncthreads();
        if (t + 1 < ntile) ldstage(t + 1);
        uint32_t kb = sb + 8192 + (t & 1) * 16384;

        float s[8][4];
        #pragma unroll
        for (int nb = 0; nb < 8; nb++)
            #pragma unroll
            for (int j = 0; j < 4; j++) s[nb][j] = 0.f;

        #pragma unroll
        for (int ks = 0; ks < 4; ks++) {
            uint32_t qf[4];
            {
                int r = wq + (lid & 15);
                uint32_t off = r * 128 + (((2 * ks + (lid >> 4)) ^ (r & 7)) << 4);
                ldsm4(qf, sb + off);
            }
            #pragma unroll
            for (int ng = 0; ng < 4; ng++) {
                int r = ng * 16 + (lid & 15);
                uint32_t off = r * 128 + (((2 * ks + (lid >> 4)) ^ (r & 7)) << 4);
                uint32_t kf[4];
                ldsm4(kf, kb + off);
                mma_f16(s[2 * ng],     qf, kf[0], kf[2]);
                mma_f16(s[2 * ng + 1], qf, kf[1], kf[3]);
            }
        }

        #pragma unroll
        for (int nb = 0; nb < 8; nb++)
            #pragma unroll
            for (int j = 0; j < 4; j++) s[nb][j] *= 0.125f;

        if (t == ntile - 1) {
            int r0g = q0 + wq + (lid >> 2);
            #pragma unroll
            for (int nb = 0; nb < 8; nb++) {
                int colg = t * 64 + nb * 8 + (lid & 3) * 2;
                if (colg     > r0g)     s[nb][0] = -1e30f;
                if (colg + 1 > r0g)     s[nb][1] = -1e30f;
                if (colg     > r0g + 8) s[nb][2] = -1e30f;
                if (colg + 1 > r0g + 8) s[nb][3] = -1e30f;
            }
        }

        #pragma unroll
        for (int half = 0; half < 2; half++) {
            float mx = -1e30f;
            #pragma unroll
            for (int nb = 0; nb < 8; nb++)
                mx = fmaxf(mx, fmaxf(s[nb][2 * half], s[nb][2 * half + 1]));
            mx = fmaxf(mx, __shfl_xor_sync(~0u, mx, 1));
            mx = fmaxf(mx, __shfl_xor_sync(~0u, mx, 2));
            float mn = fmaxf(mrun[half], mx);
            float al = __expf(mrun[half] - mn);
            mrun[half] = mn;
            float sum = 0.f;
            #pragma unroll
            for (int nb = 0; nb < 8; nb++) {
                float p0 = __expf(s[nb][2 * half]     - mn);
                float p1 = __expf(s[nb][2 * half + 1] - mn);
                s[nb][2 * half] = p0; s[nb][2 * half + 1] = p1;
                sum += p0 + p1;
            }
            lrun[half] = lrun[half] * al + sum;
            #pragma unroll
            for (int nb = 0; nb < 8; nb++) {
                o[nb][2 * half] *= al; o[nb][2 * half + 1] *= al;
            }
        }

        #pragma unroll
        for (int kk = 0; kk < 4; kk++) {
            uint32_t pf[4];
            pf[0] = pack_h2(s[2 * kk][0],     s[2 * kk][1]);
            pf[1] = pack_h2(s[2 * kk][2],     s[2 * kk][3]);
            pf[2] = pack_h2(s[2 * kk + 1][0], s[2 * kk + 1][1]);
            pf[3] = pack_h2(s[2 * kk + 1][2], s[2 * kk + 1][3]);
            #pragma unroll
            for (int cc = 0; cc < 4; cc++) {
                int r = kk * 16 + (lid & 15);
                uint32_t off = r * 128 + (((2 * cc + (lid >> 4)) ^ (r & 7)) << 4);
                uint32_t vf[4];
                ldsm4t(vf, kb + 8192 + off);
                mma_f16(o[2 * cc],     pf, vf[0], vf[1]);
                mma_f16(o[2 * cc + 1], pf, vf[2], vf[3]);
            }
        }
    }

    float inv[2];
    #pragma unroll
    for (int half = 0; half < 2; half++) {
        float l = lrun[half];
        l += __shfl_xor_sync(~0u, l, 1);
        l += __shfl_xor_sync(~0u, l, 2);
        inv[half] = 1.0f / l;
    }
    int r0 = q0 + wq + (lid >> 2);
    #pragma unroll
    for (int nb = 0; nb < 8; nb++) {
        int col = h * HDIM + nb * 8 + (lid & 3) * 2;
        size_t o0 = (size_t)(b * SEQ + r0) * DMODEL + col;
        size_t o1 = (size_t)(b * SEQ + r0 + 8) * DMODEL + col;
        *(__half2*)&Y[o0] = __floats2half2_rn(o[nb][0] * inv[0], o[nb][1] * inv[0]);
        *(__half2*)&Y[o1] = __floats2half2_rn(o[nb][2] * inv[1], o[nb][3] * inv[1]);
    }
}

// ---------------- weight conversions ------------------------------------------
__global__ void cvt_wte16(const float* __restrict__ wte) {
    size_t i = (size_t)blockIdx.x * 256 + threadIdx.x;
    if (i >= (size_t)VPAD * DMODEL) return;
    float v = (i < (size_t)VOCAB * DMODEL) ? wte[i] : 0.0f;
    g_wte16[i] = __float2half_rn(v);
}

// w [L,K,N] f32 -> out [L,N,K] fp16. grid (N/32, K/32, L), block (32,8)
__global__ void cvt_wT16(const float* __restrict__ w, __half* __restrict__ tf,
                         int K, int N) {
    __shared__ float t[32][33];
    const float* wsrc = w + (size_t)blockIdx.z * K * N;
    __half* tfd = tf + (size_t)blockIdx.z * N * K;
    int n0 = blockIdx.x * 32, k0 = blockIdx.y * 32;
    int tx = threadIdx.x, ty = threadIdx.y;
    #pragma unroll
    for (int i = 0; i < 4; i++)
        t[ty + 8 * i][tx] = wsrc[(size_t)(k0 + ty + 8 * i) * N + n0 + tx];
    __syncthreads();
    #pragma unroll
    for (int i = 0; i < 4; i++) {
        size_t o = (size_t)(n0 + ty + 8 * i) * K + k0 + tx;
        tfd[o] = __float2half_rn(t[tx][ty + 8 * i]);
    }
}

// ---------------- embedding --------------------------------------------------
__global__ void embed_kernel(const int* __restrict__ idx,
                             const float* __restrict__ wte,
                             const float* __restrict__ wpe) {
    int row = blockIdx.x;
    int t = row & (SEQ - 1);
    int tok = idx[row];
    const float* we = wte + (size_t)tok * DMODEL;
    const float* wp = wpe + (size_t)t * DMODEL;
    float* xr = g_x + (size_t)row * DMODEL;
    for (int d = threadIdx.x; d < DMODEL; d += blockDim.x)
        xr[d] = we[d] + wp[d];
}

// ---------------- layernorm (writes fp16 plane) -------------------------------
__global__ void __launch_bounds__(256) ln_kernel(const float* __restrict__ x,
                                                 const float* __restrict__ sc,
                                                 const float* __restrict__ bi,
                                                 __half* __restrict__ outF) {
    __shared__ float red[8];
    int row = blockIdx.x, tid = threadIdx.x;
    const float* xr = x + (size_t)row * DMODEL;
    float v0 = xr[tid], v1 = xr[tid + 256], v2 = xr[tid + 512];

    float s = v0 + v1 + v2;
    #pragma unroll
    for (int o = 16; o > 0; o >>= 1) s += __shfl_xor_sync(~0u, s, o);
    if ((tid & 31) == 0) red[tid >> 5] = s;
    __syncthreads();
    if (tid < 32) {
        float t = (tid < 8) ? red[tid] : 0.f;
        #pragma unroll
        for (int o = 4; o > 0; o >>= 1) t += __shfl_xor_sync(~0u, t, o);
        if (tid == 0) red[0] = t;
    }
    __syncthreads();
    float mu = red[0] * (1.0f / DMODEL);
    __syncthreads();

    float d0 = v0 - mu, d1 = v1 - mu, d2 = v2 - mu;
    float s2 = d0 * d0 + d1 * d1 + d2 * d2;
    #pragma unroll
    for (int o = 16; o > 0; o >>= 1) s2 += __shfl_xor_sync(~0u, s2, o);
    if ((tid & 31) == 0) red[tid >> 5] = s2;
    __syncthreads();
    if (tid < 32) {
        float t = (tid < 8) ? red[tid] : 0.f;
        #pragma unroll
        for (int o = 4; o > 0; o >>= 1) t += __shfl_xor_sync(~0u, t, o);
        if (tid == 0) red[0] = t;
    }
    __syncthreads();
    float var = red[0] * (1.0f / DMODEL);
    float rs = rsqrtf(var + 1e-5f);

    size_t base = (size_t)row * DMODEL;
    #pragma unroll
    for (int e = 0; e < 3; e++) {
        float d = (e == 0) ? d0 : (e == 1) ? d1 : d2;
        int c = tid + 256 * e;
        outF[base + c] = __float2half_rn(d * rs * sc[c] + bi[c]);
    }
}

// ---------------- loss: merge lm_head partials --------------------------------
__global__ void __launch_bounds__(128) lossrow2(const float* __restrict__ logits,
                                                const int* __restrict__ targets) {
    int row = blockIdx.x;
    int tid = threadIdx.x;
    const float2* p = g_lpart + (size_t)row * NBT;
    float m = -1e30f, s = 0.f;
    for (int i = tid; i < NBT; i += 128) {
        float2 v = p[i];
        lse_merge(m, s, v.x, v.y);
    }
    __shared__ float sm[128], ss[128];
    sm[tid] = m; ss[tid] = s;
    __syncthreads();
    for (int st = 64; st > 0; st >>= 1) {
        if (tid < st) {
            float ma = sm[tid], sa = ss[tid];
            float mb = sm[tid + st], sb = ss[tid + st];
            float M = fmaxf(ma, mb);
            ss[tid] = sa * __expf(ma - M) + sb * __expf(mb - M);
            sm[tid] = M;
        }
        __syncthreads();
    }
    if (tid == 0) {
        float lse = sm[0] + logf(ss[0]);
        g_rowloss[row] = lse - logits[(size_t)row * VOCAB + targets[row]];
    }
}

__global__ void __launch_bounds__(256) lossreduce_kernel(float* __restrict__ out_loss) {
    __shared__ float red[8];
    float s = 0.f;
    for (int i = threadIdx.x; i < NTOK; i += 256) s += g_rowloss[i];
    #pragma unroll
    for (int o = 16; o > 0; o >>= 1) s += __shfl_xor_sync(~0u, s, o);
    if ((threadIdx.x & 31) == 0) red[threadIdx.x >> 5] = s;
    __syncthreads();
    if (threadIdx.x == 0) {
        float t = 0.f;
        for (int w = 0; w < 8; w++) t += red[w];
        out_loss[0] = t * (1.0f / NTOK);
    }
}

// ---------------- host orchestration -----------------------------------------
extern "C" void kernel_launch(void* const* d_in, const int* in_sizes, int n_in,
                              void* d_out, int out_size) {
    const int*   idx     = (const int*)  d_in[0];
    const int*   targets = (const int*)  d_in[1];
    const float* wte     = (const float*)d_in[2];
    const float* wpe     = (const float*)d_in[3];
    const float* ln1_s   = (const float*)d_in[4];
    const float* ln1_b   = (const float*)d_in[5];
    const float* attn_w  = (const float*)d_in[6];
    const float* attn_b  = (const float*)d_in[7];
    const float* proj_w  = (const float*)d_in[8];
    const float* proj_b  = (const float*)d_in[9];
    const float* ln2_s   = (const float*)d_in[10];
    const float* ln2_b   = (const float*)d_in[11];
    const float* fc_w    = (const float*)d_in[12];
    const float* fc_b    = (const float*)d_in[13];
    const float* proj2_w = (const float*)d_in[14];
    const float* proj2_b = (const float*)d_in[15];
    const float* lnf_s   = (const float*)d_in[16];
    const float* lnf_b   = (const float*)d_in[17];
    float* out = (float*)d_out;

    float* px;
    __half *ph16, *py16, *pm16, *pq16, *pwT16, *pwte16;
    cudaGetSymbolAddress((void**)&px, g_x);
    cudaGetSymbolAddress((void**)&ph16, g_h16);
    cudaGetSymbolAddress((void**)&py16, g_y16);
    cudaGetSymbolAddress((void**)&pm16, g_m16);
    cudaGetSymbolAddress((void**)&pq16, g_qkv16);
    cudaGetSymbolAddress((void**)&pwT16, g_wT16);
    cudaGetSymbolAddress((void**)&pwte16, g_wte16);

    cudaFuncSetAttribute(gemm_f16<1>, cudaFuncAttributeMaxDynamicSharedMemorySize, FSMEM_NEED);
    cudaFuncSetAttribute(gemm_f16<2>, cudaFuncAttributeMaxDynamicSharedMemorySize, FSMEM_NEED);
    cudaFuncSetAttribute(gemm_f16<3>, cudaFuncAttributeMaxDynamicSharedMemorySize, FSMEM_NEED);
    cudaFuncSetAttribute(gemm_lmh,    cudaFuncAttributeMaxDynamicSharedMemorySize, FSMEM_NEED);
    cudaFuncSetAttribute(attn_tc, cudaFuncAttributeMaxDynamicSharedMemorySize, ATT_SMEM);

    embed_kernel<<<NTOK, 256>>>(idx, wte, wpe);

    // --- all weight conversions up-front (batched over layers) ---
    cvt_wT16<<<dim3(3 * DMODEL / 32, DMODEL / 32, NLAYER), dim3(32, 8)>>>(
        attn_w, pwT16 + OFF_ATTN, DMODEL, 3 * DMODEL);
    cvt_wT16<<<dim3(DMODEL / 32, DMODEL / 32, NLAYER), dim3(32, 8)>>>(
        proj_w, pwT16 + OFF_PROJ, DMODEL, DMODEL);
    cvt_wT16<<<dim3(4 * DMODEL / 32, DMODEL / 32, NLAYER), dim3(32, 8)>>>(
        fc_w, pwT16 + OFF_FC, DMODEL, 4 * DMODEL);
    cvt_wT16<<<dim3(DMODEL / 32, 4 * DMODEL / 32, NLAYER), dim3(32, 8)>>>(
        proj2_w, pwT16 + OFF_PROJ2, 4 * DMODEL, DMODEL);
    {
        size_t nw = (size_t)VPAD * DMODEL;
        cvt_wte16<<<(unsigned)((nw + 255) / 256), 256>>>(wte);
    }

    for (int l = 0; l < NLAYER; l++) {
        const float* ab  = attn_b  + (size_t)l * 3 * DMODEL;
        const float* pb  = proj_b  + (size_t)l * DMODEL;
        const float* fb  = fc_b    + (size_t)l * 4 * DMODEL;
        const float* p2b = proj2_b + (size_t)l * DMODEL;
        size_t oAttn  = OFF_ATTN  + (size_t)l * SZ_ATTN;
        size_t oProj  = OFF_PROJ  + (size_t)l * SZ_PROJ;
        size_t oFc    = OFF_FC    + (size_t)l * SZ_FC;
        size_t oProj2 = OFF_PROJ2 + (size_t)l * SZ_PROJ2;

        // --- attention block ---
        ln_kernel<<<NTOK, 256>>>(px, ln1_s + l * DMODEL, ln1_b + l * DMODEL, ph16);
        gemm_f16<1><<<dim3(NTOK / 128, 3 * DMODEL / 128), 512, FSMEM_NEED>>>(
            ph16, pwT16 + oAttn, ab, nullptr, pq16, 3 * DMODEL, DMODEL);
        attn_tc<<<dim3(SEQ / 64, NHEAD, 2), 128, ATT_SMEM>>>(pq16, py16);
        gemm_f16<3><<<dim3(NTOK / 128, DMODEL / 128), 512, FSMEM_NEED>>>(
            py16, pwT16 + oProj, pb, px, nullptr, DMODEL, DMODEL);

        // --- MLP block ---
        ln_kernel<<<NTOK, 256>>>(px, ln2_s + l * DMODEL, ln2_b + l * DMODEL, ph16);
        gemm_f16<2><<<dim3(NTOK / 128, 4 * DMODEL / 128), 512, FSMEM_NEED>>>(
            ph16, pwT16 + oFc, fb, nullptr, pm16, 4 * DMODEL, DMODEL);
        gemm_f16<3><<<dim3(NTOK / 128, DMODEL / 128), 512, FSMEM_NEED>>>(
            pm16, pwT16 + oProj2, p2b, px, nullptr, DMODEL, 4 * DMODEL);
    }

    // --- final LN + tied lm_head (fp16, fused loss partials) + loss ---
    ln_kernel<<<NTOK, 256>>>(px, lnf_s, lnf_b, ph16);
    gemm_lmh<<<dim3(NTOK / 128, VPAD / 128), 512, FSMEM_NEED>>>(
        ph16, pwte16, out, VOCAB, DMODEL);

    lossrow2<<<NTOK, 128>>>(out, targets);
    lossreduce_kernel<<<1, 256>>>(out + (size_t)NTOK * VOCAB);
}

// round 14
// speedup vs baseline: 2.4467x; 1.0252x over previous
#include <cuda_runtime.h>
#include <cuda_bf16.h>
#include <cuda_fp16.h>
#include <math.h>
#include <stdint.h>

// Problem constants
#define NTOK 2048          // B*T
#define SEQ  1024
#define DMODEL 768
#define NHEAD 12
#define HDIM 64
#define NLAYER 8
#define VOCAB 50257
#define VPAD  50304        // 393*128
#define NBT   (VPAD / 128) // 393 lm_head column tiles

// per-layer transposed-weight plane offsets (elements)
#define OFF_ATTN  0
#define SZ_ATTN   (3 * DMODEL * DMODEL)
#define OFF_PROJ  (NLAYER * SZ_ATTN)
#define SZ_PROJ   (DMODEL * DMODEL)
#define OFF_FC    (OFF_PROJ + NLAYER * SZ_PROJ)
#define SZ_FC     (4 * DMODEL * DMODEL)
#define OFF_PROJ2 (OFF_FC + NLAYER * SZ_FC)
#define SZ_PROJ2  (4 * DMODEL * DMODEL)
#define WT_TOTAL  (OFF_PROJ2 + NLAYER * SZ_PROJ2)

// ---------------- scratch (device globals; no allocation allowed) ------------
__device__ float g_x[NTOK * DMODEL];
__device__ float g_rowloss[NTOK];
__device__ float2 g_lpart[NTOK * NBT];         // lm_head loss partials (max, sumexp)
__device__ __half g_h16[NTOK * DMODEL];        // LN out (fp16)
__device__ __half g_y16[NTOK * DMODEL];        // attn out (fp16)
__device__ __half g_m16[NTOK * 4 * DMODEL];    // mlp hidden (fp16)
__device__ __half g_qkv16[NTOK * 3 * DMODEL];  // qkv (fp16)
__device__ __half g_wT16[WT_TOTAL];            // transposed weights (fp16)
__device__ __half g_wte16[(size_t)VPAD * DMODEL];

// ---------------- helpers -----------------------------------------------------
__device__ __forceinline__ uint32_t smem_u32(const void* p) {
    uint32_t a;
    asm("{ .reg .u64 t; cvta.to.shared.u64 t, %1; cvt.u32.u64 %0, t; }" : "=r"(a) : "l"(p));
    return a;
}

#define CP_ASYNC16(s, g) \
    asm volatile("cp.async.cg.shared.global [%0], [%1], 16;" :: "r"(s), "l"(g) : "memory")
#define CP_COMMIT() asm volatile("cp.async.commit_group;" ::: "memory")

__device__ __forceinline__ void ldsm4(uint32_t r[4], uint32_t addr) {
    asm volatile("ldmatrix.sync.aligned.m8n8.x4.shared.b16 {%0,%1,%2,%3}, [%4];"
        : "=r"(r[0]), "=r"(r[1]), "=r"(r[2]), "=r"(r[3]) : "r"(addr));
}
__device__ __forceinline__ void ldsm4t(uint32_t r[4], uint32_t addr) {
    asm volatile("ldmatrix.sync.aligned.m8n8.x4.trans.shared.b16 {%0,%1,%2,%3}, [%4];"
        : "=r"(r[0]), "=r"(r[1]), "=r"(r[2]), "=r"(r[3]) : "r"(addr));
}
__device__ __forceinline__ void mma_f16(float c[4], const uint32_t a[4],
                                        uint32_t b0, uint32_t b1) {
    asm volatile("mma.sync.aligned.m16n8k16.row.col.f32.f16.f16.f32 "
        "{%0,%1,%2,%3}, {%4,%5,%6,%7}, {%8,%9}, {%0,%1,%2,%3};"
        : "+f"(c[0]), "+f"(c[1]), "+f"(c[2]), "+f"(c[3])
        : "r"(a[0]), "r"(a[1]), "r"(a[2]), "r"(a[3]), "r"(b0), "r"(b1));
}

// pack two fp32 into one u32 of fp16x2 (elem0 low)
__device__ __forceinline__ uint32_t pack_h2(float a, float b) {
    __half2 h = __floats2half2_rn(a, b);
    uint32_t u;
    memcpy(&u, &h, 4);
    return u;
}

__device__ __forceinline__ float gelu_f(float x) {
    const float c = 0.7978845608028654f;
    float x3 = x * x * x;
    return 0.5f * x * (1.0f + tanhf(c * (x + 0.044715f * x3)));
}

// online logsumexp
__device__ __forceinline__ void lse_add(float& m, float& s, float v) {
    float nm = fmaxf(m, v);
    s = s * __expf(m - nm) + __expf(v - nm);
    m = nm;
}
__device__ __forceinline__ void lse_merge(float& m, float& s, float m2, float s2) {
    float nm = fmaxf(m, m2);
    s = s * __expf(m - nm) + s2 * __expf(m2 - nm);
    m = nm;
}

// ---------------- fp16 single-plane GEMM --------------------------------------
// C[M,N] = A[M,K]*B^T, fp16 operands, fp32 accum. CTA tile MTx128, 512 threads
// (16 warps, warp tile (MT/4)x32), KC=64, 4-stage cp.async, single barrier/chunk.
// EPI: 0 = lm_head: plain f32 out (N-pred) + fused logsumexp partials
//      1 = +bias -> fp16 plane (qkv); 2 = gelu(+bias) -> fp16 plane (fc);
//      3 = +bias, residual f32 C += (proj / proj2)
#define KC 64
#define NSTG 4

template <int EPI, int MT>
__global__ void __launch_bounds__(512, 1)
gemm_f16(const __half* __restrict__ A, const __half* __restrict__ B,
         const float* __restrict__ bias, float* __restrict__ C,
         __half* __restrict__ CF, int N, int K) {
    constexpr int MI  = MT / 64;          // a-frag groups per warp (2 or 4)
    constexpr int APL = MT * 128;         // A plane bytes
    constexpr int STG = APL + 16384;      // stage bytes (A + B(128 rows))

    extern __shared__ char dsm[];
    uint32_t sb = (smem_u32(dsm) + 127) & ~127u;

    const int tid = threadIdx.x;
    const int wid = tid >> 5, lid = tid & 31;
    const long bm = (long)blockIdx.x * MT;
    const long bn = (long)blockIdx.y * 128;
    const int wm = (wid >> 2) * (MT / 4);
    const int wn = (wid & 3) * 32;
    const int lrow = lid & 15, lg = lid >> 4;

    const int nch = K / KC;

    auto load_stage = [&](int c) {
        uint32_t stb = sb + (c % NSTG) * STG;
        int kc0 = c * KC;
        #pragma unroll
        for (int u = tid; u < MT * 8; u += 512) {
            int row = u >> 3, g = u & 7;
            CP_ASYNC16(stb + row * 128 + ((g ^ (row & 7)) << 4),
                       A + (bm + row) * (long)K + kc0 + g * 8);
        }
        #pragma unroll
        for (int u = tid; u < 128 * 8; u += 512) {
            int row = u >> 3, g = u & 7;
            CP_ASYNC16(stb + APL + row * 128 + ((g ^ (row & 7)) << 4),
                       B + (bn + row) * (long)K + kc0 + g * 8);
        }
        CP_COMMIT();
    };

    float creg[MI][4][4];
    #pragma unroll
    for (int a = 0; a < MI; a++)
        #pragma unroll
        for (int b = 0; b < 4; b++)
            #pragma unroll
            for (int k = 0; k < 4; k++) creg[a][b][k] = 0.f;

    load_stage(0);
    load_stage(1);
    load_stage(2);

    for (int c = 0; c < nch; c++) {
        int rem = nch - 1 - c;
        if (rem >= 2)      { asm volatile("cp.async.wait_group 2;" ::: "memory"); }
        else if (rem == 1) { asm volatile("cp.async.wait_group 1;" ::: "memory"); }
        else               { asm volatile("cp.async.wait_group 0;" ::: "memory"); }
        __syncthreads();
        if (c + 3 < nch) load_stage(c + 3);   // targets buffer freed by chunk c-1

        uint32_t stb = sb + (c % NSTG) * STG;
        #pragma unroll
        for (int ks = 0; ks < 4; ks++) {
            int g = 2 * ks + lg;
            uint32_t aF[MI][4], bF[2][4];
            #pragma unroll
            for (int mi = 0; mi < MI; mi++) {
                int row = wm + mi * 16 + lrow;
                uint32_t off = row * 128 + ((g ^ (row & 7)) << 4);
                ldsm4(aF[mi], stb + off);
            }
            #pragma unroll
            for (int ng = 0; ng < 2; ng++) {
                int row = wn + ng * 16 + lrow;
                uint32_t off = row * 128 + ((g ^ (row & 7)) << 4);
                ldsm4(bF[ng], stb + APL + off);
            }
            #pragma unroll
            for (int mi = 0; mi < MI; mi++)
                #pragma unroll
                for (int ni = 0; ni < 4; ni++) {
                    int ng = ni >> 1, h = ni & 1;
                    mma_f16(creg[mi][ni], aF[mi], bF[ng][h], bF[ng][h + 2]);
                }
        }
    }

    // ---- epilogue ----
    int gid = lid >> 2, tin = lid & 3;
    if (EPI == 0) {
        // lm_head: logits + per-row logsumexp partials
        float pm[MI][2], ps[MI][2];
        #pragma unroll
        for (int a = 0; a < MI; a++)
            #pragma unroll
            for (int b = 0; b < 2; b++) { pm[a][b] = -1e30f; ps[a][b] = 0.f; }

        #pragma unroll
        for (int mi = 0; mi < MI; mi++) {
            long row0 = bm + wm + mi * 16 + gid;
            long row1 = row0 + 8;
            #pragma unroll
            for (int ni = 0; ni < 4; ni++) {
                long col = bn + wn + ni * 8 + tin * 2;
                float v0 = creg[mi][ni][0];
                float v1 = creg[mi][ni][1];
                float v2 = creg[mi][ni][2];
                float v3 = creg[mi][ni][3];
                if (col < N) {
                    C[row0 * N + col] = v0; C[row1 * N + col] = v2;
                    lse_add(pm[mi][0], ps[mi][0], v0);
                    lse_add(pm[mi][1], ps[mi][1], v2);
                }
                if (col + 1 < N) {
                    C[row0 * N + col + 1] = v1; C[row1 * N + col + 1] = v3;
                    lse_add(pm[mi][0], ps[mi][0], v1);
                    lse_add(pm[mi][1], ps[mi][1], v3);
                }
            }
        }
        float2* buf = (float2*)dsm;
        int unit = (wid & 3) * 4 + tin;
        __syncthreads();
        #pragma unroll
        for (int mi = 0; mi < MI; mi++)
            #pragma unroll
            for (int rh = 0; rh < 2; rh++) {
                int rit = wm + mi * 16 + gid + rh * 8;
                buf[rit * 16 + unit] = make_float2(pm[mi][rh], ps[mi][rh]);
            }
        __syncthreads();
        if (tid < MT) {
            float m = -1e30f, s = 0.f;
            #pragma unroll
            for (int u = 0; u < 16; u++) {
                float2 p = buf[tid * 16 + u];
                lse_merge(m, s, p.x, p.y);
            }
            g_lpart[(bm + tid) * NBT + blockIdx.y] = make_float2(m, s);
        }
    } else {
        #pragma unroll
        for (int mi = 0; mi < MI; mi++) {
            long row0 = bm + wm + mi * 16 + gid;
            long row1 = row0 + 8;
            #pragma unroll
            for (int ni = 0; ni < 4; ni++) {
                long col = bn + wn + ni * 8 + tin * 2;
                float b0 = bias[col], b1 = bias[col + 1];
                float v0 = creg[mi][ni][0] + b0;
                float v1 = creg[mi][ni][1] + b1;
                float v2 = creg[mi][ni][2] + b0;
                float v3 = creg[mi][ni][3] + b1;
                size_t o0 = (size_t)row0 * N + col;
                size_t o1 = (size_t)row1 * N + col;
                if (EPI == 1) {
                    *(__half2*)&CF[o0] = __floats2half2_rn(v0, v1);
                    *(__half2*)&CF[o1] = __floats2half2_rn(v2, v3);
                } else if (EPI == 2) {
                    *(__half2*)&CF[o0] = __floats2half2_rn(gelu_f(v0), gelu_f(v1));
                    *(__half2*)&CF[o1] = __floats2half2_rn(gelu_f(v2), gelu_f(v3));
                } else {
                    float2 c0 = *(float2*)&C[o0];
                    float2 c1 = *(float2*)&C[o1];
                    *(float2*)&C[o0] = make_float2(v0 + c0.x, v1 + c0.y);
                    *(float2*)&C[o1] = make_float2(v2 + c1.x, v3 + c1.y);
                }
            }
        }
    }
}

#define SM_128 (NSTG * (128 * 128 + 16384) + 128)   // 131200
#define SM_256 (NSTG * (256 * 128 + 16384) + 128)   // 196736

// ---------------- fp16 flash attention -----------------------------------------
// grid (SEQ/64, NHEAD, B), 128 threads. Reversed x order: longest KV first.
// smem: Q(8K) | stage{0,1}: K(8K) V(8K)
#define ATT_SMEM (8192 + 2 * 16384 + 128)

__global__ void __launch_bounds__(128, 4)
attn_tc(const __half* __restrict__ QKV, __half* __restrict__ Y) {
    extern __shared__ char dsm[];
    uint32_t sb = (smem_u32(dsm) + 127) & ~127u;

    const int tid = threadIdx.x;
    const int wid = tid >> 5, lid = tid & 31;
    const int qtile = gridDim.x - 1 - blockIdx.x;   // heavy blocks first
    const int q0 = qtile * 64, h = blockIdx.y, b = blockIdx.z;
    const int wq = wid * 16;
    const int ntile = qtile + 1;
    const size_t rstride = 3 * DMODEL;

    auto ldplane = [&](uint32_t dst, const __half* src) {
        #pragma unroll
        for (int i = 0; i < 4; i++) {
            int u = tid + 128 * i;
            int row = u >> 3, ch = u & 7;
            CP_ASYNC16(dst + row * 128 + ((ch ^ (row & 7)) << 4),
                       src + (size_t)row * rstride + ch * 8);
        }
    };
    auto ldstage = [&](int t) {
        uint32_t s = sb + 8192 + (t & 1) * 16384;
        size_t off = (size_t)(b * SEQ + t * 64) * rstride + h * HDIM;
        ldplane(s,        QKV + off + DMODEL);       // K
        ldplane(s + 8192, QKV + off + 2 * DMODEL);   // V
        CP_COMMIT();
    };

    {
        size_t qoff = (size_t)(b * SEQ + q0) * rstride + h * HDIM;
        ldplane(sb, QKV + qoff);
    }
    ldstage(0);

    float o[8][4];
    #pragma unroll
    for (int nb = 0; nb < 8; nb++)
        #pragma unroll
        for (int j = 0; j < 4; j++) o[nb][j] = 0.f;
    float mrun[2] = {-1e30f, -1e30f}, lrun[2] = {0.f, 0.f};

    for (int t = 0; t < ntile; t++) {
        asm volatile("cp.async.wait_group 0;" ::: "memory");
        __syncthreads();
        if (t + 1 < ntile) ldstage(t + 1);
        uint32_t kb = sb + 8192 + (t & 1) * 16384;

        float s[8][4];
        #pragma unroll
        for (int nb = 0; nb < 8; nb++)
            #pragma unroll
            for (int j = 0; j < 4; j++) s[nb][j] = 0.f;

        #pragma unroll
        for (int ks = 0; ks < 4; ks++) {
            uint32_t qf[4];
            {
                int r = wq + (lid & 15);
                uint32_t off = r * 128 + (((2 * ks + (lid >> 4)) ^ (r & 7)) << 4);
                ldsm4(qf, sb + off);
            }
            #pragma unroll
            for (int ng = 0; ng < 4; ng++) {
                int r = ng * 16 + (lid & 15);
                uint32_t off = r * 128 + (((2 * ks + (lid >> 4)) ^ (r & 7)) << 4);
                uint32_t kf[4];
                ldsm4(kf, kb + off);
                mma_f16(s[2 * ng],     qf, kf[0], kf[2]);
                mma_f16(s[2 * ng + 1], qf, kf[1], kf[3]);
            }
        }

        #pragma unroll
        for (int nb = 0; nb < 8; nb++)
            #pragma unroll
            for (int j = 0; j < 4; j++) s[nb][j] *= 0.125f;

        if (t == ntile - 1) {
            int r0g = q0 + wq + (lid >> 2);
            #pragma unroll
            for (int nb = 0; nb < 8; nb++) {
                int colg = t * 64 + nb * 8 + (lid & 3) * 2;
                if (colg     > r0g)     s[nb][0] = -1e30f;
                if (colg + 1 > r0g)     s[nb][1] = -1e30f;
                if (colg     > r0g + 8) s[nb][2] = -1e30f;
                if (colg + 1 > r0g + 8) s[nb][3] = -1e30f;
            }
        }

        #pragma unroll
        for (int half = 0; half < 2; half++) {
            float mx = -1e30f;
            #pragma unroll
            for (int nb = 0; nb < 8; nb++)
                mx = fmaxf(mx, fmaxf(s[nb][2 * half], s[nb][2 * half + 1]));
            mx = fmaxf(mx, __shfl_xor_sync(~0u, mx, 1));
            mx = fmaxf(mx, __shfl_xor_sync(~0u, mx, 2));
            float mn = fmaxf(mrun[half], mx);
            float al = __expf(mrun[half] - mn);
            mrun[half] = mn;
            float sum = 0.f;
            #pragma unroll
            for (int nb = 0; nb < 8; nb++) {
                float p0 = __expf(s[nb][2 * half]     - mn);
                float p1 = __expf(s[nb][2 * half + 1] - mn);
                s[nb][2 * half] = p0; s[nb][2 * half + 1] = p1;
                sum += p0 + p1;
            }
            lrun[half] = lrun[half] * al + sum;
            #pragma unroll
            for (int nb = 0; nb < 8; nb++) {
                o[nb][2 * half] *= al; o[nb][2 * half + 1] *= al;
            }
        }

        #pragma unroll
        for (int kk = 0; kk < 4; kk++) {
            uint32_t pf[4];
            pf[0] = pack_h2(s[2 * kk][0],     s[2 * kk][1]);
            pf[1] = pack_h2(s[2 * kk][2],     s[2 * kk][3]);
            pf[2] = pack_h2(s[2 * kk + 1][0], s[2 * kk + 1][1]);
            pf[3] = pack_h2(s[2 * kk + 1][2], s[2 * kk + 1][3]);
            #pragma unroll
            for (int cc = 0; cc < 4; cc++) {
                int r = kk * 16 + (lid & 15);
                uint32_t off = r * 128 + (((2 * cc + (lid >> 4)) ^ (r & 7)) << 4);
                uint32_t vf[4];
                ldsm4t(vf, kb + 8192 + off);
                mma_f16(o[2 * cc],     pf, vf[0], vf[1]);
                mma_f16(o[2 * cc + 1], pf, vf[2], vf[3]);
            }
        }
    }

    float inv[2];
    #pragma unroll
    for (int half = 0; half < 2; half++) {
        float l = lrun[half];
        l += __shfl_xor_sync(~0u, l, 1);
        l += __shfl_xor_sync(~0u, l, 2);
        inv[half] = 1.0f / l;
    }
    int r0 = q0 + wq + (lid >> 2);
    #pragma unroll
    for (int nb = 0; nb < 8; nb++) {
        int col = h * HDIM + nb * 8 + (lid & 3) * 2;
        size_t o0 = (size_t)(b * SEQ + r0) * DMODEL + col;
        size_t o1 = (size_t)(b * SEQ + r0 + 8) * DMODEL + col;
        *(__half2*)&Y[o0] = __floats2half2_rn(o[nb][0] * inv[0], o[nb][1] * inv[0]);
        *(__half2*)&Y[o1] = __floats2half2_rn(o[nb][2] * inv[1], o[nb][3] * inv[1]);
    }
}

// ---------------- weight conversions ------------------------------------------
__global__ void cvt_wte16(const float* __restrict__ wte) {
    size_t i = (size_t)blockIdx.x * 256 + threadIdx.x;
    if (i >= (size_t)VPAD * DMODEL) return;
    float v = (i < (size_t)VOCAB * DMODEL) ? wte[i] : 0.0f;
    g_wte16[i] = __float2half_rn(v);
}

// w [L,K,N] f32 -> out [L,N,K] fp16. grid (N/32, K/32, L), block (32,8)
__global__ void cvt_wT16(const float* __restrict__ w, __half* __restrict__ tf,
                         int K, int N) {
    __shared__ float t[32][33];
    const float* wsrc = w + (size_t)blockIdx.z * K * N;
    __half* tfd = tf + (size_t)blockIdx.z * N * K;
    int n0 = blockIdx.x * 32, k0 = blockIdx.y * 32;
    int tx = threadIdx.x, ty = threadIdx.y;
    #pragma unroll
    for (int i = 0; i < 4; i++)
        t[ty + 8 * i][tx] = wsrc[(size_t)(k0 + ty + 8 * i) * N + n0 + tx];
    __syncthreads();
    #pragma unroll
    for (int i = 0; i < 4; i++) {
        size_t o = (size_t)(n0 + ty + 8 * i) * K + k0 + tx;
        tfd[o] = __float2half_rn(t[tx][ty + 8 * i]);
    }
}

// ---------------- embedding --------------------------------------------------
__global__ void embed_kernel(const int* __restrict__ idx,
                             const float* __restrict__ wte,
                             const float* __restrict__ wpe) {
    int row = blockIdx.x;
    int t = row & (SEQ - 1);
    int tok = idx[row];
    const float* we = wte + (size_t)tok * DMODEL;
    const float* wp = wpe + (size_t)t * DMODEL;
    float* xr = g_x + (size_t)row * DMODEL;
    for (int d = threadIdx.x; d < DMODEL; d += blockDim.x)
        xr[d] = we[d] + wp[d];
}

// ---------------- layernorm (writes fp16 plane) -------------------------------
__global__ void __launch_bounds__(256) ln_kernel(const float* __restrict__ x,
                                                 const float* __restrict__ sc,
                                                 const float* __restrict__ bi,
                                                 __half* __restrict__ outF) {
    __shared__ float red[8];
    int row = blockIdx.x, tid = threadIdx.x;
    const float* xr = x + (size_t)row * DMODEL;
    float v0 = xr[tid], v1 = xr[tid + 256], v2 = xr[tid + 512];

    float s = v0 + v1 + v2;
    #pragma unroll
    for (int o = 16; o > 0; o >>= 1) s += __shfl_xor_sync(~0u, s, o);
    if ((tid & 31) == 0) red[tid >> 5] = s;
    __syncthreads();
    if (tid < 32) {
        float t = (tid < 8) ? red[tid] : 0.f;
        #pragma unroll
        for (int o = 4; o > 0; o >>= 1) t += __shfl_xor_sync(~0u, t, o);
        if (tid == 0) red[0] = t;
    }
    __syncthreads();
    float mu = red[0] * (1.0f / DMODEL);
    __syncthreads();

    float d0 = v0 - mu, d1 = v1 - mu, d2 = v2 - mu;
    float s2 = d0 * d0 + d1 * d1 + d2 * d2;
    #pragma unroll
    for (int o = 16; o > 0; o >>= 1) s2 += __shfl_xor_sync(~0u, s2, o);
    if ((tid & 31) == 0) red[tid >> 5] = s2;
    __syncthreads();
    if (tid < 32) {
        float t = (tid < 8) ? red[tid] : 0.f;
        #pragma unroll
        for (int o = 4; o > 0; o >>= 1) t += __shfl_xor_sync(~0u, t, o);
        if (tid == 0) red[0] = t;
    }
    __syncthreads();
    float var = red[0] * (1.0f / DMODEL);
    float rs = rsqrtf(var + 1e-5f);

    size_t base = (size_t)row * DMODEL;
    #pragma unroll
    for (int e = 0; e < 3; e++) {
        float d = (e == 0) ? d0 : (e == 1) ? d1 : d2;
        int c = tid + 256 * e;
        outF[base + c] = __float2half_rn(d * rs * sc[c] + bi[c]);
    }
}

// ---------------- loss: merge lm_head partials --------------------------------
__global__ void __launch_bounds__(128) lossrow2(const float* __restrict__ logits,
                                                const int* __restrict__ targets) {
    int row = blockIdx.x;
    int tid = threadIdx.x;
    const float2* p = g_lpart + (size_t)row * NBT;
    float m = -1e30f, s = 0.f;
    for (int i = tid; i < NBT; i += 128) {
        float2 v = p[i];
        lse_merge(m, s, v.x, v.y);
    }
    __shared__ float sm[128], ss[128];
    sm[tid] = m; ss[tid] = s;
    __syncthreads();
    for (int st = 64; st > 0; st >>= 1) {
        if (tid < st) {
            float ma = sm[tid], sa = ss[tid];
            float mb = sm[tid + st], sb = ss[tid + st];
            float M = fmaxf(ma, mb);
            ss[tid] = sa * __expf(ma - M) + sb * __expf(mb - M);
            sm[tid] = M;
        }
        __syncthreads();
    }
    if (tid == 0) {
        float lse = sm[0] + logf(ss[0]);
        g_rowloss[row] = lse - logits[(size_t)row * VOCAB + targets[row]];
    }
}

__global__ void __launch_bounds__(256) lossreduce_kernel(float* __restrict__ out_loss) {
    __shared__ float red[8];
    float s = 0.f;
    for (int i = threadIdx.x; i < NTOK; i += 256) s += g_rowloss[i];
    #pragma unroll
    for (int o = 16; o > 0; o >>= 1) s += __shfl_xor_sync(~0u, s, o);
    if ((threadIdx.x & 31) == 0) red[threadIdx.x >> 5] = s;
    __syncthreads();
    if (threadIdx.x == 0) {
        float t = 0.f;
        for (int w = 0; w < 8; w++) t += red[w];
        out_loss[0] = t * (1.0f / NTOK);
    }
}

// ---------------- host orchestration -----------------------------------------
extern "C" void kernel_launch(void* const* d_in, const int* in_sizes, int n_in,
                              void* d_out, int out_size) {
    const int*   idx     = (const int*)  d_in[0];
    const int*   targets = (const int*)  d_in[1];
    const float* wte     = (const float*)d_in[2];
    const float* wpe     = (const float*)d_in[3];
    const float* ln1_s   = (const float*)d_in[4];
    const float* ln1_b   = (const float*)d_in[5];
    const float* attn_w  = (const float*)d_in[6];
    const float* attn_b  = (const float*)d_in[7];
    const float* proj_w  = (const float*)d_in[8];
    const float* proj_b  = (const float*)d_in[9];
    const float* ln2_s   = (const float*)d_in[10];
    const float* ln2_b   = (const float*)d_in[11];
    const float* fc_w    = (const float*)d_in[12];
    const float* fc_b    = (const float*)d_in[13];
    const float* proj2_w = (const float*)d_in[14];
    const float* proj2_b = (const float*)d_in[15];
    const float* lnf_s   = (const float*)d_in[16];
    const float* lnf_b   = (const float*)d_in[17];
    float* out = (float*)d_out;

    float* px;
    __half *ph16, *py16, *pm16, *pq16, *pwT16, *pwte16;
    cudaGetSymbolAddress((void**)&px, g_x);
    cudaGetSymbolAddress((void**)&ph16, g_h16);
    cudaGetSymbolAddress((void**)&py16, g_y16);
    cudaGetSymbolAddress((void**)&pm16, g_m16);
    cudaGetSymbolAddress((void**)&pq16, g_qkv16);
    cudaGetSymbolAddress((void**)&pwT16, g_wT16);
    cudaGetSymbolAddress((void**)&pwte16, g_wte16);

    cudaFuncSetAttribute(gemm_f16<1, 256>, cudaFuncAttributeMaxDynamicSharedMemorySize, SM_256);
    cudaFuncSetAttribute(gemm_f16<2, 256>, cudaFuncAttributeMaxDynamicSharedMemorySize, SM_256);
    cudaFuncSetAttribute(gemm_f16<3, 128>, cudaFuncAttributeMaxDynamicSharedMemorySize, SM_128);
    cudaFuncSetAttribute(gemm_f16<0, 256>, cudaFuncAttributeMaxDynamicSharedMemorySize, SM_256);
    cudaFuncSetAttribute(attn_tc, cudaFuncAttributeMaxDynamicSharedMemorySize, ATT_SMEM);

    embed_kernel<<<NTOK, 256>>>(idx, wte, wpe);

    // --- all weight conversions up-front (batched over layers) ---
    cvt_wT16<<<dim3(3 * DMODEL / 32, DMODEL / 32, NLAYER), dim3(32, 8)>>>(
        attn_w, pwT16 + OFF_ATTN, DMODEL, 3 * DMODEL);
    cvt_wT16<<<dim3(DMODEL / 32, DMODEL / 32, NLAYER), dim3(32, 8)>>>(
        proj_w, pwT16 + OFF_PROJ, DMODEL, DMODEL);
    cvt_wT16<<<dim3(4 * DMODEL / 32, DMODEL / 32, NLAYER), dim3(32, 8)>>>(
        fc_w, pwT16 + OFF_FC, DMODEL, 4 * DMODEL);
    cvt_wT16<<<dim3(DMODEL / 32, 4 * DMODEL / 32, NLAYER), dim3(32, 8)>>>(
        proj2_w, pwT16 + OFF_PROJ2, 4 * DMODEL, DMODEL);
    {
        size_t nw = (size_t)VPAD * DMODEL;
        cvt_wte16<<<(unsigned)((nw + 255) / 256), 256>>>(wte);
    }

    for (int l = 0; l < NLAYER; l++) {
        const float* ab  = attn_b  + (size_t)l * 3 * DMODEL;
        const float* pb  = proj_b  + (size_t)l * DMODEL;
        const float* fb  = fc_b    + (size_t)l * 4 * DMODEL;
        const float* p2b = proj2_b + (size_t)l * DMODEL;
        size_t oAttn  = OFF_ATTN  + (size_t)l * SZ_ATTN;
        size_t oProj  = OFF_PROJ  + (size_t)l * SZ_PROJ;
        size_t oFc    = OFF_FC    + (size_t)l * SZ_FC;
        size_t oProj2 = OFF_PROJ2 + (size_t)l * SZ_PROJ2;

        // --- attention block ---
        ln_kernel<<<NTOK, 256>>>(px, ln1_s + l * DMODEL, ln1_b + l * DMODEL, ph16);
        gemm_f16<1, 256><<<dim3(NTOK / 256, 3 * DMODEL / 128), 512, SM_256>>>(
            ph16, pwT16 + oAttn, ab, nullptr, pq16, 3 * DMODEL, DMODEL);
        attn_tc<<<dim3(SEQ / 64, NHEAD, 2), 128, ATT_SMEM>>>(pq16, py16);
        gemm_f16<3, 128><<<dim3(NTOK / 128, DMODEL / 128), 512, SM_128>>>(
            py16, pwT16 + oProj, pb, px, nullptr, DMODEL, DMODEL);

        // --- MLP block ---
        ln_kernel<<<NTOK, 256>>>(px, ln2_s + l * DMODEL, ln2_b + l * DMODEL, ph16);
        gemm_f16<2, 256><<<dim3(NTOK / 256, 4 * DMODEL / 128), 512, SM_256>>>(
            ph16, pwT16 + oFc, fb, nullptr, pm16, 4 * DMODEL, DMODEL);
        gemm_f16<3, 128><<<dim3(NTOK / 128, DMODEL / 128), 512, SM_128>>>(
            pm16, pwT16 + oProj2, p2b, px, nullptr, DMODEL, 4 * DMODEL);
    }

    // --- final LN + tied lm_head (fp16, fused loss partials) + loss ---
    ln_kernel<<<NTOK, 256>>>(px, lnf_s, lnf_b, ph16);
    gemm_f16<0, 256><<<dim3(NTOK / 256, VPAD / 128), 512, SM_256>>>(
        ph16, pwte16, nullptr, out, nullptr, VOCAB, DMODEL);

    lossrow2<<<NTOK, 128>>>(out, targets);
    lossreduce_kernel<<<1, 256>>>(out + (size_t)NTOK * VOCAB);
}